// round 10
// baseline (speedup 1.0000x reference)
#include <cuda_runtime.h>
#include <cuda_bf16.h>
#include <math.h>
#include <stdint.h>

#define BATCH 16
#define NPTS 2048
#define CINF 6
#define RR 20
#define GG 128
#define F1V 1000
#define NCLS 40
#define FPAD 1024
#define RK 6016
#define RM 384

typedef __nv_bfloat16 bf16;

// ---------------- scratch (device globals; zero-initialized, no allocations) ----------------
__device__ float g_L[(size_t)BATCH*NPTS*NPTS];
__device__ float g_out1[(size_t)BATCH*NPTS*F1V];
__device__ float g_x12[(size_t)BATCH*NPTS*F1V];
__device__ float g_out2[(size_t)BATCH*NPTS*F1V];
__device__ bf16  g_Lh[(size_t)BATCH*NPTS*NPTS];
__device__ bf16  g_Ll[(size_t)BATCH*NPTS*NPTS];
__device__ bf16  g_out1h[(size_t)BATCH*NPTS*FPAD];
__device__ bf16  g_out1l[(size_t)BATCH*NPTS*FPAD];
__device__ bf16  g_out1Th[(size_t)BATCH*FPAD*NPTS];
__device__ bf16  g_out1Tl[(size_t)BATCH*FPAD*NPTS];
__device__ bf16  g_x12h[(size_t)BATCH*NPTS*FPAD];
__device__ bf16  g_x12l[(size_t)BATCH*NPTS*FPAD];
__device__ bf16  g_x12Th[(size_t)BATCH*FPAD*NPTS];
__device__ bf16  g_x12Tl[(size_t)BATCH*FPAD*NPTS];
__device__ bf16  g_x22h[(size_t)BATCH*NPTS*FPAD];
__device__ bf16  g_x22l[(size_t)BATCH*NPTS*FPAD];
__device__ bf16  g_W2Th[3*FPAD*FPAD];
__device__ bf16  g_W2Tl[3*FPAD*FPAD];
__device__ bf16  g_xsRh[(size_t)RM*RK];
__device__ bf16  g_xsRl[(size_t)RM*RK];
__device__ bf16  g_WrTh[(size_t)FPAD*RK];
__device__ bf16  g_WrTl[(size_t)FPAD*RK];
__device__ float g_x11[BATCH*NPTS*CINF];
__device__ float g_x21[BATCH*NPTS*CINF];
__device__ float g_Lx[BATCH*NPTS*CINF];
__device__ float g_rowsum[BATCH*NPTS];
__device__ float g_sqn[BATCH*NPTS];
__device__ float g_vR[BATCH*RR*F1V];
__device__ float g_outR[BATCH*RR*F1V];
__device__ float g_g[BATCH*F1V];
__device__ float g_gR[BATCH*F1V];
__device__ float g_h1[BATCH*512];
__device__ float g_h2[BATCH*128];
__device__ float g_acc[8];

// ---------------- helpers ----------------
__device__ __forceinline__ uint32_t smem_u32(const void* p){
  uint32_t a;
  asm("{ .reg .u64 t; cvta.to.shared.u64 t, %1; cvt.u32.u64 %0, t; }" : "=r"(a) : "l"(p));
  return a;
}
__device__ __forceinline__ void cp16(uint32_t s, const void* g){
  asm volatile("cp.async.cg.shared.global [%0], [%1], 16;" :: "r"(s), "l"(g));
}
__device__ __forceinline__ void ldsm4(uint32_t& r0, uint32_t& r1, uint32_t& r2, uint32_t& r3, uint32_t a){
  asm volatile("ldmatrix.sync.aligned.m8n8.x4.shared.b16 {%0,%1,%2,%3}, [%4];"
    : "=r"(r0), "=r"(r1), "=r"(r2), "=r"(r3) : "r"(a));
}
__device__ __forceinline__ void mma16816(float* d, const uint32_t* a, const uint32_t* b){
  asm volatile("mma.sync.aligned.m16n8k16.row.col.f32.bf16.bf16.f32 "
    "{%0,%1,%2,%3}, {%4,%5,%6,%7}, {%8,%9}, {%0,%1,%2,%3};"
    : "+f"(d[0]), "+f"(d[1]), "+f"(d[2]), "+f"(d[3])
    : "r"(a[0]), "r"(a[1]), "r"(a[2]), "r"(a[3]), "r"(b[0]), "r"(b[1]));
}
__device__ __forceinline__ void split2(float v, bf16* ph, bf16* pl){
  bf16 h = __float2bfloat16(v);
  *ph = h;
  *pl = __float2bfloat16(v - __bfloat162float(h));
}

// ---------------- HMMA GEMM: C[M,N], CTA tile 128x256, BK=64, 2-stage, bf16 2-way split, 3 passes ----------------
// epi: 0 plain C; 1 exp(2a - sq[m] - sq[n]) upper-only; 2 C + split2; 3 split2 of (2a - Z); 4 relu(a + bias[n])
struct GemmArgs {
  const bf16 *Ah[3], *Al[3], *Bh[3], *Bl[3];
  long ldA, ldB, sA, sB;
  float* C; long ldC, sC;
  bf16 *Ch, *Cl; long ldH, sH;
  const float* Z; long ldZ, sZ;
  const float* bias;
  const float* sq; long sSq;
  int M, N, nseg, kcs, epi;
};

#define ROWP    144              // 128B row + 16B pad (conflict-free)
#define APART_B (128*ROWP)       // 18432
#define BPART_B (256*ROWP)       // 36864
#define OFF_AH  0
#define OFF_AL  APART_B
#define OFF_BH  (2*APART_B)
#define OFF_BL  (2*APART_B + BPART_B)
#define STAGE_B (2*APART_B + 2*BPART_B)   // 110592
#define HSM_TOT (2*STAGE_B)               // 221184

__global__ __launch_bounds__(256, 1) void hgemm_kernel(GemmArgs P){
  // symmetric pairwise: skip blocks entirely below the diagonal
  if (P.epi == 1 && 2*blockIdx.x + 2 <= blockIdx.y) return;

  extern __shared__ char sm[];
  uint32_t sb = smem_u32(sm);
  int tid = threadIdx.x;
  int w = tid >> 5, l = tid & 31;
  int wm = w & 3;            // 4 m-warps, 32 rows each
  int wn = w >> 2;           // 2 n-warps, 128 cols each
  int bz = blockIdx.z;
  int m0 = blockIdx.y * 128, n0 = blockIdx.x * 256;
  const int nk = P.nseg * P.kcs;

  float acc[2][16][4];
  #pragma unroll
  for (int t = 0; t < 2; t++)
    #pragma unroll
    for (int j = 0; j < 16; j++)
      #pragma unroll
      for (int r = 0; r < 4; r++) acc[t][j][r] = 0.f;

  // ---- stage loader: Ah/Al 128x64, Bh/Bl 256x64, pitch 144B ----
  auto stage_load = [&](int kt){
    int seg = kt / P.kcs, kc = kt % P.kcs;
    const bf16* pa[2] = {
      P.Ah[seg] + (size_t)bz*P.sA + (size_t)m0*P.ldA + (size_t)kc*64,
      P.Al[seg] + (size_t)bz*P.sA + (size_t)m0*P.ldA + (size_t)kc*64 };
    const bf16* pb[2] = {
      P.Bh[seg] + (size_t)bz*P.sB + (size_t)n0*P.ldB + (size_t)kc*64,
      P.Bl[seg] + (size_t)bz*P.sB + (size_t)n0*P.ldB + (size_t)kc*64 };
    uint32_t st = sb + (uint32_t)(kt & 1) * STAGE_B;
    #pragma unroll
    for (int i = 0; i < 8; i++){               // A: 2 parts x 1024 cp16
      int part = i >> 2;
      int q = tid + (i & 3)*256;               // 0..1023
      int row = q >> 3, col = q & 7;
      cp16(st + (part ? OFF_AL : OFF_AH) + row*ROWP + col*16, pa[part] + (size_t)row*P.ldA + col*8);
    }
    #pragma unroll
    for (int i = 0; i < 16; i++){              // B: 2 parts x 2048 cp16
      int part = i >> 3;
      int q = tid + (i & 7)*256;               // 0..2047
      int row = q >> 3, col = q & 7;
      cp16(st + (part ? OFF_BL : OFF_BH) + row*ROWP + col*16, pb[part] + (size_t)row*P.ldB + col*8);
    }
    asm volatile("cp.async.commit_group;" ::: "memory");
  };

  stage_load(0);
  if (nk > 1) stage_load(1);

  for (int kt = 0; kt < nk; kt++){
    if (kt < nk - 1) asm volatile("cp.async.wait_group 1;" ::: "memory");
    else             asm volatile("cp.async.wait_group 0;" ::: "memory");
    __syncthreads();

    uint32_t st = sb + (uint32_t)(kt & 1) * STAGE_B;
    #pragma unroll
    for (int step = 0; step < 4; step++){
      uint32_t ah[2][4], al[2][4];
      #pragma unroll
      for (int t = 0; t < 2; t++){
        int row = wm*32 + t*16 + (l & 15);
        uint32_t koff = (uint32_t)(step*32 + ((l >> 4) & 1)*16);
        uint32_t addr = st + row*ROWP + koff;
        ldsm4(ah[t][0], ah[t][1], ah[t][2], ah[t][3], addr + OFF_AH);
        ldsm4(al[t][0], al[t][1], al[t][2], al[t][3], addr + OFF_AL);
      }
      #pragma unroll
      for (int g = 0; g < 2; g++){
        // batch-load B for 4 jj (8 ldsm4, 32 regs) -> 16 independent acc chains
        uint32_t bh[4][4], bl[4][4];
        #pragma unroll
        for (int q = 0; q < 4; q++){
          int jj = g*4 + q;
          int n = wn*128 + jj*16 + (((l >> 4) & 1) << 3) + (l & 7);
          uint32_t koff = (uint32_t)(step*32 + ((l >> 3) & 1)*16);
          uint32_t addr = st + n*ROWP + koff;
          ldsm4(bh[q][0], bh[q][1], bh[q][2], bh[q][3], addr + OFF_BH);
          ldsm4(bl[q][0], bl[q][1], bl[q][2], bl[q][3], addr + OFF_BL);
        }
        #pragma unroll
        for (int q = 0; q < 4; q++){
          int jj = g*4 + q;
          #pragma unroll
          for (int t = 0; t < 2; t++){
            mma16816(acc[t][2*jj  ], ah[t], bh[q]);
            mma16816(acc[t][2*jj  ], ah[t], bl[q]);
            mma16816(acc[t][2*jj  ], al[t], bh[q]);
            mma16816(acc[t][2*jj+1], ah[t], bh[q]+2);
            mma16816(acc[t][2*jj+1], ah[t], bl[q]+2);
            mma16816(acc[t][2*jj+1], al[t], bh[q]+2);
          }
        }
      }
    }
    __syncthreads();
    if (kt + 2 <= nk - 1) stage_load(kt + 2);
  }

  // ---- epilogue ----
  const float* sqb = nullptr;
  if (P.epi == 1) sqb = P.sq + (size_t)bz*P.sSq;
  float* C = P.C ? (P.C + (size_t)bz*P.sC) : nullptr;
  bf16* Ch = P.Ch ? (P.Ch + (size_t)bz*P.sH) : nullptr;
  bf16* Cl = P.Cl ? (P.Cl + (size_t)bz*P.sH) : nullptr;
  const float* Z = P.Z ? (P.Z + (size_t)bz*P.sZ) : nullptr;
  int lm = l >> 2, ln = (l & 3)*2;

  #pragma unroll
  for (int t = 0; t < 2; t++){
    #pragma unroll
    for (int j = 0; j < 16; j++){
      #pragma unroll
      for (int r = 0; r < 4; r++){
        int m = m0 + wm*32 + t*16 + lm + (r >> 1)*8;
        int n = n0 + wn*128 + j*8 + ln + (r & 1);
        if (m < P.M && n < P.N){
          float a = acc[t][j][r];
          if (P.epi == 0){
            C[(size_t)m*P.ldC + n] = a;
          } else if (P.epi == 1){
            C[(size_t)m*P.ldC + n] = expf(2.f*a - sqb[m] - sqb[n]);
          } else if (P.epi == 2){
            C[(size_t)m*P.ldC + n] = a;
            split2(a, Ch + (size_t)m*P.ldH + n, Cl + (size_t)m*P.ldH + n);
          } else if (P.epi == 3){
            float v = 2.f*a - Z[(size_t)m*P.ldZ + n];
            split2(v, Ch + (size_t)m*P.ldH + n, Cl + (size_t)m*P.ldH + n);
          } else {
            C[(size_t)m*P.ldC + n] = fmaxf(a + P.bias[n], 0.f);
          }
        }
      }
    }
  }
}

// mirror upper triangle of g_L into lower triangle (coalesced tiled transpose)
__global__ void mirror_kernel(){
  int b = blockIdx.z;
  int tx = blockIdx.x, ty = blockIdx.y;
  if (tx <= ty) return;
  __shared__ float t[32][33];
  int x = threadIdx.x, y = threadIdx.y;
  size_t base = (size_t)b*NPTS*NPTS;
  for (int i = 0; i < 32; i += 8){
    int m = ty*32 + y + i, n = tx*32 + x;
    t[y+i][x] = g_L[base + (size_t)m*NPTS + n];
  }
  __syncthreads();
  for (int i = 0; i < 32; i += 8){
    int m = tx*32 + y + i, n = ty*32 + x;
    g_L[base + (size_t)m*NPTS + n] = t[x][y+i];
  }
}

// ---------------- small kernels ----------------
__global__ void zeroacc_kernel(){ if (threadIdx.x < 8) g_acc[threadIdx.x] = 0.f; }

__global__ void pairwise6_kernel(const float* __restrict__ x){
  int b = blockIdx.z;
  int i0 = blockIdx.y*16, j0 = blockIdx.x*16;
  __shared__ float xi[16][6], xj[16][6];
  int tid = threadIdx.y*16 + threadIdx.x;
  if (tid < 96){
    int r = tid/6, c = tid%6;
    xi[r][c] = x[((size_t)b*NPTS + i0 + r)*CINF + c];
    xj[r][c] = x[((size_t)b*NPTS + j0 + r)*CINF + c];
  }
  __syncthreads();
  int i = threadIdx.y, j = threadIdx.x;
  float d = 0.f;
  #pragma unroll
  for (int c = 0; c < 6; c++){ float t = xi[i][c]-xj[j][c]; d += t*t; }
  g_L[((size_t)b*NPTS + i0+i)*NPTS + j0+j] = expf(-d);
}

__global__ void rowsum_kernel(){
  size_t row = blockIdx.x;
  const float* p = g_L + row*NPTS;
  float s = 0.f;
  for (int k = threadIdx.x; k < NPTS; k += 256) s += p[k];
  __shared__ float sh[256];
  sh[threadIdx.x] = s; __syncthreads();
  for (int o = 128; o > 0; o >>= 1){ if (threadIdx.x < o) sh[threadIdx.x] += sh[threadIdx.x+o]; __syncthreads(); }
  if (!threadIdx.x) g_rowsum[row] = sh[0];
}

__global__ void laplacian_kernel(int writeBf16){
  size_t idx = (size_t)blockIdx.x*256 + threadIdx.x;
  size_t total = (size_t)BATCH*NPTS*NPTS;
  if (idx >= total) return;
  size_t bi = idx / NPTS;
  int j = (int)(idx % NPTS);
  int i = (int)(bi % NPTS);
  float a = g_L[idx];
  float v = rsqrtf(g_rowsum[bi]) * a * rsqrtf(g_rowsum[bi - i + j]);
  float Lv = (i == j ? 1.0f : 0.0f) - v;
  g_L[idx] = Lv;
  if (writeBf16) split2(Lv, &g_Lh[idx], &g_Ll[idx]);
}

__global__ void gemv6_kernel(const float* __restrict__ X, const float* __restrict__ Z,
                             float* __restrict__ Y, float s, float t){
  int b = blockIdx.y;
  __shared__ float xs[NPTS*CINF];
  for (int idx = threadIdx.x; idx < NPTS*CINF; idx += 256)
    xs[idx] = X[(size_t)b*NPTS*CINF + idx];
  __syncthreads();
  int warp = threadIdx.x >> 5, lane = threadIdx.x & 31;
  int i = blockIdx.x*8 + warp;
  const float* Lrow = g_L + ((size_t)b*NPTS + i)*NPTS;
  float acc[6] = {0,0,0,0,0,0};
  for (int k = lane; k < NPTS; k += 32){
    float l = Lrow[k];
    #pragma unroll
    for (int c = 0; c < 6; c++) acc[c] += l * xs[k*6 + c];
  }
  #pragma unroll
  for (int c = 0; c < 6; c++)
    for (int o = 16; o > 0; o >>= 1) acc[c] += __shfl_down_sync(0xffffffffu, acc[c], o);
  if (!lane){
    size_t base = ((size_t)b*NPTS + i)*CINF;
    #pragma unroll
    for (int c = 0; c < 6; c++){
      float v = s*acc[c];
      if (Z) v += t*Z[base + c];
      Y[base + c] = v;
    }
  }
}

__global__ void cheb1_out_kernel(const float* __restrict__ x, const float* __restrict__ W1,
                                 const float* __restrict__ b1){
  int f = blockIdx.x*128 + threadIdx.x;
  int row0 = blockIdx.y*16;
  __shared__ float xsr[16][18];
  for (int idx = threadIdx.x; idx < 16*18; idx += 128){
    int r = idx/18, q = idx%18, c = q/3, kk = q%3;
    size_t g = (size_t)(row0 + r)*CINF + c;
    xsr[r][q] = (kk == 0) ? x[g] : ((kk == 1) ? g_x11[g] : g_x21[g]);
  }
  __syncthreads();
  if (f >= F1V) return;
  float w[18];
  #pragma unroll
  for (int q = 0; q < 18; q++) w[q] = W1[q*F1V + f];
  float bb = b1[f];
  for (int r = 0; r < 16; r++){
    float a = bb;
    #pragma unroll
    for (int q = 0; q < 18; q++) a += xsr[r][q]*w[q];
    float v = fmaxf(a, 0.f);
    size_t rowi = (size_t)(row0 + r);
    g_out1[rowi*F1V + f] = v;
    split2(v, &g_out1h[rowi*FPAD + f], &g_out1l[rowi*FPAD + f]);
  }
}

__global__ void regnorm_kernel(const float* __restrict__ outp, const float* __restrict__ xc, int slot){
  int b = blockIdx.y;
  int f = blockIdx.x*128 + threadIdx.x;
  __shared__ float sh[128*6];
  float acc[6] = {0,0,0,0,0,0};
  for (int i0 = 0; i0 < NPTS; i0 += 128){
    __syncthreads();
    for (int idx = threadIdx.x; idx < 128*6; idx += 128)
      sh[idx] = xc[((size_t)b*NPTS + i0)*CINF + idx];
    __syncthreads();
    if (f < F1V){
      for (int ii = 0; ii < 128; ii++){
        float o = outp[((size_t)b*NPTS + i0 + ii)*F1V + f];
        #pragma unroll
        for (int c = 0; c < 6; c++) acc[c] += o*sh[ii*6 + c];
      }
    }
  }
  float s = 0.f;
  #pragma unroll
  for (int c = 0; c < 6; c++) s += acc[c]*acc[c];
  if (f >= F1V) s = 0.f;
  __shared__ float red[128];
  red[threadIdx.x] = s; __syncthreads();
  for (int o = 64; o > 0; o >>= 1){ if (threadIdx.x < o) red[threadIdx.x] += red[threadIdx.x+o]; __syncthreads(); }
  if (!threadIdx.x) atomicAdd(&g_acc[slot], red[0]);
}

__global__ void gathermax_kernel(const int* __restrict__ sccs){
  int br = blockIdx.x;
  int b = br / RR;
  __shared__ int idx[GG];
  for (int t = threadIdx.x; t < GG; t += 256) idx[t] = sccs[(size_t)br*GG + t];
  __syncthreads();
  for (int f = threadIdx.x; f < F1V; f += 256){
    float m = -1e30f;
    for (int g = 0; g < GG; g++)
      m = fmaxf(m, g_out1[((size_t)b*NPTS + idx[g])*F1V + f]);
    g_vR[(size_t)br*F1V + f] = m;
  }
}

__global__ void sqnorm_kernel(){
  size_t row = blockIdx.x;
  const float* p = g_out1 + row*F1V;
  float s = 0.f;
  for (int k = threadIdx.x; k < F1V; k += 256){ float v = p[k]; s += v*v; }
  __shared__ float sh[256];
  sh[threadIdx.x] = s; __syncthreads();
  for (int o = 128; o > 0; o >>= 1){ if (threadIdx.x < o) sh[threadIdx.x] += sh[threadIdx.x+o]; __syncthreads(); }
  if (!threadIdx.x) g_sqn[row] = sh[0];
}

__global__ void colmax_kernel(const float* __restrict__ src, float* __restrict__ dst, int rows){
  int b = blockIdx.y;
  int f = blockIdx.x*256 + threadIdx.x;
  if (f >= F1V) return;
  float m = -1e30f;
  for (int i = 0; i < rows; i++)
    m = fmaxf(m, src[((size_t)b*rows + i)*F1V + f]);
  dst[(size_t)b*F1V + f] = m;
}

// transpose fp32 [b][2048][1000] -> bf16 split2 [b][1024 rows(n)][2048]
__global__ void transpose_hilo_kernel(const float* __restrict__ src,
                                      bf16* __restrict__ dh, bf16* __restrict__ dl){
  int b = blockIdx.z;
  __shared__ float t[32][33];
  int m0 = blockIdx.x*32, n0 = blockIdx.y*32;
  int x = threadIdx.x, y = threadIdx.y;
  for (int i = 0; i < 32; i += 8){
    int n = n0 + x, m = m0 + y + i;
    t[y+i][x] = (n < F1V) ? src[((size_t)b*NPTS + m)*F1V + n] : 0.f;
  }
  __syncthreads();
  for (int i = 0; i < 32; i += 8){
    int n = n0 + y + i, m = m0 + x;
    if (n < F1V){
      float v = t[x][y+i];
      size_t o = ((size_t)b*FPAD + n)*NPTS + m;
      split2(v, &dh[o], &dl[o]);
    }
  }
}

// W2 (3000,1000) interleaved rows (3c+k) -> W2T[seg][n][c] = W2[3c+seg][n]
__global__ void w2t_kernel(const float* __restrict__ W2){
  int seg = blockIdx.z;
  __shared__ float t[32][33];
  int k0 = blockIdx.x*32, n0 = blockIdx.y*32;
  int x = threadIdx.x, y = threadIdx.y;
  for (int i = 0; i < 32; i += 8){
    int n = n0 + x, k = k0 + y + i;
    t[y+i][x] = (n < F1V && k < F1V) ? W2[(size_t)(3*k + seg)*F1V + n] : 0.f;
  }
  __syncthreads();
  for (int i = 0; i < 32; i += 8){
    int n = n0 + y + i, k = k0 + x;
    if (n < F1V && k < F1V){
      size_t o = (size_t)seg*FPAD*FPAD + (size_t)n*FPAD + k;
      split2(t[x][y+i], &g_W2Th[o], &g_W2Tl[o]);
    }
  }
}

__global__ void wrt_kernel(const float* __restrict__ Wr){
  __shared__ float t[32][33];
  int q0 = blockIdx.x*32, n0 = blockIdx.y*32;
  int x = threadIdx.x, y = threadIdx.y;
  for (int i = 0; i < 32; i += 8){
    int n = n0 + x, q = q0 + y + i;
    t[y+i][x] = (n < F1V && q < 6000) ? Wr[(size_t)q*F1V + n] : 0.f;
  }
  __syncthreads();
  for (int i = 0; i < 32; i += 8){
    int n = n0 + y + i, q = q0 + x;
    if (n < F1V && q < 6000){
      size_t o = (size_t)n*RK + q;
      split2(t[x][y+i], &g_WrTh[o], &g_WrTl[o]);
    }
  }
}

__global__ void reeb_xs_kernel(const float* __restrict__ Lr){
  int b = blockIdx.y;
  int c = blockIdx.x*128 + threadIdx.x;
  __shared__ float Ls[RR*RR];
  for (int t = threadIdx.x; t < RR*RR; t += 128) Ls[t] = Lr[(size_t)b*RR*RR + t];
  __syncthreads();
  if (c >= F1V) return;
  float v0[RR], v1[RR], v2[RR];
  #pragma unroll
  for (int r = 0; r < RR; r++){
    v0[r] = g_vR[((size_t)b*RR + r)*F1V + c];
    size_t o = (size_t)(b*RR + r)*RK + c*6 + 0;
    split2(v0[r], &g_xsRh[o], &g_xsRl[o]);
  }
  #pragma unroll
  for (int r = 0; r < RR; r++){
    float s = 0.f;
    for (int r2 = 0; r2 < RR; r2++) s += Ls[r*RR + r2]*v0[r2];
    v1[r] = s;
    size_t o = (size_t)(b*RR + r)*RK + c*6 + 1;
    split2(s, &g_xsRh[o], &g_xsRl[o]);
  }
  for (int k = 2; k < 6; k++){
    #pragma unroll
    for (int r = 0; r < RR; r++){
      float s = 0.f;
      for (int r2 = 0; r2 < RR; r2++) s += Ls[r*RR + r2]*v1[r2];
      v2[r] = 2.f*s - v0[r];
      size_t o = (size_t)(b*RR + r)*RK + c*6 + k;
      split2(v2[r], &g_xsRh[o], &g_xsRl[o]);
    }
    #pragma unroll
    for (int r = 0; r < RR; r++){ v0[r] = v1[r]; v1[r] = v2[r]; }
  }
}

__global__ void fc1_kernel(const float* __restrict__ W, const float* __restrict__ bias){
  int b = blockIdx.x;
  __shared__ float ft[2*F1V];
  for (int c = threadIdx.x; c < 2*F1V; c += 512)
    ft[c] = (c < F1V) ? g_gR[(size_t)b*F1V + c] : g_g[(size_t)b*F1V + c - F1V];
  __syncthreads();
  int f = threadIdx.x;
  float a = bias[f];
  for (int c = 0; c < 2*F1V; c++) a += ft[c]*W[(size_t)c*512 + f];
  g_h1[b*512 + f] = fmaxf(a, 0.f);
}

__global__ void fc2_kernel(const float* __restrict__ W, const float* __restrict__ bias){
  int b = blockIdx.x;
  __shared__ float hs[512];
  for (int c = threadIdx.x; c < 512; c += 128) hs[c] = g_h1[b*512 + c];
  __syncthreads();
  int f = threadIdx.x;
  float a = bias[f];
  for (int c = 0; c < 512; c++) a += hs[c]*W[c*128 + f];
  g_h2[b*128 + f] = fmaxf(a, 0.f);
}

__global__ void fc3_kernel(const float* __restrict__ W, const float* __restrict__ bias, float* __restrict__ out){
  int b = blockIdx.x;
  __shared__ float hs[128];
  for (int c = threadIdx.x; c < 128; c += 64) hs[c] = g_h2[b*128 + c];
  __syncthreads();
  int f = threadIdx.x;
  if (f < NCLS){
    float a = bias[f];
    for (int c = 0; c < 128; c++) a += hs[c]*W[c*NCLS + f];
    out[b*NCLS + f] = a;
  }
}

__global__ void wreg_kernel(const float* W1, const float* B1, const float* W2, const float* B2,
                            const float* W3, const float* B3, float* out){
  int layer = blockIdx.x;
  const float* W; const float* Bp; int n, ld;
  if (layer == 0){ W = W1; Bp = B1; n = 2000; ld = 512; }
  else if (layer == 1){ W = W2; Bp = B2; n = 512; ld = 128; }
  else { W = W3; Bp = B3; n = 128; ld = 40; }
  float s = 0.f;
  for (int c = threadIdx.x; c < n; c += 256){ float v = W[(size_t)c*ld]; s += v*v; }
  __shared__ float sh[256];
  sh[threadIdx.x] = s; __syncthreads();
  for (int o = 128; o > 0; o >>= 1){ if (threadIdx.x < o) sh[threadIdx.x] += sh[threadIdx.x+o]; __syncthreads(); }
  if (!threadIdx.x){ out[642 + layer*2] = sh[0]; out[643 + layer*2] = Bp[0]*Bp[0]; }
}

__global__ void finalize_kernel(float* out){
  out[640] = sqrtf(g_acc[0]);
  out[641] = sqrtf(g_acc[1]);
}

// ---------------- host launch ----------------
extern "C" void kernel_launch(void* const* d_in, const int* in_sizes, int n_in,
                              void* d_out, int out_size){
  const float* x    = (const float*)d_in[0];
  const float* Lr   = (const float*)d_in[1];
  const int*   sccs = (const int*)  d_in[2];
  const float* W1   = (const float*)d_in[3];  const float* b1  = (const float*)d_in[4];
  const float* W2   = (const float*)d_in[5];  const float* b2  = (const float*)d_in[6];
  const float* Wr   = (const float*)d_in[7];  const float* br  = (const float*)d_in[8];
  const float* Wfc1 = (const float*)d_in[9];  const float* bfc1= (const float*)d_in[10];
  const float* Wfc2 = (const float*)d_in[11]; const float* bfc2= (const float*)d_in[12];
  const float* Wfc3 = (const float*)d_in[13]; const float* bfc3= (const float*)d_in[14];
  float* out = (float*)d_out;

  static bool attr_done = false;
  if (!attr_done){
    cudaFuncSetAttribute(hgemm_kernel, cudaFuncAttributeMaxDynamicSharedMemorySize, HSM_TOT);
    attr_done = true;
  }

  float *pL, *pout1, *px12, *pout2, *px11, *px21, *pLx, *psqn, *poutR, *pg, *pgR;
  bf16 *pLh, *pLl, *pout1h, *pout1l, *pout1Th, *pout1Tl;
  bf16 *px12h, *px12l, *px12Th, *px12Tl;
  bf16 *px22h, *px22l, *pW2Th, *pW2Tl;
  bf16 *pxsRh, *pxsRl, *pWrTh, *pWrTl;
  cudaGetSymbolAddress((void**)&pL,      g_L);
  cudaGetSymbolAddress((void**)&pout1,   g_out1);
  cudaGetSymbolAddress((void**)&px12,    g_x12);
  cudaGetSymbolAddress((void**)&pout2,   g_out2);
  cudaGetSymbolAddress((void**)&px11,    g_x11);
  cudaGetSymbolAddress((void**)&px21,    g_x21);
  cudaGetSymbolAddress((void**)&pLx,     g_Lx);
  cudaGetSymbolAddress((void**)&psqn,    g_sqn);
  cudaGetSymbolAddress((void**)&poutR,   g_outR);
  cudaGetSymbolAddress((void**)&pg,      g_g);
  cudaGetSymbolAddress((void**)&pgR,     g_gR);
  cudaGetSymbolAddress((void**)&pLh,     g_Lh);
  cudaGetSymbolAddress((void**)&pLl,     g_Ll);
  cudaGetSymbolAddress((void**)&pout1h,  g_out1h);
  cudaGetSymbolAddress((void**)&pout1l,  g_out1l);
  cudaGetSymbolAddress((void**)&pout1Th, g_out1Th);
  cudaGetSymbolAddress((void**)&pout1Tl, g_out1Tl);
  cudaGetSymbolAddress((void**)&px12h,   g_x12h);
  cudaGetSymbolAddress((void**)&px12l,   g_x12l);
  cudaGetSymbolAddress((void**)&px12Th,  g_x12Th);
  cudaGetSymbolAddress((void**)&px12Tl,  g_x12Tl);
  cudaGetSymbolAddress((void**)&px22h,   g_x22h);
  cudaGetSymbolAddress((void**)&px22l,   g_x22l);
  cudaGetSymbolAddress((void**)&pW2Th,   g_W2Th);
  cudaGetSymbolAddress((void**)&pW2Tl,   g_W2Tl);
  cudaGetSymbolAddress((void**)&pxsRh,   g_xsRh);
  cudaGetSymbolAddress((void**)&pxsRl,   g_xsRl);
  cudaGetSymbolAddress((void**)&pWrTh,   g_WrTh);
  cudaGetSymbolAddress((void**)&pWrTl,   g_WrTl);

  zeroacc_kernel<<<1, 32>>>();

  // L1 from pairwise(x)
  pairwise6_kernel<<<dim3(NPTS/16, NPTS/16, BATCH), dim3(16,16)>>>(x);
  rowsum_kernel<<<BATCH*NPTS, 256>>>();
  laplacian_kernel<<<(unsigned)(((size_t)BATCH*NPTS*NPTS + 255)/256), 256>>>(0);

  // cheb conv 1
  gemv6_kernel<<<dim3(NPTS/8, BATCH), 256>>>(x, nullptr, px11, 1.f, 0.f);
  gemv6_kernel<<<dim3(NPTS/8, BATCH), 256>>>(px11, x, px21, 2.f, -1.f);
  cheb1_out_kernel<<<dim3(8, (BATCH*NPTS)/16), 128>>>(x, W1, b1);
  transpose_hilo_kernel<<<dim3(NPTS/32, 32, BATCH), dim3(32,8)>>>(pout1, pout1Th, pout1Tl);
  regnorm_kernel<<<dim3(8, BATCH), 128>>>(pout1, px11, 0);
  gathermax_kernel<<<BATCH*RR, 256>>>(sccs);
  sqnorm_kernel<<<BATCH*NPTS, 256>>>();

  GemmArgs A{};
  // adj2 = exp(2*out1@out1^T - sq_m - sq_n), upper blocks then mirror
  for (int s = 0; s < 3; s++){
    A.Ah[s]=pout1h; A.Al[s]=pout1l;
    A.Bh[s]=pout1h; A.Bl[s]=pout1l;
  }
  A.ldA = FPAD; A.ldB = FPAD; A.sA = (long)NPTS*FPAD; A.sB = (long)NPTS*FPAD;
  A.C = pL; A.ldC = NPTS; A.sC = (long)NPTS*NPTS;
  A.Ch = nullptr; A.Cl = nullptr; A.ldH = 0; A.sH = 0;
  A.Z = nullptr; A.ldZ = 0; A.sZ = 0; A.bias = nullptr;
  A.sq = psqn; A.sSq = NPTS;
  A.M = NPTS; A.N = NPTS; A.nseg = 1; A.kcs = FPAD/64; A.epi = 1;
  hgemm_kernel<<<dim3(8,16,BATCH), 256, HSM_TOT>>>(A);
  mirror_kernel<<<dim3(NPTS/32, NPTS/32, BATCH), dim3(32,8)>>>();

  rowsum_kernel<<<BATCH*NPTS, 256>>>();
  laplacian_kernel<<<(unsigned)(((size_t)BATCH*NPTS*NPTS + 255)/256), 256>>>(1);

  // x12 = L2 @ out1
  for (int s = 0; s < 3; s++){
    A.Ah[s]=pLh; A.Al[s]=pLl;
    A.Bh[s]=pout1Th; A.Bl[s]=pout1Tl;
  }
  A.ldA = NPTS; A.ldB = NPTS; A.sA = (long)NPTS*NPTS; A.sB = (long)FPAD*NPTS;
  A.C = px12; A.ldC = F1V; A.sC = (long)NPTS*F1V;
  A.Ch = px12h; A.Cl = px12l; A.ldH = FPAD; A.sH = (long)NPTS*FPAD;
  A.Z = nullptr; A.sq = nullptr; A.bias = nullptr;
  A.M = NPTS; A.N = F1V; A.nseg = 1; A.kcs = NPTS/64; A.epi = 2;
  hgemm_kernel<<<dim3(4,16,BATCH), 256, HSM_TOT>>>(A);

  transpose_hilo_kernel<<<dim3(NPTS/32, 32, BATCH), dim3(32,8)>>>(px12, px12Th, px12Tl);

  // x22 = 2*L2@x12 - out1 (split2 only)
  for (int s = 0; s < 3; s++){
    A.Ah[s]=pLh; A.Al[s]=pLl;
    A.Bh[s]=px12Th; A.Bl[s]=px12Tl;
  }
  A.C = nullptr; A.ldC = 0; A.sC = 0;
  A.Ch = px22h; A.Cl = px22l; A.ldH = FPAD; A.sH = (long)NPTS*FPAD;
  A.Z = pout1; A.ldZ = F1V; A.sZ = (long)NPTS*F1V;
  A.M = NPTS; A.N = F1V; A.nseg = 1; A.kcs = NPTS/64; A.epi = 3;
  hgemm_kernel<<<dim3(4,16,BATCH), 256, HSM_TOT>>>(A);

  // W2 transposed split2 (interleaved rows 3c+seg)
  w2t_kernel<<<dim3(32, 32, 3), dim3(32,8)>>>(W2);

  // out2 = relu(out1@W2a + x12@W2b + x22@W2c + b2), M flattened
  A.Ah[0]=pout1h; A.Al[0]=pout1l;
  A.Ah[1]=px12h;  A.Al[1]=px12l;
  A.Ah[2]=px22h;  A.Al[2]=px22l;
  A.Bh[0]=pW2Th;                       A.Bl[0]=pW2Tl;
  A.Bh[1]=pW2Th + (size_t)FPAD*FPAD;   A.Bl[1]=pW2Tl + (size_t)FPAD*FPAD;
  A.Bh[2]=pW2Th + (size_t)2*FPAD*FPAD; A.Bl[2]=pW2Tl + (size_t)2*FPAD*FPAD;
  A.ldA = FPAD; A.ldB = FPAD; A.sA = 0; A.sB = 0;
  A.C = pout2; A.ldC = F1V; A.sC = 0;
  A.Ch = nullptr; A.Cl = nullptr; A.Z = nullptr;
  A.bias = b2;
  A.M = BATCH*NPTS; A.N = F1V; A.nseg = 3; A.kcs = FPAD/64; A.epi = 4;
  hgemm_kernel<<<dim3(4,256,1), 256, HSM_TOT>>>(A);

  // reg1 = ||out2^T (L2 x)||
  gemv6_kernel<<<dim3(NPTS/8, BATCH), 256>>>(x, nullptr, pLx, 1.f, 0.f);
  regnorm_kernel<<<dim3(8, BATCH), 128>>>(pout2, pLx, 1);
  colmax_kernel<<<dim3(4, BATCH), 256>>>(pout2, pg, NPTS);

  // Reeb branch
  reeb_xs_kernel<<<dim3(8, BATCH), 128>>>(Lr);
  wrt_kernel<<<dim3(188, 32), dim3(32,8)>>>(Wr);
  A.Ah[0]=pxsRh; A.Al[0]=pxsRl;
  A.Ah[1]=pxsRh; A.Al[1]=pxsRl;
  A.Ah[2]=pxsRh; A.Al[2]=pxsRl;
  A.Bh[0]=pWrTh; A.Bl[0]=pWrTl;
  A.Bh[1]=pWrTh; A.Bl[1]=pWrTl;
  A.Bh[2]=pWrTh; A.Bl[2]=pWrTl;
  A.ldA = RK; A.ldB = RK; A.sA = 0; A.sB = 0;
  A.C = poutR; A.ldC = F1V; A.sC = 0;
  A.Ch = nullptr; A.Cl = nullptr; A.Z = nullptr;
  A.bias = br;
  A.M = BATCH*RR; A.N = F1V; A.nseg = 1; A.kcs = RK/64; A.epi = 4;
  hgemm_kernel<<<dim3(4,3,1), 256, HSM_TOT>>>(A);
  colmax_kernel<<<dim3(4, BATCH), 256>>>(poutR, pgR, RR);

  // FC head
  fc1_kernel<<<BATCH, 512>>>(Wfc1, bfc1);
  fc2_kernel<<<BATCH, 128>>>(Wfc2, bfc2);
  fc3_kernel<<<BATCH, 64>>>(Wfc3, bfc3, out);

  // regs
  wreg_kernel<<<3, 256>>>(Wfc1, bfc1, Wfc2, bfc2, Wfc3, bfc3, out);
  finalize_kernel<<<1, 1>>>(out);
}

// round 11
// speedup vs baseline: 1.0420x; 1.0420x over previous
#include <cuda_runtime.h>
#include <cuda_bf16.h>
#include <math.h>
#include <stdint.h>

#define BATCH 16
#define NPTS 2048
#define CINF 6
#define RR 20
#define GG 128
#define F1V 1000
#define NCLS 40
#define FPAD 1024
#define RK 6016
#define RM 384

typedef __nv_bfloat16 bf16;

// ---------------- scratch (device globals; zero-initialized, no allocations) ----------------
__device__ float g_L[(size_t)BATCH*NPTS*NPTS];
__device__ float g_out1[(size_t)BATCH*NPTS*F1V];
__device__ float g_x12[(size_t)BATCH*NPTS*F1V];
__device__ float g_out2[(size_t)BATCH*NPTS*F1V];
__device__ bf16  g_Lh[(size_t)BATCH*NPTS*NPTS];
__device__ bf16  g_Ll[(size_t)BATCH*NPTS*NPTS];
__device__ bf16  g_out1h[(size_t)BATCH*NPTS*FPAD];
__device__ bf16  g_out1l[(size_t)BATCH*NPTS*FPAD];
__device__ bf16  g_out1Th[(size_t)BATCH*FPAD*NPTS];
__device__ bf16  g_out1Tl[(size_t)BATCH*FPAD*NPTS];
__device__ bf16  g_x12h[(size_t)BATCH*NPTS*FPAD];
__device__ bf16  g_x12l[(size_t)BATCH*NPTS*FPAD];
__device__ bf16  g_x12Th[(size_t)BATCH*FPAD*NPTS];
__device__ bf16  g_x12Tl[(size_t)BATCH*FPAD*NPTS];
__device__ bf16  g_x22h[(size_t)BATCH*NPTS*FPAD];
__device__ bf16  g_x22l[(size_t)BATCH*NPTS*FPAD];
__device__ bf16  g_W2Th[3*FPAD*FPAD];
__device__ bf16  g_W2Tl[3*FPAD*FPAD];
__device__ bf16  g_xsRh[(size_t)RM*RK];
__device__ bf16  g_xsRl[(size_t)RM*RK];
__device__ bf16  g_WrTh[(size_t)FPAD*RK];
__device__ bf16  g_WrTl[(size_t)FPAD*RK];
__device__ float g_x11[BATCH*NPTS*CINF];
__device__ float g_x21[BATCH*NPTS*CINF];
__device__ float g_Lx[BATCH*NPTS*CINF];
__device__ float g_rowsum[BATCH*NPTS];
__device__ float g_sqn[BATCH*NPTS];
__device__ float g_vR[BATCH*RR*F1V];
__device__ float g_outR[BATCH*RR*F1V];
__device__ float g_g[BATCH*F1V];
__device__ float g_gR[BATCH*F1V];
__device__ float g_h1[BATCH*512];
__device__ float g_h2[BATCH*128];
__device__ float g_acc[8];

// ---------------- helpers ----------------
__device__ __forceinline__ uint32_t smem_u32(const void* p){
  uint32_t a;
  asm("{ .reg .u64 t; cvta.to.shared.u64 t, %1; cvt.u32.u64 %0, t; }" : "=r"(a) : "l"(p));
  return a;
}
__device__ __forceinline__ void cp16(uint32_t s, const void* g){
  asm volatile("cp.async.cg.shared.global [%0], [%1], 16;" :: "r"(s), "l"(g));
}
__device__ __forceinline__ void ldsm4(uint32_t& r0, uint32_t& r1, uint32_t& r2, uint32_t& r3, uint32_t a){
  asm volatile("ldmatrix.sync.aligned.m8n8.x4.shared.b16 {%0,%1,%2,%3}, [%4];"
    : "=r"(r0), "=r"(r1), "=r"(r2), "=r"(r3) : "r"(a));
}
__device__ __forceinline__ void mma16816(float* d, const uint32_t* a, const uint32_t* b){
  asm volatile("mma.sync.aligned.m16n8k16.row.col.f32.bf16.bf16.f32 "
    "{%0,%1,%2,%3}, {%4,%5,%6,%7}, {%8,%9}, {%0,%1,%2,%3};"
    : "+f"(d[0]), "+f"(d[1]), "+f"(d[2]), "+f"(d[3])
    : "r"(a[0]), "r"(a[1]), "r"(a[2]), "r"(a[3]), "r"(b[0]), "r"(b[1]));
}
__device__ __forceinline__ void split2(float v, bf16* ph, bf16* pl){
  bf16 h = __float2bfloat16(v);
  *ph = h;
  *pl = __float2bfloat16(v - __bfloat162float(h));
}

// ---------------- HMMA GEMM: C[M,N], CTA tile 128x128, BK=32, 2-stage, 2 CTAs/SM ----------------
// epi: 0 plain C; 1 exp(2a - sq[m] - sq[n]) upper-only; 2 C + split2; 3 split2 of (2a - Z); 4 relu(a + bias[n])
struct GemmArgs {
  const bf16 *Ah[3], *Al[3], *Bh[3], *Bl[3];
  long ldA, ldB, sA, sB;
  float* C; long ldC, sC;
  bf16 *Ch, *Cl; long ldH, sH;
  const float* Z; long ldZ, sZ;
  const float* bias;
  const float* sq; long sSq;
  int M, N, nseg, kcs, epi;
};

#define STAGE_B 40960          // 4 parts * 128 rows * 80 bytes
#define PART_B  10240
#define HSM_TOT (2*STAGE_B)    // 81920 -> 2 CTAs per SM

__global__ __launch_bounds__(256, 2) void hgemm_kernel(GemmArgs P){
  // symmetric pairwise: skip lower-triangle blocks
  if (P.epi == 1 && blockIdx.x < blockIdx.y) return;

  extern __shared__ char sm[];
  uint32_t sb = smem_u32(sm);
  int tid = threadIdx.x;
  int w = tid >> 5, l = tid & 31;
  int wm = w & 3;
  int wn = w >> 2;
  int bz = blockIdx.z;
  int m0 = blockIdx.y * 128, n0 = blockIdx.x * 128;
  const int nk = P.nseg * P.kcs;

  float acc[2][8][4];
  #pragma unroll
  for (int t = 0; t < 2; t++)
    #pragma unroll
    for (int j = 0; j < 8; j++)
      #pragma unroll
      for (int r = 0; r < 4; r++) acc[t][j][r] = 0.f;

  // ---- stage loader: 4 parts (aH aL bH bL), each 128x32 bf16, pitch 80B ----
  auto stage_load = [&](int kt){
    int seg = kt / P.kcs, kc = kt % P.kcs;
    const bf16* pa[2] = {
      P.Ah[seg] + (size_t)bz*P.sA + (size_t)m0*P.ldA + (size_t)kc*32,
      P.Al[seg] + (size_t)bz*P.sA + (size_t)m0*P.ldA + (size_t)kc*32 };
    const bf16* pb[2] = {
      P.Bh[seg] + (size_t)bz*P.sB + (size_t)n0*P.ldB + (size_t)kc*32,
      P.Bl[seg] + (size_t)bz*P.sB + (size_t)n0*P.ldB + (size_t)kc*32 };
    uint32_t st = sb + (uint32_t)(kt & 1) * STAGE_B;
    #pragma unroll
    for (int i = 0; i < 8; i++){
      int part = i >> 1;                 // 0..3
      int cid = tid + (i & 1)*256;       // 0..511
      int row = cid >> 2, col = cid & 3;
      const bf16* gp = (part < 2) ? pa[part] : pb[part - 2];
      long ld = (part < 2) ? P.ldA : P.ldB;
      cp16(st + part*PART_B + row*80 + col*16, gp + (size_t)row*ld + col*8);
    }
    asm volatile("cp.async.commit_group;" ::: "memory");
  };

  stage_load(0);

  for (int kt = 0; kt < nk; kt++){
    if (kt + 1 < nk){
      stage_load(kt + 1);
      asm volatile("cp.async.wait_group 1;" ::: "memory");
    } else {
      asm volatile("cp.async.wait_group 0;" ::: "memory");
    }
    __syncthreads();

    uint32_t st = sb + (uint32_t)(kt & 1) * STAGE_B;
    #pragma unroll
    for (int step = 0; step < 2; step++){
      uint32_t ah[2][4], al[2][4];
      #pragma unroll
      for (int t = 0; t < 2; t++){
        int row = wm*32 + t*16 + (l & 15);
        uint32_t koff = (uint32_t)(step*32 + ((l >> 4) & 1)*16);
        uint32_t addr = st + row*80 + koff;
        ldsm4(ah[t][0], ah[t][1], ah[t][2], ah[t][3], addr);
        ldsm4(al[t][0], al[t][1], al[t][2], al[t][3], addr + PART_B);
      }
      uint32_t bh[8][2], bl[8][2];
      #pragma unroll
      for (int j = 0; j < 4; j++){
        int n = wn*64 + j*16 + (((l >> 4) & 1) << 3) + (l & 7);
        uint32_t koff = (uint32_t)(step*32 + ((l >> 3) & 1)*16);
        uint32_t addr = st + 2*PART_B + n*80 + koff;
        ldsm4(bh[2*j][0], bh[2*j][1], bh[2*j+1][0], bh[2*j+1][1], addr);
        ldsm4(bl[2*j][0], bl[2*j][1], bl[2*j+1][0], bl[2*j+1][1], addr + PART_B);
      }
      #pragma unroll
      for (int t = 0; t < 2; t++)
        #pragma unroll
        for (int j = 0; j < 8; j++){
          mma16816(acc[t][j], ah[t], bh[j]);
          mma16816(acc[t][j], ah[t], bl[j]);
          mma16816(acc[t][j], al[t], bh[j]);
        }
    }
    __syncthreads();
  }

  // ---- epilogue ----
  const float* sqb = nullptr;
  if (P.epi == 1) sqb = P.sq + (size_t)bz*P.sSq;
  float* C = P.C ? (P.C + (size_t)bz*P.sC) : nullptr;
  bf16* Ch = P.Ch ? (P.Ch + (size_t)bz*P.sH) : nullptr;
  bf16* Cl = P.Cl ? (P.Cl + (size_t)bz*P.sH) : nullptr;
  const float* Z = P.Z ? (P.Z + (size_t)bz*P.sZ) : nullptr;
  int lm = l >> 2, ln = (l & 3)*2;

  #pragma unroll
  for (int t = 0; t < 2; t++){
    #pragma unroll
    for (int j = 0; j < 8; j++){
      #pragma unroll
      for (int r = 0; r < 4; r++){
        int m = m0 + wm*32 + t*16 + lm + (r >> 1)*8;
        int n = n0 + wn*64 + j*8 + ln + (r & 1);
        if (m < P.M && n < P.N){
          float a = acc[t][j][r];
          if (P.epi == 0){
            C[(size_t)m*P.ldC + n] = a;
          } else if (P.epi == 1){
            C[(size_t)m*P.ldC + n] = expf(2.f*a - sqb[m] - sqb[n]);
          } else if (P.epi == 2){
            C[(size_t)m*P.ldC + n] = a;
            split2(a, Ch + (size_t)m*P.ldH + n, Cl + (size_t)m*P.ldH + n);
          } else if (P.epi == 3){
            float v = 2.f*a - Z[(size_t)m*P.ldZ + n];
            split2(v, Ch + (size_t)m*P.ldH + n, Cl + (size_t)m*P.ldH + n);
          } else {
            C[(size_t)m*P.ldC + n] = fmaxf(a + P.bias[n], 0.f);
          }
        }
      }
    }
  }
}

// mirror upper triangle of g_L into lower triangle (coalesced tiled transpose)
__global__ void mirror_kernel(){
  int b = blockIdx.z;
  int tx = blockIdx.x, ty = blockIdx.y;
  if (tx <= ty) return;
  __shared__ float t[32][33];
  int x = threadIdx.x, y = threadIdx.y;
  size_t base = (size_t)b*NPTS*NPTS;
  for (int i = 0; i < 32; i += 8){
    int m = ty*32 + y + i, n = tx*32 + x;
    t[y+i][x] = g_L[base + (size_t)m*NPTS + n];
  }
  __syncthreads();
  for (int i = 0; i < 32; i += 8){
    int m = tx*32 + y + i, n = ty*32 + x;
    g_L[base + (size_t)m*NPTS + n] = t[x][y+i];
  }
}

// ---------------- small kernels ----------------
__global__ void zeroacc_kernel(){ if (threadIdx.x < 8) g_acc[threadIdx.x] = 0.f; }

__global__ void pairwise6_kernel(const float* __restrict__ x){
  int b = blockIdx.z;
  int i0 = blockIdx.y*16, j0 = blockIdx.x*16;
  __shared__ float xi[16][6], xj[16][6];
  int tid = threadIdx.y*16 + threadIdx.x;
  if (tid < 96){
    int r = tid/6, c = tid%6;
    xi[r][c] = x[((size_t)b*NPTS + i0 + r)*CINF + c];
    xj[r][c] = x[((size_t)b*NPTS + j0 + r)*CINF + c];
  }
  __syncthreads();
  int i = threadIdx.y, j = threadIdx.x;
  float d = 0.f;
  #pragma unroll
  for (int c = 0; c < 6; c++){ float t = xi[i][c]-xj[j][c]; d += t*t; }
  g_L[((size_t)b*NPTS + i0+i)*NPTS + j0+j] = expf(-d);
}

__global__ void rowsum_kernel(){
  size_t row = blockIdx.x;
  const float* p = g_L + row*NPTS;
  float s = 0.f;
  for (int k = threadIdx.x; k < NPTS; k += 256) s += p[k];
  __shared__ float sh[256];
  sh[threadIdx.x] = s; __syncthreads();
  for (int o = 128; o > 0; o >>= 1){ if (threadIdx.x < o) sh[threadIdx.x] += sh[threadIdx.x+o]; __syncthreads(); }
  if (!threadIdx.x) g_rowsum[row] = sh[0];
}

__global__ void laplacian_kernel(int writeBf16){
  size_t idx = (size_t)blockIdx.x*256 + threadIdx.x;
  size_t total = (size_t)BATCH*NPTS*NPTS;
  if (idx >= total) return;
  size_t bi = idx / NPTS;
  int j = (int)(idx % NPTS);
  int i = (int)(bi % NPTS);
  float a = g_L[idx];
  float v = rsqrtf(g_rowsum[bi]) * a * rsqrtf(g_rowsum[bi - i + j]);
  float Lv = (i == j ? 1.0f : 0.0f) - v;
  g_L[idx] = Lv;
  if (writeBf16) split2(Lv, &g_Lh[idx], &g_Ll[idx]);
}

__global__ void gemv6_kernel(const float* __restrict__ X, const float* __restrict__ Z,
                             float* __restrict__ Y, float s, float t){
  int b = blockIdx.y;
  __shared__ float xs[NPTS*CINF];
  for (int idx = threadIdx.x; idx < NPTS*CINF; idx += 256)
    xs[idx] = X[(size_t)b*NPTS*CINF + idx];
  __syncthreads();
  int warp = threadIdx.x >> 5, lane = threadIdx.x & 31;
  int i = blockIdx.x*8 + warp;
  const float* Lrow = g_L + ((size_t)b*NPTS + i)*NPTS;
  float acc[6] = {0,0,0,0,0,0};
  for (int k = lane; k < NPTS; k += 32){
    float l = Lrow[k];
    #pragma unroll
    for (int c = 0; c < 6; c++) acc[c] += l * xs[k*6 + c];
  }
  #pragma unroll
  for (int c = 0; c < 6; c++)
    for (int o = 16; o > 0; o >>= 1) acc[c] += __shfl_down_sync(0xffffffffu, acc[c], o);
  if (!lane){
    size_t base = ((size_t)b*NPTS + i)*CINF;
    #pragma unroll
    for (int c = 0; c < 6; c++){
      float v = s*acc[c];
      if (Z) v += t*Z[base + c];
      Y[base + c] = v;
    }
  }
}

__global__ void cheb1_out_kernel(const float* __restrict__ x, const float* __restrict__ W1,
                                 const float* __restrict__ b1){
  int f = blockIdx.x*128 + threadIdx.x;
  int row0 = blockIdx.y*16;
  __shared__ float xsr[16][18];
  for (int idx = threadIdx.x; idx < 16*18; idx += 128){
    int r = idx/18, q = idx%18, c = q/3, kk = q%3;
    size_t g = (size_t)(row0 + r)*CINF + c;
    xsr[r][q] = (kk == 0) ? x[g] : ((kk == 1) ? g_x11[g] : g_x21[g]);
  }
  __syncthreads();
  if (f >= F1V) return;
  float w[18];
  #pragma unroll
  for (int q = 0; q < 18; q++) w[q] = W1[q*F1V + f];
  float bb = b1[f];
  for (int r = 0; r < 16; r++){
    float a = bb;
    #pragma unroll
    for (int q = 0; q < 18; q++) a += xsr[r][q]*w[q];
    float v = fmaxf(a, 0.f);
    size_t rowi = (size_t)(row0 + r);
    g_out1[rowi*F1V + f] = v;
    split2(v, &g_out1h[rowi*FPAD + f], &g_out1l[rowi*FPAD + f]);
  }
}

__global__ void regnorm_kernel(const float* __restrict__ outp, const float* __restrict__ xc, int slot){
  int b = blockIdx.y;
  int f = blockIdx.x*128 + threadIdx.x;
  __shared__ float sh[128*6];
  float acc[6] = {0,0,0,0,0,0};
  for (int i0 = 0; i0 < NPTS; i0 += 128){
    __syncthreads();
    for (int idx = threadIdx.x; idx < 128*6; idx += 128)
      sh[idx] = xc[((size_t)b*NPTS + i0)*CINF + idx];
    __syncthreads();
    if (f < F1V){
      for (int ii = 0; ii < 128; ii++){
        float o = outp[((size_t)b*NPTS + i0 + ii)*F1V + f];
        #pragma unroll
        for (int c = 0; c < 6; c++) acc[c] += o*sh[ii*6 + c];
      }
    }
  }
  float s = 0.f;
  #pragma unroll
  for (int c = 0; c < 6; c++) s += acc[c]*acc[c];
  if (f >= F1V) s = 0.f;
  __shared__ float red[128];
  red[threadIdx.x] = s; __syncthreads();
  for (int o = 64; o > 0; o >>= 1){ if (threadIdx.x < o) red[threadIdx.x] += red[threadIdx.x+o]; __syncthreads(); }
  if (!threadIdx.x) atomicAdd(&g_acc[slot], red[0]);
}

__global__ void gathermax_kernel(const int* __restrict__ sccs){
  int br = blockIdx.x;
  int b = br / RR;
  __shared__ int idx[GG];
  for (int t = threadIdx.x; t < GG; t += 256) idx[t] = sccs[(size_t)br*GG + t];
  __syncthreads();
  for (int f = threadIdx.x; f < F1V; f += 256){
    float m = -1e30f;
    for (int g = 0; g < GG; g++)
      m = fmaxf(m, g_out1[((size_t)b*NPTS + idx[g])*F1V + f]);
    g_vR[(size_t)br*F1V + f] = m;
  }
}

__global__ void sqnorm_kernel(){
  size_t row = blockIdx.x;
  const float* p = g_out1 + row*F1V;
  float s = 0.f;
  for (int k = threadIdx.x; k < F1V; k += 256){ float v = p[k]; s += v*v; }
  __shared__ float sh[256];
  sh[threadIdx.x] = s; __syncthreads();
  for (int o = 128; o > 0; o >>= 1){ if (threadIdx.x < o) sh[threadIdx.x] += sh[threadIdx.x+o]; __syncthreads(); }
  if (!threadIdx.x) g_sqn[row] = sh[0];
}

__global__ void colmax_kernel(const float* __restrict__ src, float* __restrict__ dst, int rows){
  int b = blockIdx.y;
  int f = blockIdx.x*256 + threadIdx.x;
  if (f >= F1V) return;
  float m = -1e30f;
  for (int i = 0; i < rows; i++)
    m = fmaxf(m, src[((size_t)b*rows + i)*F1V + f]);
  dst[(size_t)b*F1V + f] = m;
}

// transpose fp32 [b][2048][1000] -> bf16 split2 [b][1024 rows(n)][2048]
__global__ void transpose_hilo_kernel(const float* __restrict__ src,
                                      bf16* __restrict__ dh, bf16* __restrict__ dl){
  int b = blockIdx.z;
  __shared__ float t[32][33];
  int m0 = blockIdx.x*32, n0 = blockIdx.y*32;
  int x = threadIdx.x, y = threadIdx.y;
  for (int i = 0; i < 32; i += 8){
    int n = n0 + x, m = m0 + y + i;
    t[y+i][x] = (n < F1V) ? src[((size_t)b*NPTS + m)*F1V + n] : 0.f;
  }
  __syncthreads();
  for (int i = 0; i < 32; i += 8){
    int n = n0 + y + i, m = m0 + x;
    if (n < F1V){
      float v = t[x][y+i];
      size_t o = ((size_t)b*FPAD + n)*NPTS + m;
      split2(v, &dh[o], &dl[o]);
    }
  }
}

// W2 (3000,1000) interleaved rows (3c+k) -> W2T[seg][n][c] = W2[3c+seg][n]
__global__ void w2t_kernel(const float* __restrict__ W2){
  int seg = blockIdx.z;
  __shared__ float t[32][33];
  int k0 = blockIdx.x*32, n0 = blockIdx.y*32;
  int x = threadIdx.x, y = threadIdx.y;
  for (int i = 0; i < 32; i += 8){
    int n = n0 + x, k = k0 + y + i;
    t[y+i][x] = (n < F1V && k < F1V) ? W2[(size_t)(3*k + seg)*F1V + n] : 0.f;
  }
  __syncthreads();
  for (int i = 0; i < 32; i += 8){
    int n = n0 + y + i, k = k0 + x;
    if (n < F1V && k < F1V){
      size_t o = (size_t)seg*FPAD*FPAD + (size_t)n*FPAD + k;
      split2(t[x][y+i], &g_W2Th[o], &g_W2Tl[o]);
    }
  }
}

__global__ void wrt_kernel(const float* __restrict__ Wr){
  __shared__ float t[32][33];
  int q0 = blockIdx.x*32, n0 = blockIdx.y*32;
  int x = threadIdx.x, y = threadIdx.y;
  for (int i = 0; i < 32; i += 8){
    int n = n0 + x, q = q0 + y + i;
    t[y+i][x] = (n < F1V && q < 6000) ? Wr[(size_t)q*F1V + n] : 0.f;
  }
  __syncthreads();
  for (int i = 0; i < 32; i += 8){
    int n = n0 + y + i, q = q0 + x;
    if (n < F1V && q < 6000){
      size_t o = (size_t)n*RK + q;
      split2(t[x][y+i], &g_WrTh[o], &g_WrTl[o]);
    }
  }
}

__global__ void reeb_xs_kernel(const float* __restrict__ Lr){
  int b = blockIdx.y;
  int c = blockIdx.x*128 + threadIdx.x;
  __shared__ float Ls[RR*RR];
  for (int t = threadIdx.x; t < RR*RR; t += 128) Ls[t] = Lr[(size_t)b*RR*RR + t];
  __syncthreads();
  if (c >= F1V) return;
  float v0[RR], v1[RR], v2[RR];
  #pragma unroll
  for (int r = 0; r < RR; r++){
    v0[r] = g_vR[((size_t)b*RR + r)*F1V + c];
    size_t o = (size_t)(b*RR + r)*RK + c*6 + 0;
    split2(v0[r], &g_xsRh[o], &g_xsRl[o]);
  }
  #pragma unroll
  for (int r = 0; r < RR; r++){
    float s = 0.f;
    for (int r2 = 0; r2 < RR; r2++) s += Ls[r*RR + r2]*v0[r2];
    v1[r] = s;
    size_t o = (size_t)(b*RR + r)*RK + c*6 + 1;
    split2(s, &g_xsRh[o], &g_xsRl[o]);
  }
  for (int k = 2; k < 6; k++){
    #pragma unroll
    for (int r = 0; r < RR; r++){
      float s = 0.f;
      for (int r2 = 0; r2 < RR; r2++) s += Ls[r*RR + r2]*v1[r2];
      v2[r] = 2.f*s - v0[r];
      size_t o = (size_t)(b*RR + r)*RK + c*6 + k;
      split2(v2[r], &g_xsRh[o], &g_xsRl[o]);
    }
    #pragma unroll
    for (int r = 0; r < RR; r++){ v0[r] = v1[r]; v1[r] = v2[r]; }
  }
}

__global__ void fc1_kernel(const float* __restrict__ W, const float* __restrict__ bias){
  int b = blockIdx.x;
  __shared__ float ft[2*F1V];
  for (int c = threadIdx.x; c < 2*F1V; c += 512)
    ft[c] = (c < F1V) ? g_gR[(size_t)b*F1V + c] : g_g[(size_t)b*F1V + c - F1V];
  __syncthreads();
  int f = threadIdx.x;
  float a = bias[f];
  for (int c = 0; c < 2*F1V; c++) a += ft[c]*W[(size_t)c*512 + f];
  g_h1[b*512 + f] = fmaxf(a, 0.f);
}

__global__ void fc2_kernel(const float* __restrict__ W, const float* __restrict__ bias){
  int b = blockIdx.x;
  __shared__ float hs[512];
  for (int c = threadIdx.x; c < 512; c += 128) hs[c] = g_h1[b*512 + c];
  __syncthreads();
  int f = threadIdx.x;
  float a = bias[f];
  for (int c = 0; c < 512; c++) a += hs[c]*W[c*128 + f];
  g_h2[b*128 + f] = fmaxf(a, 0.f);
}

__global__ void fc3_kernel(const float* __restrict__ W, const float* __restrict__ bias, float* __restrict__ out){
  int b = blockIdx.x;
  __shared__ float hs[128];
  for (int c = threadIdx.x; c < 128; c += 64) hs[c] = g_h2[b*128 + c];
  __syncthreads();
  int f = threadIdx.x;
  if (f < NCLS){
    float a = bias[f];
    for (int c = 0; c < 128; c++) a += hs[c]*W[c*NCLS + f];
    out[b*NCLS + f] = a;
  }
}

__global__ void wreg_kernel(const float* W1, const float* B1, const float* W2, const float* B2,
                            const float* W3, const float* B3, float* out){
  int layer = blockIdx.x;
  const float* W; const float* Bp; int n, ld;
  if (layer == 0){ W = W1; Bp = B1; n = 2000; ld = 512; }
  else if (layer == 1){ W = W2; Bp = B2; n = 512; ld = 128; }
  else { W = W3; Bp = B3; n = 128; ld = 40; }
  float s = 0.f;
  for (int c = threadIdx.x; c < n; c += 256){ float v = W[(size_t)c*ld]; s += v*v; }
  __shared__ float sh[256];
  sh[threadIdx.x] = s; __syncthreads();
  for (int o = 128; o > 0; o >>= 1){ if (threadIdx.x < o) sh[threadIdx.x] += sh[threadIdx.x+o]; __syncthreads(); }
  if (!threadIdx.x){ out[642 + layer*2] = sh[0]; out[643 + layer*2] = Bp[0]*Bp[0]; }
}

__global__ void finalize_kernel(float* out){
  out[640] = sqrtf(g_acc[0]);
  out[641] = sqrtf(g_acc[1]);
}

// ---------------- host launch ----------------
extern "C" void kernel_launch(void* const* d_in, const int* in_sizes, int n_in,
                              void* d_out, int out_size){
  const float* x    = (const float*)d_in[0];
  const float* Lr   = (const float*)d_in[1];
  const int*   sccs = (const int*)  d_in[2];
  const float* W1   = (const float*)d_in[3];  const float* b1  = (const float*)d_in[4];
  const float* W2   = (const float*)d_in[5];  const float* b2  = (const float*)d_in[6];
  const float* Wr   = (const float*)d_in[7];  const float* br  = (const float*)d_in[8];
  const float* Wfc1 = (const float*)d_in[9];  const float* bfc1= (const float*)d_in[10];
  const float* Wfc2 = (const float*)d_in[11]; const float* bfc2= (const float*)d_in[12];
  const float* Wfc3 = (const float*)d_in[13]; const float* bfc3= (const float*)d_in[14];
  float* out = (float*)d_out;

  static bool attr_done = false;
  if (!attr_done){
    cudaFuncSetAttribute(hgemm_kernel, cudaFuncAttributeMaxDynamicSharedMemorySize, HSM_TOT);
    attr_done = true;
  }

  float *pL, *pout1, *px12, *pout2, *px11, *px21, *pLx, *psqn, *poutR, *pg, *pgR;
  bf16 *pLh, *pLl, *pout1h, *pout1l, *pout1Th, *pout1Tl;
  bf16 *px12h, *px12l, *px12Th, *px12Tl;
  bf16 *px22h, *px22l, *pW2Th, *pW2Tl;
  bf16 *pxsRh, *pxsRl, *pWrTh, *pWrTl;
  cudaGetSymbolAddress((void**)&pL,      g_L);
  cudaGetSymbolAddress((void**)&pout1,   g_out1);
  cudaGetSymbolAddress((void**)&px12,    g_x12);
  cudaGetSymbolAddress((void**)&pout2,   g_out2);
  cudaGetSymbolAddress((void**)&px11,    g_x11);
  cudaGetSymbolAddress((void**)&px21,    g_x21);
  cudaGetSymbolAddress((void**)&pLx,     g_Lx);
  cudaGetSymbolAddress((void**)&psqn,    g_sqn);
  cudaGetSymbolAddress((void**)&poutR,   g_outR);
  cudaGetSymbolAddress((void**)&pg,      g_g);
  cudaGetSymbolAddress((void**)&pgR,     g_gR);
  cudaGetSymbolAddress((void**)&pLh,     g_Lh);
  cudaGetSymbolAddress((void**)&pLl,     g_Ll);
  cudaGetSymbolAddress((void**)&pout1h,  g_out1h);
  cudaGetSymbolAddress((void**)&pout1l,  g_out1l);
  cudaGetSymbolAddress((void**)&pout1Th, g_out1Th);
  cudaGetSymbolAddress((void**)&pout1Tl, g_out1Tl);
  cudaGetSymbolAddress((void**)&px12h,   g_x12h);
  cudaGetSymbolAddress((void**)&px12l,   g_x12l);
  cudaGetSymbolAddress((void**)&px12Th,  g_x12Th);
  cudaGetSymbolAddress((void**)&px12Tl,  g_x12Tl);
  cudaGetSymbolAddress((void**)&px22h,   g_x22h);
  cudaGetSymbolAddress((void**)&px22l,   g_x22l);
  cudaGetSymbolAddress((void**)&pW2Th,   g_W2Th);
  cudaGetSymbolAddress((void**)&pW2Tl,   g_W2Tl);
  cudaGetSymbolAddress((void**)&pxsRh,   g_xsRh);
  cudaGetSymbolAddress((void**)&pxsRl,   g_xsRl);
  cudaGetSymbolAddress((void**)&pWrTh,   g_WrTh);
  cudaGetSymbolAddress((void**)&pWrTl,   g_WrTl);

  zeroacc_kernel<<<1, 32>>>();

  // L1 from pairwise(x)
  pairwise6_kernel<<<dim3(NPTS/16, NPTS/16, BATCH), dim3(16,16)>>>(x);
  rowsum_kernel<<<BATCH*NPTS, 256>>>();
  laplacian_kernel<<<(unsigned)(((size_t)BATCH*NPTS*NPTS + 255)/256), 256>>>(0);

  // cheb conv 1
  gemv6_kernel<<<dim3(NPTS/8, BATCH), 256>>>(x, nullptr, px11, 1.f, 0.f);
  gemv6_kernel<<<dim3(NPTS/8, BATCH), 256>>>(px11, x, px21, 2.f, -1.f);
  cheb1_out_kernel<<<dim3(8, (BATCH*NPTS)/16), 128>>>(x, W1, b1);
  transpose_hilo_kernel<<<dim3(NPTS/32, 32, BATCH), dim3(32,8)>>>(pout1, pout1Th, pout1Tl);
  regnorm_kernel<<<dim3(8, BATCH), 128>>>(pout1, px11, 0);
  gathermax_kernel<<<BATCH*RR, 256>>>(sccs);
  sqnorm_kernel<<<BATCH*NPTS, 256>>>();

  GemmArgs A{};
  // adj2 = exp(2*out1@out1^T - sq_m - sq_n), upper triangle then mirror
  for (int s = 0; s < 3; s++){
    A.Ah[s]=pout1h; A.Al[s]=pout1l;
    A.Bh[s]=pout1h; A.Bl[s]=pout1l;
  }
  A.ldA = FPAD; A.ldB = FPAD; A.sA = (long)NPTS*FPAD; A.sB = (long)NPTS*FPAD;
  A.C = pL; A.ldC = NPTS; A.sC = (long)NPTS*NPTS;
  A.Ch = nullptr; A.Cl = nullptr; A.ldH = 0; A.sH = 0;
  A.Z = nullptr; A.ldZ = 0; A.sZ = 0; A.bias = nullptr;
  A.sq = psqn; A.sSq = NPTS;
  A.M = NPTS; A.N = NPTS; A.nseg = 1; A.kcs = FPAD/32; A.epi = 1;
  hgemm_kernel<<<dim3(16,16,BATCH), 256, HSM_TOT>>>(A);
  mirror_kernel<<<dim3(NPTS/32, NPTS/32, BATCH), dim3(32,8)>>>();

  rowsum_kernel<<<BATCH*NPTS, 256>>>();
  laplacian_kernel<<<(unsigned)(((size_t)BATCH*NPTS*NPTS + 255)/256), 256>>>(1);

  // x12 = L2 @ out1
  for (int s = 0; s < 3; s++){
    A.Ah[s]=pLh; A.Al[s]=pLl;
    A.Bh[s]=pout1Th; A.Bl[s]=pout1Tl;
  }
  A.ldA = NPTS; A.ldB = NPTS; A.sA = (long)NPTS*NPTS; A.sB = (long)FPAD*NPTS;
  A.C = px12; A.ldC = F1V; A.sC = (long)NPTS*F1V;
  A.Ch = px12h; A.Cl = px12l; A.ldH = FPAD; A.sH = (long)NPTS*FPAD;
  A.Z = nullptr; A.sq = nullptr; A.bias = nullptr;
  A.M = NPTS; A.N = F1V; A.nseg = 1; A.kcs = NPTS/32; A.epi = 2;
  hgemm_kernel<<<dim3(8,16,BATCH), 256, HSM_TOT>>>(A);

  transpose_hilo_kernel<<<dim3(NPTS/32, 32, BATCH), dim3(32,8)>>>(px12, px12Th, px12Tl);

  // x22 = 2*L2@x12 - out1 (split2 only)
  for (int s = 0; s < 3; s++){
    A.Ah[s]=pLh; A.Al[s]=pLl;
    A.Bh[s]=px12Th; A.Bl[s]=px12Tl;
  }
  A.C = nullptr; A.ldC = 0; A.sC = 0;
  A.Ch = px22h; A.Cl = px22l; A.ldH = FPAD; A.sH = (long)NPTS*FPAD;
  A.Z = pout1; A.ldZ = F1V; A.sZ = (long)NPTS*F1V;
  A.M = NPTS; A.N = F1V; A.nseg = 1; A.kcs = NPTS/32; A.epi = 3;
  hgemm_kernel<<<dim3(8,16,BATCH), 256, HSM_TOT>>>(A);

  // W2 transposed split2 (interleaved rows 3c+seg)
  w2t_kernel<<<dim3(32, 32, 3), dim3(32,8)>>>(W2);

  // out2 = relu(out1@W2a + x12@W2b + x22@W2c + b2), M flattened
  A.Ah[0]=pout1h; A.Al[0]=pout1l;
  A.Ah[1]=px12h;  A.Al[1]=px12l;
  A.Ah[2]=px22h;  A.Al[2]=px22l;
  A.Bh[0]=pW2Th;                       A.Bl[0]=pW2Tl;
  A.Bh[1]=pW2Th + (size_t)FPAD*FPAD;   A.Bl[1]=pW2Tl + (size_t)FPAD*FPAD;
  A.Bh[2]=pW2Th + (size_t)2*FPAD*FPAD; A.Bl[2]=pW2Tl + (size_t)2*FPAD*FPAD;
  A.ldA = FPAD; A.ldB = FPAD; A.sA = 0; A.sB = 0;
  A.C = pout2; A.ldC = F1V; A.sC = 0;
  A.Ch = nullptr; A.Cl = nullptr; A.Z = nullptr;
  A.bias = b2;
  A.M = BATCH*NPTS; A.N = F1V; A.nseg = 3; A.kcs = FPAD/32; A.epi = 4;
  hgemm_kernel<<<dim3(8,256,1), 256, HSM_TOT>>>(A);

  // reg1 = ||out2^T (L2 x)||
  gemv6_kernel<<<dim3(NPTS/8, BATCH), 256>>>(x, nullptr, pLx, 1.f, 0.f);
  regnorm_kernel<<<dim3(8, BATCH), 128>>>(pout2, pLx, 1);
  colmax_kernel<<<dim3(4, BATCH), 256>>>(pout2, pg, NPTS);

  // Reeb branch
  reeb_xs_kernel<<<dim3(8, BATCH), 128>>>(Lr);
  wrt_kernel<<<dim3(188, 32), dim3(32,8)>>>(Wr);
  A.Ah[0]=pxsRh; A.Al[0]=pxsRl;
  A.Ah[1]=pxsRh; A.Al[1]=pxsRl;
  A.Ah[2]=pxsRh; A.Al[2]=pxsRl;
  A.Bh[0]=pWrTh; A.Bl[0]=pWrTl;
  A.Bh[1]=pWrTh; A.Bl[1]=pWrTl;
  A.Bh[2]=pWrTh; A.Bl[2]=pWrTl;
  A.ldA = RK; A.ldB = RK; A.sA = 0; A.sB = 0;
  A.C = poutR; A.ldC = F1V; A.sC = 0;
  A.Ch = nullptr; A.Cl = nullptr; A.Z = nullptr;
  A.bias = br;
  A.M = BATCH*RR; A.N = F1V; A.nseg = 1; A.kcs = RK/32; A.epi = 4;
  hgemm_kernel<<<dim3(8,3,1), 256, HSM_TOT>>>(A);
  colmax_kernel<<<dim3(4, BATCH), 256>>>(poutR, pgR, RR);

  // FC head
  fc1_kernel<<<BATCH, 512>>>(Wfc1, bfc1);
  fc2_kernel<<<BATCH, 128>>>(Wfc2, bfc2);
  fc3_kernel<<<BATCH, 64>>>(Wfc3, bfc3, out);

  // regs
  wreg_kernel<<<3, 256>>>(Wfc1, bfc1, Wfc2, bfc2, Wfc3, bfc3, out);
  finalize_kernel<<<1, 1>>>(out);
}

// round 12
// speedup vs baseline: 1.0512x; 1.0089x over previous
#include <cuda_runtime.h>
#include <cuda_bf16.h>
#include <math.h>
#include <stdint.h>

#define BATCH 16
#define NPTS 2048
#define CINF 6
#define RR 20
#define GG 128
#define F1V 1000
#define NCLS 40
#define FPAD 1024
#define RK 6016
#define RM 384

typedef __nv_bfloat16 bf16;

// ---------------- scratch (device globals; zero-initialized, no allocations) ----------------
__device__ float g_L[(size_t)BATCH*NPTS*NPTS];
__device__ float g_out1[(size_t)BATCH*NPTS*F1V];
__device__ float g_x12[(size_t)BATCH*NPTS*F1V];
__device__ float g_out2[(size_t)BATCH*NPTS*F1V];
__device__ bf16  g_Lh[(size_t)BATCH*NPTS*NPTS];
__device__ bf16  g_Ll[(size_t)BATCH*NPTS*NPTS];
__device__ bf16  g_out1h[(size_t)BATCH*NPTS*FPAD];
__device__ bf16  g_out1l[(size_t)BATCH*NPTS*FPAD];
__device__ bf16  g_out1Th[(size_t)BATCH*FPAD*NPTS];
__device__ bf16  g_out1Tl[(size_t)BATCH*FPAD*NPTS];
__device__ bf16  g_x12h[(size_t)BATCH*NPTS*FPAD];
__device__ bf16  g_x12l[(size_t)BATCH*NPTS*FPAD];
__device__ bf16  g_x12Th[(size_t)BATCH*FPAD*NPTS];
__device__ bf16  g_x12Tl[(size_t)BATCH*FPAD*NPTS];
__device__ bf16  g_x22h[(size_t)BATCH*NPTS*FPAD];
__device__ bf16  g_x22l[(size_t)BATCH*NPTS*FPAD];
__device__ bf16  g_W2Th[3*FPAD*FPAD];
__device__ bf16  g_W2Tl[3*FPAD*FPAD];
__device__ bf16  g_xsRh[(size_t)RM*RK];
__device__ bf16  g_xsRl[(size_t)RM*RK];
__device__ bf16  g_WrTh[(size_t)FPAD*RK];
__device__ bf16  g_WrTl[(size_t)FPAD*RK];
__device__ float g_x11[BATCH*NPTS*CINF];
__device__ float g_x21[BATCH*NPTS*CINF];
__device__ float g_Lx[BATCH*NPTS*CINF];
__device__ float g_rowsum[BATCH*NPTS];
__device__ float g_sqn[BATCH*NPTS];
__device__ float g_vR[BATCH*RR*F1V];
__device__ float g_outR[BATCH*RR*F1V];
__device__ float g_g[BATCH*F1V];
__device__ float g_gR[BATCH*F1V];
__device__ float g_h1[BATCH*512];
__device__ float g_h2[BATCH*128];
__device__ float g_acc[8];

// ---------------- helpers ----------------
__device__ __forceinline__ uint32_t smem_u32(const void* p){
  uint32_t a;
  asm("{ .reg .u64 t; cvta.to.shared.u64 t, %1; cvt.u32.u64 %0, t; }" : "=r"(a) : "l"(p));
  return a;
}
__device__ __forceinline__ void cp16(uint32_t s, const void* g){
  asm volatile("cp.async.cg.shared.global [%0], [%1], 16;" :: "r"(s), "l"(g));
}
__device__ __forceinline__ void ldsm4(uint32_t& r0, uint32_t& r1, uint32_t& r2, uint32_t& r3, uint32_t a){
  asm volatile("ldmatrix.sync.aligned.m8n8.x4.shared.b16 {%0,%1,%2,%3}, [%4];"
    : "=r"(r0), "=r"(r1), "=r"(r2), "=r"(r3) : "r"(a));
}
__device__ __forceinline__ void mma16816(float* d, const uint32_t* a, const uint32_t* b){
  asm volatile("mma.sync.aligned.m16n8k16.row.col.f32.bf16.bf16.f32 "
    "{%0,%1,%2,%3}, {%4,%5,%6,%7}, {%8,%9}, {%0,%1,%2,%3};"
    : "+f"(d[0]), "+f"(d[1]), "+f"(d[2]), "+f"(d[3])
    : "r"(a[0]), "r"(a[1]), "r"(a[2]), "r"(a[3]), "r"(b[0]), "r"(b[1]));
}
__device__ __forceinline__ void split2(float v, bf16* ph, bf16* pl){
  bf16 h = __float2bfloat16(v);
  *ph = h;
  *pl = __float2bfloat16(v - __bfloat162float(h));
}

// ---------------- HMMA GEMM: C[M,N], CTA tile 128x128, BK=32, 2-stage, 2 CTAs/SM ----------------
// epi: 0 plain C; 1 exp(2a - sq[m] - sq[n]) upper-only + rowsum atomics; 2 C + split2; 3 split2 of (2a - Z); 4 relu(a + bias[n])
struct GemmArgs {
  const bf16 *Ah[3], *Al[3], *Bh[3], *Bl[3];
  long ldA, ldB, sA, sB;
  float* C; long ldC, sC;
  bf16 *Ch, *Cl; long ldH, sH;
  const float* Z; long ldZ, sZ;
  const float* bias;
  const float* sq; long sSq;
  int M, N, nseg, kcs, epi;
};

#define STAGE_B 40960          // 4 parts * 128 rows * 80 bytes
#define PART_B  10240
#define HSM_TOT (2*STAGE_B)    // 81920 -> 2 CTAs per SM

__global__ __launch_bounds__(256, 2) void hgemm_kernel(GemmArgs P){
  // symmetric pairwise: skip lower-triangle blocks
  if (P.epi == 1 && blockIdx.x < blockIdx.y) return;

  extern __shared__ char sm[];
  uint32_t sb = smem_u32(sm);
  int tid = threadIdx.x;
  int w = tid >> 5, l = tid & 31;
  int wm = w & 3;
  int wn = w >> 2;
  int bz = blockIdx.z;
  int m0 = blockIdx.y * 128, n0 = blockIdx.x * 128;
  const int nk = P.nseg * P.kcs;

  float acc[2][8][4];
  #pragma unroll
  for (int t = 0; t < 2; t++)
    #pragma unroll
    for (int j = 0; j < 8; j++)
      #pragma unroll
      for (int r = 0; r < 4; r++) acc[t][j][r] = 0.f;

  // ---- stage loader: 4 parts (aH aL bH bL), each 128x32 bf16, pitch 80B ----
  auto stage_load = [&](int kt){
    int seg = kt / P.kcs, kc = kt % P.kcs;
    const bf16* pa[2] = {
      P.Ah[seg] + (size_t)bz*P.sA + (size_t)m0*P.ldA + (size_t)kc*32,
      P.Al[seg] + (size_t)bz*P.sA + (size_t)m0*P.ldA + (size_t)kc*32 };
    const bf16* pb[2] = {
      P.Bh[seg] + (size_t)bz*P.sB + (size_t)n0*P.ldB + (size_t)kc*32,
      P.Bl[seg] + (size_t)bz*P.sB + (size_t)n0*P.ldB + (size_t)kc*32 };
    uint32_t st = sb + (uint32_t)(kt & 1) * STAGE_B;
    #pragma unroll
    for (int i = 0; i < 8; i++){
      int part = i >> 1;                 // 0..3
      int cid = tid + (i & 1)*256;       // 0..511
      int row = cid >> 2, col = cid & 3;
      const bf16* gp = (part < 2) ? pa[part] : pb[part - 2];
      long ld = (part < 2) ? P.ldA : P.ldB;
      cp16(st + part*PART_B + row*80 + col*16, gp + (size_t)row*ld + col*8);
    }
    asm volatile("cp.async.commit_group;" ::: "memory");
  };

  stage_load(0);

  for (int kt = 0; kt < nk; kt++){
    if (kt + 1 < nk){
      stage_load(kt + 1);
      asm volatile("cp.async.wait_group 1;" ::: "memory");
    } else {
      asm volatile("cp.async.wait_group 0;" ::: "memory");
    }
    __syncthreads();

    uint32_t st = sb + (uint32_t)(kt & 1) * STAGE_B;
    #pragma unroll
    for (int step = 0; step < 2; step++){
      uint32_t ah[2][4], al[2][4];
      #pragma unroll
      for (int t = 0; t < 2; t++){
        int row = wm*32 + t*16 + (l & 15);
        uint32_t koff = (uint32_t)(step*32 + ((l >> 4) & 1)*16);
        uint32_t addr = st + row*80 + koff;
        ldsm4(ah[t][0], ah[t][1], ah[t][2], ah[t][3], addr);
        ldsm4(al[t][0], al[t][1], al[t][2], al[t][3], addr + PART_B);
      }
      uint32_t bh[8][2], bl[8][2];
      #pragma unroll
      for (int j = 0; j < 4; j++){
        int n = wn*64 + j*16 + (((l >> 4) & 1) << 3) + (l & 7);
        uint32_t koff = (uint32_t)(step*32 + ((l >> 3) & 1)*16);
        uint32_t addr = st + 2*PART_B + n*80 + koff;
        ldsm4(bh[2*j][0], bh[2*j][1], bh[2*j+1][0], bh[2*j+1][1], addr);
        ldsm4(bl[2*j][0], bl[2*j][1], bl[2*j+1][0], bl[2*j+1][1], addr + PART_B);
      }
      #pragma unroll
      for (int t = 0; t < 2; t++)
        #pragma unroll
        for (int j = 0; j < 8; j++){
          mma16816(acc[t][j], ah[t], bh[j]);
          mma16816(acc[t][j], ah[t], bl[j]);
          mma16816(acc[t][j], al[t], bh[j]);
        }
    }
    __syncthreads();
  }

  // ---- epilogue ----
  int lm = l >> 2, ln = (l & 3)*2;

  if (P.epi == 1){
    // pairwise adjacency: write upper blocks + fused rowsum atomics
    const float* sqb = P.sq + (size_t)bz*P.sSq;
    float* C = P.C + (size_t)bz*P.sC;
    float* rs = g_rowsum + (size_t)bz*NPTS;
    bool dup = (blockIdx.x > blockIdx.y);
    float rowm[4] = {0.f, 0.f, 0.f, 0.f};
    float rown[16];
    #pragma unroll
    for (int q = 0; q < 16; q++) rown[q] = 0.f;
    #pragma unroll
    for (int t = 0; t < 2; t++){
      #pragma unroll
      for (int j = 0; j < 8; j++){
        #pragma unroll
        for (int r = 0; r < 4; r++){
          int m = m0 + wm*32 + t*16 + lm + (r >> 1)*8;
          int n = n0 + wn*64 + j*8 + ln + (r & 1);
          float e = expf(2.f*acc[t][j][r] - sqb[m] - sqb[n]);
          C[(size_t)m*P.ldC + n] = e;
          rowm[t*2 + (r >> 1)] += e;
          rown[j*2 + (r & 1)] += e;
        }
      }
    }
    #pragma unroll
    for (int q = 0; q < 4; q++){
      int m = m0 + wm*32 + (q >> 1)*16 + lm + (q & 1)*8;
      atomicAdd(&rs[m], rowm[q]);
    }
    if (dup){
      #pragma unroll
      for (int q = 0; q < 16; q++){
        int n = n0 + wn*64 + (q >> 1)*8 + ln + (q & 1);
        atomicAdd(&rs[n], rown[q]);
      }
    }
    return;
  }

  float* C = P.C ? (P.C + (size_t)bz*P.sC) : nullptr;
  bf16* Ch = P.Ch ? (P.Ch + (size_t)bz*P.sH) : nullptr;
  bf16* Cl = P.Cl ? (P.Cl + (size_t)bz*P.sH) : nullptr;
  const float* Z = P.Z ? (P.Z + (size_t)bz*P.sZ) : nullptr;

  #pragma unroll
  for (int t = 0; t < 2; t++){
    #pragma unroll
    for (int j = 0; j < 8; j++){
      #pragma unroll
      for (int r = 0; r < 4; r++){
        int m = m0 + wm*32 + t*16 + lm + (r >> 1)*8;
        int n = n0 + wn*64 + j*8 + ln + (r & 1);
        if (m < P.M && n < P.N){
          float a = acc[t][j][r];
          if (P.epi == 0){
            C[(size_t)m*P.ldC + n] = a;
          } else if (P.epi == 2){
            C[(size_t)m*P.ldC + n] = a;
            split2(a, Ch + (size_t)m*P.ldH + n, Cl + (size_t)m*P.ldH + n);
          } else if (P.epi == 3){
            float v = 2.f*a - Z[(size_t)m*P.ldZ + n];
            split2(v, Ch + (size_t)m*P.ldH + n, Cl + (size_t)m*P.ldH + n);
          } else {
            C[(size_t)m*P.ldC + n] = fmaxf(a + P.bias[n], 0.f);
          }
        }
      }
    }
  }
}

// fused mirror + laplacian + bf16 split for L2 (upper tiles -> both triangles)
__global__ void mirror_lap_kernel(){
  int b = blockIdx.z;
  int tx = blockIdx.x, ty = blockIdx.y;
  if (tx < ty) return;
  __shared__ float t[32][33];
  __shared__ float rim[32], rin[32];
  int x = threadIdx.x, y = threadIdx.y;
  size_t base = (size_t)b*NPTS*NPTS;
  for (int i = 0; i < 32; i += 8){
    int m = ty*32 + y + i, n = tx*32 + x;
    t[y+i][x] = g_L[base + (size_t)m*NPTS + n];
  }
  if (y == 0) rim[x] = rsqrtf(g_rowsum[b*NPTS + ty*32 + x]);
  if (y == 1) rin[x] = rsqrtf(g_rowsum[b*NPTS + tx*32 + x]);
  __syncthreads();
  for (int i = 0; i < 32; i += 8){
    int m = ty*32 + y + i, n = tx*32 + x;
    float Lv = ((m == n) ? 1.f : 0.f) - rim[y+i]*t[y+i][x]*rin[x];
    t[y+i][x] = Lv;
    size_t o = base + (size_t)m*NPTS + n;
    g_L[o] = Lv;
    split2(Lv, &g_Lh[o], &g_Ll[o]);
  }
  if (tx > ty){
    __syncthreads();
    for (int i = 0; i < 32; i += 8){
      int m = tx*32 + y + i, n = ty*32 + x;
      float Lv = t[x][y+i];
      size_t o = base + (size_t)m*NPTS + n;
      g_L[o] = Lv;
      split2(Lv, &g_Lh[o], &g_Ll[o]);
    }
  }
}

// ---------------- small kernels ----------------
__global__ void zeroacc_kernel(){ if (threadIdx.x < 8) g_acc[threadIdx.x] = 0.f; }

__global__ void zero_rs_kernel(){
  int i = blockIdx.x*256 + threadIdx.x;
  if (i < BATCH*NPTS) g_rowsum[i] = 0.f;
}

__global__ void pairwise6_kernel(const float* __restrict__ x){
  int b = blockIdx.z;
  int i0 = blockIdx.y*16, j0 = blockIdx.x*16;
  __shared__ float xi[16][6], xj[16][6];
  int tid = threadIdx.y*16 + threadIdx.x;
  if (tid < 96){
    int r = tid/6, c = tid%6;
    xi[r][c] = x[((size_t)b*NPTS + i0 + r)*CINF + c];
    xj[r][c] = x[((size_t)b*NPTS + j0 + r)*CINF + c];
  }
  __syncthreads();
  int i = threadIdx.y, j = threadIdx.x;
  float d = 0.f;
  #pragma unroll
  for (int c = 0; c < 6; c++){ float t = xi[i][c]-xj[j][c]; d += t*t; }
  float e = expf(-d);
  g_L[((size_t)b*NPTS + i0+i)*NPTS + j0+j] = e;
  // fused row sum: reduce across j (16-lane segments) then one atomic per row
  float s = e;
  #pragma unroll
  for (int o = 8; o > 0; o >>= 1) s += __shfl_down_sync(0xffffffffu, s, o, 16);
  if (j == 0) atomicAdd(&g_rowsum[b*NPTS + i0 + i], s);
}

__global__ void laplacian_kernel(){
  size_t idx = (size_t)blockIdx.x*256 + threadIdx.x;
  size_t total = (size_t)BATCH*NPTS*NPTS;
  if (idx >= total) return;
  size_t bi = idx / NPTS;
  int j = (int)(idx % NPTS);
  int i = (int)(bi % NPTS);
  float a = g_L[idx];
  float v = rsqrtf(g_rowsum[bi]) * a * rsqrtf(g_rowsum[bi - i + j]);
  g_L[idx] = (i == j ? 1.0f : 0.0f) - v;
}

__global__ void gemv6_kernel(const float* __restrict__ X, const float* __restrict__ Z,
                             float* __restrict__ Y, float s, float t){
  int b = blockIdx.y;
  __shared__ float xs[NPTS*CINF];
  for (int idx = threadIdx.x; idx < NPTS*CINF; idx += 256)
    xs[idx] = X[(size_t)b*NPTS*CINF + idx];
  __syncthreads();
  int warp = threadIdx.x >> 5, lane = threadIdx.x & 31;
  int i = blockIdx.x*8 + warp;
  const float* Lrow = g_L + ((size_t)b*NPTS + i)*NPTS;
  float acc[6] = {0,0,0,0,0,0};
  for (int k = lane; k < NPTS; k += 32){
    float l = Lrow[k];
    #pragma unroll
    for (int c = 0; c < 6; c++) acc[c] += l * xs[k*6 + c];
  }
  #pragma unroll
  for (int c = 0; c < 6; c++)
    for (int o = 16; o > 0; o >>= 1) acc[c] += __shfl_down_sync(0xffffffffu, acc[c], o);
  if (!lane){
    size_t base = ((size_t)b*NPTS + i)*CINF;
    #pragma unroll
    for (int c = 0; c < 6; c++){
      float v = s*acc[c];
      if (Z) v += t*Z[base + c];
      Y[base + c] = v;
    }
  }
}

__global__ void cheb1_out_kernel(const float* __restrict__ x, const float* __restrict__ W1,
                                 const float* __restrict__ b1){
  int f = blockIdx.x*128 + threadIdx.x;
  int row0 = blockIdx.y*16;
  __shared__ float xsr[16][18];
  for (int idx = threadIdx.x; idx < 16*18; idx += 128){
    int r = idx/18, q = idx%18, c = q/3, kk = q%3;
    size_t g = (size_t)(row0 + r)*CINF + c;
    xsr[r][q] = (kk == 0) ? x[g] : ((kk == 1) ? g_x11[g] : g_x21[g]);
  }
  __syncthreads();
  if (f >= F1V) return;
  float w[18];
  #pragma unroll
  for (int q = 0; q < 18; q++) w[q] = W1[q*F1V + f];
  float bb = b1[f];
  for (int r = 0; r < 16; r++){
    float a = bb;
    #pragma unroll
    for (int q = 0; q < 18; q++) a += xsr[r][q]*w[q];
    float v = fmaxf(a, 0.f);
    size_t rowi = (size_t)(row0 + r);
    g_out1[rowi*F1V + f] = v;
    split2(v, &g_out1h[rowi*FPAD + f], &g_out1l[rowi*FPAD + f]);
  }
}

__global__ void regnorm_kernel(const float* __restrict__ outp, const float* __restrict__ xc, int slot){
  int b = blockIdx.y;
  int f = blockIdx.x*128 + threadIdx.x;
  __shared__ float sh[128*6];
  float acc[6] = {0,0,0,0,0,0};
  for (int i0 = 0; i0 < NPTS; i0 += 128){
    __syncthreads();
    for (int idx = threadIdx.x; idx < 128*6; idx += 128)
      sh[idx] = xc[((size_t)b*NPTS + i0)*CINF + idx];
    __syncthreads();
    if (f < F1V){
      for (int ii = 0; ii < 128; ii++){
        float o = outp[((size_t)b*NPTS + i0 + ii)*F1V + f];
        #pragma unroll
        for (int c = 0; c < 6; c++) acc[c] += o*sh[ii*6 + c];
      }
    }
  }
  float s = 0.f;
  #pragma unroll
  for (int c = 0; c < 6; c++) s += acc[c]*acc[c];
  if (f >= F1V) s = 0.f;
  __shared__ float red[128];
  red[threadIdx.x] = s; __syncthreads();
  for (int o = 64; o > 0; o >>= 1){ if (threadIdx.x < o) red[threadIdx.x] += red[threadIdx.x+o]; __syncthreads(); }
  if (!threadIdx.x) atomicAdd(&g_acc[slot], red[0]);
}

__global__ void gathermax_kernel(const int* __restrict__ sccs){
  int br = blockIdx.x;
  int b = br / RR;
  __shared__ int idx[GG];
  for (int t = threadIdx.x; t < GG; t += 256) idx[t] = sccs[(size_t)br*GG + t];
  __syncthreads();
  for (int f = threadIdx.x; f < F1V; f += 256){
    float m = -1e30f;
    for (int g = 0; g < GG; g++)
      m = fmaxf(m, g_out1[((size_t)b*NPTS + idx[g])*F1V + f]);
    g_vR[(size_t)br*F1V + f] = m;
  }
}

__global__ void sqnorm_kernel(){
  size_t row = blockIdx.x;
  const float* p = g_out1 + row*F1V;
  float s = 0.f;
  for (int k = threadIdx.x; k < F1V; k += 256){ float v = p[k]; s += v*v; }
  __shared__ float sh[256];
  sh[threadIdx.x] = s; __syncthreads();
  for (int o = 128; o > 0; o >>= 1){ if (threadIdx.x < o) sh[threadIdx.x] += sh[threadIdx.x+o]; __syncthreads(); }
  if (!threadIdx.x) g_sqn[row] = sh[0];
}

__global__ void colmax_kernel(const float* __restrict__ src, float* __restrict__ dst, int rows){
  int b = blockIdx.y;
  int f = blockIdx.x*256 + threadIdx.x;
  if (f >= F1V) return;
  float m = -1e30f;
  for (int i = 0; i < rows; i++)
    m = fmaxf(m, src[((size_t)b*rows + i)*F1V + f]);
  dst[(size_t)b*F1V + f] = m;
}

// transpose fp32 [b][2048][1000] -> bf16 split2 [b][1024 rows(n)][2048]
__global__ void transpose_hilo_kernel(const float* __restrict__ src,
                                      bf16* __restrict__ dh, bf16* __restrict__ dl){
  int b = blockIdx.z;
  __shared__ float t[32][33];
  int m0 = blockIdx.x*32, n0 = blockIdx.y*32;
  int x = threadIdx.x, y = threadIdx.y;
  for (int i = 0; i < 32; i += 8){
    int n = n0 + x, m = m0 + y + i;
    t[y+i][x] = (n < F1V) ? src[((size_t)b*NPTS + m)*F1V + n] : 0.f;
  }
  __syncthreads();
  for (int i = 0; i < 32; i += 8){
    int n = n0 + y + i, m = m0 + x;
    if (n < F1V){
      float v = t[x][y+i];
      size_t o = ((size_t)b*FPAD + n)*NPTS + m;
      split2(v, &dh[o], &dl[o]);
    }
  }
}

// W2 (3000,1000) interleaved rows (3c+k) -> W2T[seg][n][c] = W2[3c+seg][n]
__global__ void w2t_kernel(const float* __restrict__ W2){
  int seg = blockIdx.z;
  __shared__ float t[32][33];
  int k0 = blockIdx.x*32, n0 = blockIdx.y*32;
  int x = threadIdx.x, y = threadIdx.y;
  for (int i = 0; i < 32; i += 8){
    int n = n0 + x, k = k0 + y + i;
    t[y+i][x] = (n < F1V && k < F1V) ? W2[(size_t)(3*k + seg)*F1V + n] : 0.f;
  }
  __syncthreads();
  for (int i = 0; i < 32; i += 8){
    int n = n0 + y + i, k = k0 + x;
    if (n < F1V && k < F1V){
      size_t o = (size_t)seg*FPAD*FPAD + (size_t)n*FPAD + k;
      split2(t[x][y+i], &g_W2Th[o], &g_W2Tl[o]);
    }
  }
}

__global__ void wrt_kernel(const float* __restrict__ Wr){
  __shared__ float t[32][33];
  int q0 = blockIdx.x*32, n0 = blockIdx.y*32;
  int x = threadIdx.x, y = threadIdx.y;
  for (int i = 0; i < 32; i += 8){
    int n = n0 + x, q = q0 + y + i;
    t[y+i][x] = (n < F1V && q < 6000) ? Wr[(size_t)q*F1V + n] : 0.f;
  }
  __syncthreads();
  for (int i = 0; i < 32; i += 8){
    int n = n0 + y + i, q = q0 + x;
    if (n < F1V && q < 6000){
      size_t o = (size_t)n*RK + q;
      split2(t[x][y+i], &g_WrTh[o], &g_WrTl[o]);
    }
  }
}

__global__ void reeb_xs_kernel(const float* __restrict__ Lr){
  int b = blockIdx.y;
  int c = blockIdx.x*128 + threadIdx.x;
  __shared__ float Ls[RR*RR];
  for (int t = threadIdx.x; t < RR*RR; t += 128) Ls[t] = Lr[(size_t)b*RR*RR + t];
  __syncthreads();
  if (c >= F1V) return;
  float v0[RR], v1[RR], v2[RR];
  #pragma unroll
  for (int r = 0; r < RR; r++){
    v0[r] = g_vR[((size_t)b*RR + r)*F1V + c];
    size_t o = (size_t)(b*RR + r)*RK + c*6 + 0;
    split2(v0[r], &g_xsRh[o], &g_xsRl[o]);
  }
  #pragma unroll
  for (int r = 0; r < RR; r++){
    float s = 0.f;
    for (int r2 = 0; r2 < RR; r2++) s += Ls[r*RR + r2]*v0[r2];
    v1[r] = s;
    size_t o = (size_t)(b*RR + r)*RK + c*6 + 1;
    split2(s, &g_xsRh[o], &g_xsRl[o]);
  }
  for (int k = 2; k < 6; k++){
    #pragma unroll
    for (int r = 0; r < RR; r++){
      float s = 0.f;
      for (int r2 = 0; r2 < RR; r2++) s += Ls[r*RR + r2]*v1[r2];
      v2[r] = 2.f*s - v0[r];
      size_t o = (size_t)(b*RR + r)*RK + c*6 + k;
      split2(v2[r], &g_xsRh[o], &g_xsRl[o]);
    }
    #pragma unroll
    for (int r = 0; r < RR; r++){ v0[r] = v1[r]; v1[r] = v2[r]; }
  }
}

__global__ void fc1_kernel(const float* __restrict__ W, const float* __restrict__ bias){
  int b = blockIdx.x;
  __shared__ float ft[2*F1V];
  for (int c = threadIdx.x; c < 2*F1V; c += 512)
    ft[c] = (c < F1V) ? g_gR[(size_t)b*F1V + c] : g_g[(size_t)b*F1V + c - F1V];
  __syncthreads();
  int f = threadIdx.x;
  float a = bias[f];
  for (int c = 0; c < 2*F1V; c++) a += ft[c]*W[(size_t)c*512 + f];
  g_h1[b*512 + f] = fmaxf(a, 0.f);
}

__global__ void fc2_kernel(const float* __restrict__ W, const float* __restrict__ bias){
  int b = blockIdx.x;
  __shared__ float hs[512];
  for (int c = threadIdx.x; c < 512; c += 128) hs[c] = g_h1[b*512 + c];
  __syncthreads();
  int f = threadIdx.x;
  float a = bias[f];
  for (int c = 0; c < 512; c++) a += hs[c]*W[c*128 + f];
  g_h2[b*128 + f] = fmaxf(a, 0.f);
}

__global__ void fc3_kernel(const float* __restrict__ W, const float* __restrict__ bias, float* __restrict__ out){
  int b = blockIdx.x;
  __shared__ float hs[128];
  for (int c = threadIdx.x; c < 128; c += 64) hs[c] = g_h2[b*128 + c];
  __syncthreads();
  int f = threadIdx.x;
  if (f < NCLS){
    float a = bias[f];
    for (int c = 0; c < 128; c++) a += hs[c]*W[c*NCLS + f];
    out[b*NCLS + f] = a;
  }
}

__global__ void wreg_kernel(const float* W1, const float* B1, const float* W2, const float* B2,
                            const float* W3, const float* B3, float* out){
  int layer = blockIdx.x;
  const float* W; const float* Bp; int n, ld;
  if (layer == 0){ W = W1; Bp = B1; n = 2000; ld = 512; }
  else if (layer == 1){ W = W2; Bp = B2; n = 512; ld = 128; }
  else { W = W3; Bp = B3; n = 128; ld = 40; }
  float s = 0.f;
  for (int c = threadIdx.x; c < n; c += 256){ float v = W[(size_t)c*ld]; s += v*v; }
  __shared__ float sh[256];
  sh[threadIdx.x] = s; __syncthreads();
  for (int o = 128; o > 0; o >>= 1){ if (threadIdx.x < o) sh[threadIdx.x] += sh[threadIdx.x+o]; __syncthreads(); }
  if (!threadIdx.x){ out[642 + layer*2] = sh[0]; out[643 + layer*2] = Bp[0]*Bp[0]; }
}

__global__ void finalize_kernel(float* out){
  out[640] = sqrtf(g_acc[0]);
  out[641] = sqrtf(g_acc[1]);
}

// ---------------- host launch ----------------
extern "C" void kernel_launch(void* const* d_in, const int* in_sizes, int n_in,
                              void* d_out, int out_size){
  const float* x    = (const float*)d_in[0];
  const float* Lr   = (const float*)d_in[1];
  const int*   sccs = (const int*)  d_in[2];
  const float* W1   = (const float*)d_in[3];  const float* b1  = (const float*)d_in[4];
  const float* W2   = (const float*)d_in[5];  const float* b2  = (const float*)d_in[6];
  const float* Wr   = (const float*)d_in[7];  const float* br  = (const float*)d_in[8];
  const float* Wfc1 = (const float*)d_in[9];  const float* bfc1= (const float*)d_in[10];
  const float* Wfc2 = (const float*)d_in[11]; const float* bfc2= (const float*)d_in[12];
  const float* Wfc3 = (const float*)d_in[13]; const float* bfc3= (const float*)d_in[14];
  float* out = (float*)d_out;

  static bool attr_done = false;
  if (!attr_done){
    cudaFuncSetAttribute(hgemm_kernel, cudaFuncAttributeMaxDynamicSharedMemorySize, HSM_TOT);
    attr_done = true;
  }

  float *pL, *pout1, *px12, *pout2, *px11, *px21, *pLx, *psqn, *poutR, *pg, *pgR;
  bf16 *pLh, *pLl, *pout1h, *pout1l, *pout1Th, *pout1Tl;
  bf16 *px12h, *px12l, *px12Th, *px12Tl;
  bf16 *px22h, *px22l, *pW2Th, *pW2Tl;
  bf16 *pxsRh, *pxsRl, *pWrTh, *pWrTl;
  cudaGetSymbolAddress((void**)&pL,      g_L);
  cudaGetSymbolAddress((void**)&pout1,   g_out1);
  cudaGetSymbolAddress((void**)&px12,    g_x12);
  cudaGetSymbolAddress((void**)&pout2,   g_out2);
  cudaGetSymbolAddress((void**)&px11,    g_x11);
  cudaGetSymbolAddress((void**)&px21,    g_x21);
  cudaGetSymbolAddress((void**)&pLx,     g_Lx);
  cudaGetSymbolAddress((void**)&psqn,    g_sqn);
  cudaGetSymbolAddress((void**)&poutR,   g_outR);
  cudaGetSymbolAddress((void**)&pg,      g_g);
  cudaGetSymbolAddress((void**)&pgR,     g_gR);
  cudaGetSymbolAddress((void**)&pLh,     g_Lh);
  cudaGetSymbolAddress((void**)&pLl,     g_Ll);
  cudaGetSymbolAddress((void**)&pout1h,  g_out1h);
  cudaGetSymbolAddress((void**)&pout1l,  g_out1l);
  cudaGetSymbolAddress((void**)&pout1Th, g_out1Th);
  cudaGetSymbolAddress((void**)&pout1Tl, g_out1Tl);
  cudaGetSymbolAddress((void**)&px12h,   g_x12h);
  cudaGetSymbolAddress((void**)&px12l,   g_x12l);
  cudaGetSymbolAddress((void**)&px12Th,  g_x12Th);
  cudaGetSymbolAddress((void**)&px12Tl,  g_x12Tl);
  cudaGetSymbolAddress((void**)&px22h,   g_x22h);
  cudaGetSymbolAddress((void**)&px22l,   g_x22l);
  cudaGetSymbolAddress((void**)&pW2Th,   g_W2Th);
  cudaGetSymbolAddress((void**)&pW2Tl,   g_W2Tl);
  cudaGetSymbolAddress((void**)&pxsRh,   g_xsRh);
  cudaGetSymbolAddress((void**)&pxsRl,   g_xsRl);
  cudaGetSymbolAddress((void**)&pWrTh,   g_WrTh);
  cudaGetSymbolAddress((void**)&pWrTl,   g_WrTl);

  zeroacc_kernel<<<1, 32>>>();
  zero_rs_kernel<<<128, 256>>>();

  // L1 from pairwise(x) with fused rowsum
  pairwise6_kernel<<<dim3(NPTS/16, NPTS/16, BATCH), dim3(16,16)>>>(x);
  laplacian_kernel<<<(unsigned)(((size_t)BATCH*NPTS*NPTS + 255)/256), 256>>>();

  // cheb conv 1
  gemv6_kernel<<<dim3(NPTS/8, BATCH), 256>>>(x, nullptr, px11, 1.f, 0.f);
  gemv6_kernel<<<dim3(NPTS/8, BATCH), 256>>>(px11, x, px21, 2.f, -1.f);
  cheb1_out_kernel<<<dim3(8, (BATCH*NPTS)/16), 128>>>(x, W1, b1);
  transpose_hilo_kernel<<<dim3(NPTS/32, 32, BATCH), dim3(32,8)>>>(pout1, pout1Th, pout1Tl);
  regnorm_kernel<<<dim3(8, BATCH), 128>>>(pout1, px11, 0);
  gathermax_kernel<<<BATCH*RR, 256>>>(sccs);
  sqnorm_kernel<<<BATCH*NPTS, 256>>>();

  // zero rowsum for L2 accumulation
  zero_rs_kernel<<<128, 256>>>();

  GemmArgs A{};
  // adj2 = exp(2*out1@out1^T - sq_m - sq_n), upper triangle + fused rowsum atomics
  for (int s = 0; s < 3; s++){
    A.Ah[s]=pout1h; A.Al[s]=pout1l;
    A.Bh[s]=pout1h; A.Bl[s]=pout1l;
  }
  A.ldA = FPAD; A.ldB = FPAD; A.sA = (long)NPTS*FPAD; A.sB = (long)NPTS*FPAD;
  A.C = pL; A.ldC = NPTS; A.sC = (long)NPTS*NPTS;
  A.Ch = nullptr; A.Cl = nullptr; A.ldH = 0; A.sH = 0;
  A.Z = nullptr; A.ldZ = 0; A.sZ = 0; A.bias = nullptr;
  A.sq = psqn; A.sSq = NPTS;
  A.M = NPTS; A.N = NPTS; A.nseg = 1; A.kcs = FPAD/32; A.epi = 1;
  hgemm_kernel<<<dim3(16,16,BATCH), 256, HSM_TOT>>>(A);

  // fused mirror + laplacian + bf16 split
  mirror_lap_kernel<<<dim3(NPTS/32, NPTS/32, BATCH), dim3(32,8)>>>();

  // x12 = L2 @ out1
  for (int s = 0; s < 3; s++){
    A.Ah[s]=pLh; A.Al[s]=pLl;
    A.Bh[s]=pout1Th; A.Bl[s]=pout1Tl;
  }
  A.ldA = NPTS; A.ldB = NPTS; A.sA = (long)NPTS*NPTS; A.sB = (long)FPAD*NPTS;
  A.C = px12; A.ldC = F1V; A.sC = (long)NPTS*F1V;
  A.Ch = px12h; A.Cl = px12l; A.ldH = FPAD; A.sH = (long)NPTS*FPAD;
  A.Z = nullptr; A.sq = nullptr; A.bias = nullptr;
  A.M = NPTS; A.N = F1V; A.nseg = 1; A.kcs = NPTS/32; A.epi = 2;
  hgemm_kernel<<<dim3(8,16,BATCH), 256, HSM_TOT>>>(A);

  transpose_hilo_kernel<<<dim3(NPTS/32, 32, BATCH), dim3(32,8)>>>(px12, px12Th, px12Tl);

  // x22 = 2*L2@x12 - out1 (split2 only)
  for (int s = 0; s < 3; s++){
    A.Ah[s]=pLh; A.Al[s]=pLl;
    A.Bh[s]=px12Th; A.Bl[s]=px12Tl;
  }
  A.C = nullptr; A.ldC = 0; A.sC = 0;
  A.Ch = px22h; A.Cl = px22l; A.ldH = FPAD; A.sH = (long)NPTS*FPAD;
  A.Z = pout1; A.ldZ = F1V; A.sZ = (long)NPTS*F1V;
  A.M = NPTS; A.N = F1V; A.nseg = 1; A.kcs = NPTS/32; A.epi = 3;
  hgemm_kernel<<<dim3(8,16,BATCH), 256, HSM_TOT>>>(A);

  // W2 transposed split2 (interleaved rows 3c+seg)
  w2t_kernel<<<dim3(32, 32, 3), dim3(32,8)>>>(W2);

  // out2 = relu(out1@W2a + x12@W2b + x22@W2c + b2), M flattened
  A.Ah[0]=pout1h; A.Al[0]=pout1l;
  A.Ah[1]=px12h;  A.Al[1]=px12l;
  A.Ah[2]=px22h;  A.Al[2]=px22l;
  A.Bh[0]=pW2Th;                       A.Bl[0]=pW2Tl;
  A.Bh[1]=pW2Th + (size_t)FPAD*FPAD;   A.Bl[1]=pW2Tl + (size_t)FPAD*FPAD;
  A.Bh[2]=pW2Th + (size_t)2*FPAD*FPAD; A.Bl[2]=pW2Tl + (size_t)2*FPAD*FPAD;
  A.ldA = FPAD; A.ldB = FPAD; A.sA = 0; A.sB = 0;
  A.C = pout2; A.ldC = F1V; A.sC = 0;
  A.Ch = nullptr; A.Cl = nullptr; A.Z = nullptr;
  A.bias = b2;
  A.M = BATCH*NPTS; A.N = F1V; A.nseg = 3; A.kcs = FPAD/32; A.epi = 4;
  hgemm_kernel<<<dim3(8,256,1), 256, HSM_TOT>>>(A);

  // reg1 = ||out2^T (L2 x)||
  gemv6_kernel<<<dim3(NPTS/8, BATCH), 256>>>(x, nullptr, pLx, 1.f, 0.f);
  regnorm_kernel<<<dim3(8, BATCH), 128>>>(pout2, pLx, 1);
  colmax_kernel<<<dim3(4, BATCH), 256>>>(pout2, pg, NPTS);

  // Reeb branch
  reeb_xs_kernel<<<dim3(8, BATCH), 128>>>(Lr);
  wrt_kernel<<<dim3(188, 32), dim3(32,8)>>>(Wr);
  A.Ah[0]=pxsRh; A.Al[0]=pxsRl;
  A.Ah[1]=pxsRh; A.Al[1]=pxsRl;
  A.Ah[2]=pxsRh; A.Al[2]=pxsRl;
  A.Bh[0]=pWrTh; A.Bl[0]=pWrTl;
  A.Bh[1]=pWrTh; A.Bl[1]=pWrTl;
  A.Bh[2]=pWrTh; A.Bl[2]=pWrTl;
  A.ldA = RK; A.ldB = RK; A.sA = 0; A.sB = 0;
  A.C = poutR; A.ldC = F1V; A.sC = 0;
  A.Ch = nullptr; A.Cl = nullptr; A.Z = nullptr;
  A.bias = br;
  A.M = BATCH*RR; A.N = F1V; A.nseg = 1; A.kcs = RK/32; A.epi = 4;
  hgemm_kernel<<<dim3(8,3,1), 256, HSM_TOT>>>(A);
  colmax_kernel<<<dim3(4, BATCH), 256>>>(poutR, pgR, RR);

  // FC head
  fc1_kernel<<<BATCH, 512>>>(Wfc1, bfc1);
  fc2_kernel<<<BATCH, 128>>>(Wfc2, bfc2);
  fc3_kernel<<<BATCH, 64>>>(Wfc3, bfc3, out);

  // regs
  wreg_kernel<<<3, 256>>>(Wfc1, bfc1, Wfc2, bfc2, Wfc3, bfc3, out);
  finalize_kernel<<<1, 1>>>(out);
}

// round 13
// speedup vs baseline: 1.1161x; 1.0617x over previous
#include <cuda_runtime.h>
#include <cuda_bf16.h>
#include <math.h>
#include <stdint.h>

#define BATCH 16
#define NPTS 2048
#define CINF 6
#define RR 20
#define GG 128
#define F1V 1000
#define NCLS 40
#define FPAD 1024
#define RK 6016
#define RM 384

typedef __nv_bfloat16 bf16;

// ---------------- scratch (device globals; zero-initialized, no allocations) ----------------
__device__ float g_L[(size_t)BATCH*NPTS*NPTS];
__device__ float g_out1[(size_t)BATCH*NPTS*F1V];
__device__ float g_x12[(size_t)BATCH*NPTS*F1V];
__device__ float g_out2[(size_t)BATCH*NPTS*F1V];
__device__ bf16  g_Lh[(size_t)BATCH*NPTS*NPTS];
__device__ bf16  g_Ll[(size_t)BATCH*NPTS*NPTS];
__device__ bf16  g_out1h[(size_t)BATCH*NPTS*FPAD];
__device__ bf16  g_out1l[(size_t)BATCH*NPTS*FPAD];
__device__ bf16  g_out1Th[(size_t)BATCH*FPAD*NPTS];
__device__ bf16  g_out1Tl[(size_t)BATCH*FPAD*NPTS];
__device__ bf16  g_x12h[(size_t)BATCH*NPTS*FPAD];
__device__ bf16  g_x12l[(size_t)BATCH*NPTS*FPAD];
__device__ bf16  g_x12Th[(size_t)BATCH*FPAD*NPTS];
__device__ bf16  g_x12Tl[(size_t)BATCH*FPAD*NPTS];
__device__ bf16  g_x22h[(size_t)BATCH*NPTS*FPAD];
__device__ bf16  g_x22l[(size_t)BATCH*NPTS*FPAD];
__device__ bf16  g_W2Th[3*FPAD*FPAD];
__device__ bf16  g_W2Tl[3*FPAD*FPAD];
__device__ bf16  g_xsRh[(size_t)RM*RK];
__device__ bf16  g_xsRl[(size_t)RM*RK];
__device__ bf16  g_WrTh[(size_t)FPAD*RK];
__device__ bf16  g_WrTl[(size_t)FPAD*RK];
__device__ float g_x11[BATCH*NPTS*CINF];
__device__ float g_x21[BATCH*NPTS*CINF];
__device__ float g_Lx[BATCH*NPTS*CINF];
__device__ float g_rowsum[BATCH*NPTS];
__device__ float g_sqn[BATCH*NPTS];
__device__ float g_vR[BATCH*RR*F1V];
__device__ float g_outR[BATCH*RR*F1V];
__device__ float g_g[BATCH*F1V];
__device__ float g_gR[BATCH*F1V];
__device__ float g_h1[BATCH*512];
__device__ float g_h2[BATCH*128];
__device__ float g_acc[8];

// ---------------- helpers ----------------
__device__ __forceinline__ uint32_t smem_u32(const void* p){
  uint32_t a;
  asm("{ .reg .u64 t; cvta.to.shared.u64 t, %1; cvt.u32.u64 %0, t; }" : "=r"(a) : "l"(p));
  return a;
}
__device__ __forceinline__ void cp16(uint32_t s, const void* g){
  asm volatile("cp.async.cg.shared.global [%0], [%1], 16;" :: "r"(s), "l"(g));
}
__device__ __forceinline__ void ldsm4(uint32_t& r0, uint32_t& r1, uint32_t& r2, uint32_t& r3, uint32_t a){
  asm volatile("ldmatrix.sync.aligned.m8n8.x4.shared.b16 {%0,%1,%2,%3}, [%4];"
    : "=r"(r0), "=r"(r1), "=r"(r2), "=r"(r3) : "r"(a));
}
__device__ __forceinline__ void mma16816(float* d, const uint32_t* a, const uint32_t* b){
  asm volatile("mma.sync.aligned.m16n8k16.row.col.f32.bf16.bf16.f32 "
    "{%0,%1,%2,%3}, {%4,%5,%6,%7}, {%8,%9}, {%0,%1,%2,%3};"
    : "+f"(d[0]), "+f"(d[1]), "+f"(d[2]), "+f"(d[3])
    : "r"(a[0]), "r"(a[1]), "r"(a[2]), "r"(a[3]), "r"(b[0]), "r"(b[1]));
}
__device__ __forceinline__ void split2(float v, bf16* ph, bf16* pl){
  bf16 h = __float2bfloat16(v);
  *ph = h;
  *pl = __float2bfloat16(v - __bfloat162float(h));
}

// ---------------- HMMA GEMM: C[M,N], CTA tile 128x128, BK=32, 2-stage, 2 CTAs/SM ----------------
// epi: 0 plain C; 1 exp(2a - sq[m] - sq[n]) upper-only + rowsum atomics; 2 C + split2; 3 split2 of (2a - Z); 4 relu(a + bias[n])
struct GemmArgs {
  const bf16 *Ah[3], *Al[3], *Bh[3], *Bl[3];
  long ldA, ldB, sA, sB;
  float* C; long ldC, sC;
  bf16 *Ch, *Cl; long ldH, sH;
  const float* Z; long ldZ, sZ;
  const float* bias;
  const float* sq; long sSq;
  int M, N, nseg, kcs, epi;
};

#define STAGE_B 40960          // 4 parts * 128 rows * 80 bytes
#define PART_B  10240
#define HSM_TOT (2*STAGE_B)    // 81920 -> 2 CTAs per SM

__global__ __launch_bounds__(256, 2) void hgemm_kernel(GemmArgs P){
  // symmetric pairwise: skip lower-triangle blocks
  if (P.epi == 1 && blockIdx.x < blockIdx.y) return;

  extern __shared__ char sm[];
  uint32_t sb = smem_u32(sm);
  int tid = threadIdx.x;
  int w = tid >> 5, l = tid & 31;
  int wm = w & 3;
  int wn = w >> 2;
  int bz = blockIdx.z;
  int m0 = blockIdx.y * 128, n0 = blockIdx.x * 128;
  const int nk = P.nseg * P.kcs;

  float acc[2][8][4];
  #pragma unroll
  for (int t = 0; t < 2; t++)
    #pragma unroll
    for (int j = 0; j < 8; j++)
      #pragma unroll
      for (int r = 0; r < 4; r++) acc[t][j][r] = 0.f;

  auto stage_load = [&](int kt){
    int seg = kt / P.kcs, kc = kt % P.kcs;
    const bf16* pa[2] = {
      P.Ah[seg] + (size_t)bz*P.sA + (size_t)m0*P.ldA + (size_t)kc*32,
      P.Al[seg] + (size_t)bz*P.sA + (size_t)m0*P.ldA + (size_t)kc*32 };
    const bf16* pb[2] = {
      P.Bh[seg] + (size_t)bz*P.sB + (size_t)n0*P.ldB + (size_t)kc*32,
      P.Bl[seg] + (size_t)bz*P.sB + (size_t)n0*P.ldB + (size_t)kc*32 };
    uint32_t st = sb + (uint32_t)(kt & 1) * STAGE_B;
    #pragma unroll
    for (int i = 0; i < 8; i++){
      int part = i >> 1;
      int cid = tid + (i & 1)*256;
      int row = cid >> 2, col = cid & 3;
      const bf16* gp = (part < 2) ? pa[part] : pb[part - 2];
      long ld = (part < 2) ? P.ldA : P.ldB;
      cp16(st + part*PART_B + row*80 + col*16, gp + (size_t)row*ld + col*8);
    }
    asm volatile("cp.async.commit_group;" ::: "memory");
  };

  stage_load(0);

  for (int kt = 0; kt < nk; kt++){
    if (kt + 1 < nk){
      stage_load(kt + 1);
      asm volatile("cp.async.wait_group 1;" ::: "memory");
    } else {
      asm volatile("cp.async.wait_group 0;" ::: "memory");
    }
    __syncthreads();

    uint32_t st = sb + (uint32_t)(kt & 1) * STAGE_B;
    #pragma unroll
    for (int step = 0; step < 2; step++){
      uint32_t ah[2][4], al[2][4];
      #pragma unroll
      for (int t = 0; t < 2; t++){
        int row = wm*32 + t*16 + (l & 15);
        uint32_t koff = (uint32_t)(step*32 + ((l >> 4) & 1)*16);
        uint32_t addr = st + row*80 + koff;
        ldsm4(ah[t][0], ah[t][1], ah[t][2], ah[t][3], addr);
        ldsm4(al[t][0], al[t][1], al[t][2], al[t][3], addr + PART_B);
      }
      uint32_t bh[8][2], bl[8][2];
      #pragma unroll
      for (int j = 0; j < 4; j++){
        int n = wn*64 + j*16 + (((l >> 4) & 1) << 3) + (l & 7);
        uint32_t koff = (uint32_t)(step*32 + ((l >> 3) & 1)*16);
        uint32_t addr = st + 2*PART_B + n*80 + koff;
        ldsm4(bh[2*j][0], bh[2*j][1], bh[2*j+1][0], bh[2*j+1][1], addr);
        ldsm4(bl[2*j][0], bl[2*j][1], bl[2*j+1][0], bl[2*j+1][1], addr + PART_B);
      }
      #pragma unroll
      for (int t = 0; t < 2; t++)
        #pragma unroll
        for (int j = 0; j < 8; j++){
          mma16816(acc[t][j], ah[t], bh[j]);
          mma16816(acc[t][j], ah[t], bl[j]);
          mma16816(acc[t][j], al[t], bh[j]);
        }
    }
    __syncthreads();
  }

  // ---- epilogue ----
  int lm = l >> 2, ln = (l & 3)*2;

  if (P.epi == 1){
    const float* sqb = P.sq + (size_t)bz*P.sSq;
    float* C = P.C + (size_t)bz*P.sC;
    float* rs = g_rowsum + (size_t)bz*NPTS;
    bool dup = (blockIdx.x > blockIdx.y);
    float rowm[4] = {0.f, 0.f, 0.f, 0.f};
    float rown[16];
    #pragma unroll
    for (int q = 0; q < 16; q++) rown[q] = 0.f;
    #pragma unroll
    for (int t = 0; t < 2; t++){
      #pragma unroll
      for (int j = 0; j < 8; j++){
        #pragma unroll
        for (int r = 0; r < 4; r++){
          int m = m0 + wm*32 + t*16 + lm + (r >> 1)*8;
          int n = n0 + wn*64 + j*8 + ln + (r & 1);
          float e = expf(2.f*acc[t][j][r] - sqb[m] - sqb[n]);
          C[(size_t)m*P.ldC + n] = e;
          rowm[t*2 + (r >> 1)] += e;
          rown[j*2 + (r & 1)] += e;
        }
      }
    }
    #pragma unroll
    for (int q = 0; q < 4; q++){
      int m = m0 + wm*32 + (q >> 1)*16 + lm + (q & 1)*8;
      atomicAdd(&rs[m], rowm[q]);
    }
    if (dup){
      #pragma unroll
      for (int q = 0; q < 16; q++){
        int n = n0 + wn*64 + (q >> 1)*8 + ln + (q & 1);
        atomicAdd(&rs[n], rown[q]);
      }
    }
    return;
  }

  float* C = P.C ? (P.C + (size_t)bz*P.sC) : nullptr;
  bf16* Ch = P.Ch ? (P.Ch + (size_t)bz*P.sH) : nullptr;
  bf16* Cl = P.Cl ? (P.Cl + (size_t)bz*P.sH) : nullptr;
  const float* Z = P.Z ? (P.Z + (size_t)bz*P.sZ) : nullptr;

  #pragma unroll
  for (int t = 0; t < 2; t++){
    #pragma unroll
    for (int j = 0; j < 8; j++){
      #pragma unroll
      for (int r = 0; r < 4; r++){
        int m = m0 + wm*32 + t*16 + lm + (r >> 1)*8;
        int n = n0 + wn*64 + j*8 + ln + (r & 1);
        if (m < P.M && n < P.N){
          float a = acc[t][j][r];
          if (P.epi == 0){
            C[(size_t)m*P.ldC + n] = a;
          } else if (P.epi == 2){
            C[(size_t)m*P.ldC + n] = a;
            split2(a, Ch + (size_t)m*P.ldH + n, Cl + (size_t)m*P.ldH + n);
          } else if (P.epi == 3){
            float v = 2.f*a - Z[(size_t)m*P.ldZ + n];
            split2(v, Ch + (size_t)m*P.ldH + n, Cl + (size_t)m*P.ldH + n);
          } else {
            C[(size_t)m*P.ldC + n] = fmaxf(a + P.bias[n], 0.f);
          }
        }
      }
    }
  }
}

// fused mirror + laplacian + bf16 split for L2 (upper adj tiles -> bf16 L in both triangles)
__global__ void mirror_lap_kernel(){
  int b = blockIdx.z;
  int tx = blockIdx.x, ty = blockIdx.y;
  if (tx < ty) return;
  __shared__ float t[32][33];
  __shared__ float rim[32], rin[32];
  int x = threadIdx.x, y = threadIdx.y;
  size_t base = (size_t)b*NPTS*NPTS;
  for (int i = 0; i < 32; i += 8){
    int m = ty*32 + y + i, n = tx*32 + x;
    t[y+i][x] = g_L[base + (size_t)m*NPTS + n];
  }
  if (y == 0) rim[x] = rsqrtf(g_rowsum[b*NPTS + ty*32 + x]);
  if (y == 1) rin[x] = rsqrtf(g_rowsum[b*NPTS + tx*32 + x]);
  __syncthreads();
  for (int i = 0; i < 32; i += 8){
    int m = ty*32 + y + i, n = tx*32 + x;
    float Lv = ((m == n) ? 1.f : 0.f) - rim[y+i]*t[y+i][x]*rin[x];
    t[y+i][x] = Lv;
    size_t o = base + (size_t)m*NPTS + n;
    split2(Lv, &g_Lh[o], &g_Ll[o]);
  }
  if (tx > ty){
    __syncthreads();
    for (int i = 0; i < 32; i += 8){
      int m = tx*32 + y + i, n = ty*32 + x;
      float Lv = t[x][y+i];
      size_t o = base + (size_t)m*NPTS + n;
      split2(Lv, &g_Lh[o], &g_Ll[o]);
    }
  }
}

// ---------------- small kernels ----------------
__global__ void zeroacc_kernel(){ if (threadIdx.x < 8) g_acc[threadIdx.x] = 0.f; }

__global__ void zero_rs_kernel(){
  int i = blockIdx.x*256 + threadIdx.x;
  if (i < BATCH*NPTS) g_rowsum[i] = 0.f;
}

// symmetric pairwise adjacency: upper blocks only, mirrored via smem; fused rowsum
__global__ void pairwise6_kernel(const float* __restrict__ x){
  if (blockIdx.x < blockIdx.y) return;
  int b = blockIdx.z;
  int i0 = blockIdx.y*16, j0 = blockIdx.x*16;
  __shared__ float xi[16][6], xj[16][6];
  __shared__ float te[16][17];
  int tid = threadIdx.y*16 + threadIdx.x;
  if (tid < 96){
    int r = tid/6, c = tid%6;
    xi[r][c] = x[((size_t)b*NPTS + i0 + r)*CINF + c];
    xj[r][c] = x[((size_t)b*NPTS + j0 + r)*CINF + c];
  }
  __syncthreads();
  int i = threadIdx.y, j = threadIdx.x;
  float d = 0.f;
  #pragma unroll
  for (int c = 0; c < 6; c++){ float t = xi[i][c]-xj[j][c]; d += t*t; }
  float e = expf(-d);
  g_L[((size_t)b*NPTS + i0+i)*NPTS + j0+j] = e;
  te[i][j] = e;
  float* rs = g_rowsum + (size_t)b*NPTS;
  float s = e;
  #pragma unroll
  for (int o = 8; o > 0; o >>= 1) s += __shfl_down_sync(0xffffffffu, s, o, 16);
  if (j == 0) atomicAdd(&rs[i0 + i], s);
  if (blockIdx.x > blockIdx.y){
    __syncthreads();
    g_L[((size_t)b*NPTS + j0+i)*NPTS + i0+j] = te[j][i];
    if (tid < 16){
      float cs = 0.f;
      #pragma unroll
      for (int k = 0; k < 16; k++) cs += te[k][tid];
      atomicAdd(&rs[j0 + tid], cs);
    }
  }
}

// Y = s * (L1 @ X) + t*Z where L1 = I - D^-1/2 A D^-1/2 applied implicitly from adjacency+rowsum
__global__ void gemv6_adj_kernel(const float* __restrict__ X, const float* __restrict__ Z,
                                 float* __restrict__ Y, float s, float t){
  int b = blockIdx.y;
  __shared__ float xs[NPTS*CINF];
  const float* rs = g_rowsum + (size_t)b*NPTS;
  for (int idx = threadIdx.x; idx < NPTS*CINF; idx += 256){
    int row = idx / CINF;
    xs[idx] = X[(size_t)b*NPTS*CINF + idx] * rsqrtf(rs[row]);
  }
  __syncthreads();
  int warp = threadIdx.x >> 5, lane = threadIdx.x & 31;
  int i = blockIdx.x*8 + warp;
  const float* Arow = g_L + ((size_t)b*NPTS + i)*NPTS;
  float acc[6] = {0,0,0,0,0,0};
  for (int k = lane; k < NPTS; k += 32){
    float a = Arow[k];
    #pragma unroll
    for (int c = 0; c < 6; c++) acc[c] += a * xs[k*6 + c];
  }
  #pragma unroll
  for (int c = 0; c < 6; c++)
    for (int o = 16; o > 0; o >>= 1) acc[c] += __shfl_down_sync(0xffffffffu, acc[c], o);
  if (!lane){
    float rsi = rsqrtf(rs[i]);
    size_t base = ((size_t)b*NPTS + i)*CINF;
    #pragma unroll
    for (int c = 0; c < 6; c++){
      float v = s*(X[base + c] - rsi*acc[c]);
      if (Z) v += t*Z[base + c];
      Y[base + c] = v;
    }
  }
}

// Y = L2 @ X with L2 stored as bf16 h/l
__global__ void gemv6_bf16_kernel(const float* __restrict__ X, float* __restrict__ Y){
  int b = blockIdx.y;
  __shared__ float xs[NPTS*CINF];
  for (int idx = threadIdx.x; idx < NPTS*CINF; idx += 256)
    xs[idx] = X[(size_t)b*NPTS*CINF + idx];
  __syncthreads();
  int warp = threadIdx.x >> 5, lane = threadIdx.x & 31;
  int i = blockIdx.x*8 + warp;
  const __nv_bfloat162* Lh2 = (const __nv_bfloat162*)(g_Lh + ((size_t)b*NPTS + i)*NPTS);
  const __nv_bfloat162* Ll2 = (const __nv_bfloat162*)(g_Ll + ((size_t)b*NPTS + i)*NPTS);
  float acc[6] = {0,0,0,0,0,0};
  for (int k = lane; k < NPTS/2; k += 32){
    float2 h = __bfloat1622float2(Lh2[k]);
    float2 lo = __bfloat1622float2(Ll2[k]);
    float a0 = h.x + lo.x, a1 = h.y + lo.y;
    #pragma unroll
    for (int c = 0; c < 6; c++)
      acc[c] += a0*xs[(2*k)*6 + c] + a1*xs[(2*k+1)*6 + c];
  }
  #pragma unroll
  for (int c = 0; c < 6; c++)
    for (int o = 16; o > 0; o >>= 1) acc[c] += __shfl_down_sync(0xffffffffu, acc[c], o);
  if (!lane){
    size_t base = ((size_t)b*NPTS + i)*CINF;
    #pragma unroll
    for (int c = 0; c < 6; c++) Y[base + c] = acc[c];
  }
}

__global__ void cheb1_out_kernel(const float* __restrict__ x, const float* __restrict__ W1,
                                 const float* __restrict__ b1){
  int f = blockIdx.x*128 + threadIdx.x;
  int row0 = blockIdx.y*16;
  __shared__ float xsr[16][18];
  for (int idx = threadIdx.x; idx < 16*18; idx += 128){
    int r = idx/18, q = idx%18, c = q/3, kk = q%3;
    size_t g = (size_t)(row0 + r)*CINF + c;
    xsr[r][q] = (kk == 0) ? x[g] : ((kk == 1) ? g_x11[g] : g_x21[g]);
  }
  __syncthreads();
  if (f >= F1V) return;
  float w[18];
  #pragma unroll
  for (int q = 0; q < 18; q++) w[q] = W1[q*F1V + f];
  float bb = b1[f];
  for (int r = 0; r < 16; r++){
    float a = bb;
    #pragma unroll
    for (int q = 0; q < 18; q++) a += xsr[r][q]*w[q];
    float v = fmaxf(a, 0.f);
    size_t rowi = (size_t)(row0 + r);
    g_out1[rowi*F1V + f] = v;
    split2(v, &g_out1h[rowi*FPAD + f], &g_out1l[rowi*FPAD + f]);
  }
}

__global__ void regnorm_kernel(const float* __restrict__ outp, const float* __restrict__ xc, int slot){
  int b = blockIdx.y;
  int f = blockIdx.x*128 + threadIdx.x;
  __shared__ float sh[128*6];
  float acc[6] = {0,0,0,0,0,0};
  for (int i0 = 0; i0 < NPTS; i0 += 128){
    __syncthreads();
    for (int idx = threadIdx.x; idx < 128*6; idx += 128)
      sh[idx] = xc[((size_t)b*NPTS + i0)*CINF + idx];
    __syncthreads();
    if (f < F1V){
      for (int ii = 0; ii < 128; ii++){
        float o = outp[((size_t)b*NPTS + i0 + ii)*F1V + f];
        #pragma unroll
        for (int c = 0; c < 6; c++) acc[c] += o*sh[ii*6 + c];
      }
    }
  }
  float s = 0.f;
  #pragma unroll
  for (int c = 0; c < 6; c++) s += acc[c]*acc[c];
  if (f >= F1V) s = 0.f;
  __shared__ float red[128];
  red[threadIdx.x] = s; __syncthreads();
  for (int o = 64; o > 0; o >>= 1){ if (threadIdx.x < o) red[threadIdx.x] += red[threadIdx.x+o]; __syncthreads(); }
  if (!threadIdx.x) atomicAdd(&g_acc[slot], red[0]);
}

__global__ void gathermax_kernel(const int* __restrict__ sccs){
  int br = blockIdx.x;
  int b = br / RR;
  __shared__ int idx[GG];
  for (int t = threadIdx.x; t < GG; t += 256) idx[t] = sccs[(size_t)br*GG + t];
  __syncthreads();
  for (int f = threadIdx.x; f < F1V; f += 256){
    float m = -1e30f;
    for (int g = 0; g < GG; g++)
      m = fmaxf(m, g_out1[((size_t)b*NPTS + idx[g])*F1V + f]);
    g_vR[(size_t)br*F1V + f] = m;
  }
}

__global__ void sqnorm_kernel(){
  size_t row = blockIdx.x;
  const float* p = g_out1 + row*F1V;
  float s = 0.f;
  for (int k = threadIdx.x; k < F1V; k += 256){ float v = p[k]; s += v*v; }
  __shared__ float sh[256];
  sh[threadIdx.x] = s; __syncthreads();
  for (int o = 128; o > 0; o >>= 1){ if (threadIdx.x < o) sh[threadIdx.x] += sh[threadIdx.x+o]; __syncthreads(); }
  if (!threadIdx.x) g_sqn[row] = sh[0];
}

__global__ void colmax_kernel(const float* __restrict__ src, float* __restrict__ dst, int rows){
  int b = blockIdx.y;
  int f = blockIdx.x*256 + threadIdx.x;
  if (f >= F1V) return;
  float m = -1e30f;
  for (int i = 0; i < rows; i++)
    m = fmaxf(m, src[((size_t)b*rows + i)*F1V + f]);
  dst[(size_t)b*F1V + f] = m;
}

__global__ void transpose_hilo_kernel(const float* __restrict__ src,
                                      bf16* __restrict__ dh, bf16* __restrict__ dl){
  int b = blockIdx.z;
  __shared__ float t[32][33];
  int m0 = blockIdx.x*32, n0 = blockIdx.y*32;
  int x = threadIdx.x, y = threadIdx.y;
  for (int i = 0; i < 32; i += 8){
    int n = n0 + x, m = m0 + y + i;
    t[y+i][x] = (n < F1V) ? src[((size_t)b*NPTS + m)*F1V + n] : 0.f;
  }
  __syncthreads();
  for (int i = 0; i < 32; i += 8){
    int n = n0 + y + i, m = m0 + x;
    if (n < F1V){
      float v = t[x][y+i];
      size_t o = ((size_t)b*FPAD + n)*NPTS + m;
      split2(v, &dh[o], &dl[o]);
    }
  }
}

__global__ void w2t_kernel(const float* __restrict__ W2){
  int seg = blockIdx.z;
  __shared__ float t[32][33];
  int k0 = blockIdx.x*32, n0 = blockIdx.y*32;
  int x = threadIdx.x, y = threadIdx.y;
  for (int i = 0; i < 32; i += 8){
    int n = n0 + x, k = k0 + y + i;
    t[y+i][x] = (n < F1V && k < F1V) ? W2[(size_t)(3*k + seg)*F1V + n] : 0.f;
  }
  __syncthreads();
  for (int i = 0; i < 32; i += 8){
    int n = n0 + y + i, k = k0 + x;
    if (n < F1V && k < F1V){
      size_t o = (size_t)seg*FPAD*FPAD + (size_t)n*FPAD + k;
      split2(t[x][y+i], &g_W2Th[o], &g_W2Tl[o]);
    }
  }
}

__global__ void wrt_kernel(const float* __restrict__ Wr){
  __shared__ float t[32][33];
  int q0 = blockIdx.x*32, n0 = blockIdx.y*32;
  int x = threadIdx.x, y = threadIdx.y;
  for (int i = 0; i < 32; i += 8){
    int n = n0 + x, q = q0 + y + i;
    t[y+i][x] = (n < F1V && q < 6000) ? Wr[(size_t)q*F1V + n] : 0.f;
  }
  __syncthreads();
  for (int i = 0; i < 32; i += 8){
    int n = n0 + y + i, q = q0 + x;
    if (n < F1V && q < 6000){
      size_t o = (size_t)n*RK + q;
      split2(t[x][y+i], &g_WrTh[o], &g_WrTl[o]);
    }
  }
}

__global__ void reeb_xs_kernel(const float* __restrict__ Lr){
  int b = blockIdx.y;
  int c = blockIdx.x*128 + threadIdx.x;
  __shared__ float Ls[RR*RR];
  for (int t = threadIdx.x; t < RR*RR; t += 128) Ls[t] = Lr[(size_t)b*RR*RR + t];
  __syncthreads();
  if (c >= F1V) return;
  float v0[RR], v1[RR], v2[RR];
  #pragma unroll
  for (int r = 0; r < RR; r++){
    v0[r] = g_vR[((size_t)b*RR + r)*F1V + c];
    size_t o = (size_t)(b*RR + r)*RK + c*6 + 0;
    split2(v0[r], &g_xsRh[o], &g_xsRl[o]);
  }
  #pragma unroll
  for (int r = 0; r < RR; r++){
    float s = 0.f;
    for (int r2 = 0; r2 < RR; r2++) s += Ls[r*RR + r2]*v0[r2];
    v1[r] = s;
    size_t o = (size_t)(b*RR + r)*RK + c*6 + 1;
    split2(s, &g_xsRh[o], &g_xsRl[o]);
  }
  for (int k = 2; k < 6; k++){
    #pragma unroll
    for (int r = 0; r < RR; r++){
      float s = 0.f;
      for (int r2 = 0; r2 < RR; r2++) s += Ls[r*RR + r2]*v1[r2];
      v2[r] = 2.f*s - v0[r];
      size_t o = (size_t)(b*RR + r)*RK + c*6 + k;
      split2(v2[r], &g_xsRh[o], &g_xsRl[o]);
    }
    #pragma unroll
    for (int r = 0; r < RR; r++){ v0[r] = v1[r]; v1[r] = v2[r]; }
  }
}

__global__ void fc1_kernel(const float* __restrict__ W, const float* __restrict__ bias){
  int b = blockIdx.x;
  __shared__ float ft[2*F1V];
  for (int c = threadIdx.x; c < 2*F1V; c += 512)
    ft[c] = (c < F1V) ? g_gR[(size_t)b*F1V + c] : g_g[(size_t)b*F1V + c - F1V];
  __syncthreads();
  int f = threadIdx.x;
  float a = bias[f];
  for (int c = 0; c < 2*F1V; c++) a += ft[c]*W[(size_t)c*512 + f];
  g_h1[b*512 + f] = fmaxf(a, 0.f);
}

__global__ void fc2_kernel(const float* __restrict__ W, const float* __restrict__ bias){
  int b = blockIdx.x;
  __shared__ float hs[512];
  for (int c = threadIdx.x; c < 512; c += 128) hs[c] = g_h1[b*512 + c];
  __syncthreads();
  int f = threadIdx.x;
  float a = bias[f];
  for (int c = 0; c < 512; c++) a += hs[c]*W[c*128 + f];
  g_h2[b*128 + f] = fmaxf(a, 0.f);
}

__global__ void fc3_kernel(const float* __restrict__ W, const float* __restrict__ bias, float* __restrict__ out){
  int b = blockIdx.x;
  __shared__ float hs[128];
  for (int c = threadIdx.x; c < 128; c += 64) hs[c] = g_h2[b*128 + c];
  __syncthreads();
  int f = threadIdx.x;
  if (f < NCLS){
    float a = bias[f];
    for (int c = 0; c < 128; c++) a += hs[c]*W[c*NCLS + f];
    out[b*NCLS + f] = a;
  }
}

__global__ void wreg_kernel(const float* W1, const float* B1, const float* W2, const float* B2,
                            const float* W3, const float* B3, float* out){
  int layer = blockIdx.x;
  const float* W; const float* Bp; int n, ld;
  if (layer == 0){ W = W1; Bp = B1; n = 2000; ld = 512; }
  else if (layer == 1){ W = W2; Bp = B2; n = 512; ld = 128; }
  else { W = W3; Bp = B3; n = 128; ld = 40; }
  float s = 0.f;
  for (int c = threadIdx.x; c < n; c += 256){ float v = W[(size_t)c*ld]; s += v*v; }
  __shared__ float sh[256];
  sh[threadIdx.x] = s; __syncthreads();
  for (int o = 128; o > 0; o >>= 1){ if (threadIdx.x < o) sh[threadIdx.x] += sh[threadIdx.x+o]; __syncthreads(); }
  if (!threadIdx.x){ out[642 + layer*2] = sh[0]; out[643 + layer*2] = Bp[0]*Bp[0]; }
}

__global__ void finalize_kernel(float* out){
  out[640] = sqrtf(g_acc[0]);
  out[641] = sqrtf(g_acc[1]);
}

// ---------------- host launch ----------------
extern "C" void kernel_launch(void* const* d_in, const int* in_sizes, int n_in,
                              void* d_out, int out_size){
  const float* x    = (const float*)d_in[0];
  const float* Lr   = (const float*)d_in[1];
  const int*   sccs = (const int*)  d_in[2];
  const float* W1   = (const float*)d_in[3];  const float* b1  = (const float*)d_in[4];
  const float* W2   = (const float*)d_in[5];  const float* b2  = (const float*)d_in[6];
  const float* Wr   = (const float*)d_in[7];  const float* br  = (const float*)d_in[8];
  const float* Wfc1 = (const float*)d_in[9];  const float* bfc1= (const float*)d_in[10];
  const float* Wfc2 = (const float*)d_in[11]; const float* bfc2= (const float*)d_in[12];
  const float* Wfc3 = (const float*)d_in[13]; const float* bfc3= (const float*)d_in[14];
  float* out = (float*)d_out;

  static bool init_done = false;
  static cudaStream_t s_side = nullptr;
  static cudaEvent_t ev1 = nullptr, ev2 = nullptr;
  if (!init_done){
    cudaFuncSetAttribute(hgemm_kernel, cudaFuncAttributeMaxDynamicSharedMemorySize, HSM_TOT);
    cudaStreamCreateWithFlags(&s_side, cudaStreamNonBlocking);
    cudaEventCreateWithFlags(&ev1, cudaEventDisableTiming);
    cudaEventCreateWithFlags(&ev2, cudaEventDisableTiming);
    init_done = true;
  }

  float *pL, *pout1, *px12, *pout2, *px11, *px21, *pLx, *psqn, *poutR, *pg, *pgR;
  bf16 *pLh, *pLl, *pout1h, *pout1l, *pout1Th, *pout1Tl;
  bf16 *px12h, *px12l, *px12Th, *px12Tl;
  bf16 *px22h, *px22l, *pW2Th, *pW2Tl;
  bf16 *pxsRh, *pxsRl, *pWrTh, *pWrTl;
  cudaGetSymbolAddress((void**)&pL,      g_L);
  cudaGetSymbolAddress((void**)&pout1,   g_out1);
  cudaGetSymbolAddress((void**)&px12,    g_x12);
  cudaGetSymbolAddress((void**)&pout2,   g_out2);
  cudaGetSymbolAddress((void**)&px11,    g_x11);
  cudaGetSymbolAddress((void**)&px21,    g_x21);
  cudaGetSymbolAddress((void**)&pLx,     g_Lx);
  cudaGetSymbolAddress((void**)&psqn,    g_sqn);
  cudaGetSymbolAddress((void**)&poutR,   g_outR);
  cudaGetSymbolAddress((void**)&pg,      g_g);
  cudaGetSymbolAddress((void**)&pgR,     g_gR);
  cudaGetSymbolAddress((void**)&pLh,     g_Lh);
  cudaGetSymbolAddress((void**)&pLl,     g_Ll);
  cudaGetSymbolAddress((void**)&pout1h,  g_out1h);
  cudaGetSymbolAddress((void**)&pout1l,  g_out1l);
  cudaGetSymbolAddress((void**)&pout1Th, g_out1Th);
  cudaGetSymbolAddress((void**)&pout1Tl, g_out1Tl);
  cudaGetSymbolAddress((void**)&px12h,   g_x12h);
  cudaGetSymbolAddress((void**)&px12l,   g_x12l);
  cudaGetSymbolAddress((void**)&px12Th,  g_x12Th);
  cudaGetSymbolAddress((void**)&px12Tl,  g_x12Tl);
  cudaGetSymbolAddress((void**)&px22h,   g_x22h);
  cudaGetSymbolAddress((void**)&px22l,   g_x22l);
  cudaGetSymbolAddress((void**)&pW2Th,   g_W2Th);
  cudaGetSymbolAddress((void**)&pW2Tl,   g_W2Tl);
  cudaGetSymbolAddress((void**)&pxsRh,   g_xsRh);
  cudaGetSymbolAddress((void**)&pxsRl,   g_xsRl);
  cudaGetSymbolAddress((void**)&pWrTh,   g_WrTh);
  cudaGetSymbolAddress((void**)&pWrTl,   g_WrTl);

  zeroacc_kernel<<<1, 32>>>();
  zero_rs_kernel<<<128, 256>>>();

  // adjacency A1 (symmetric, upper computed + mirrored) with fused rowsum; L1 never materialized
  pairwise6_kernel<<<dim3(NPTS/16, NPTS/16, BATCH), dim3(16,16)>>>(x);

  // cheb conv 1 via implicit laplacian
  gemv6_adj_kernel<<<dim3(NPTS/8, BATCH), 256>>>(x, nullptr, px11, 1.f, 0.f);
  gemv6_adj_kernel<<<dim3(NPTS/8, BATCH), 256>>>(px11, x, px21, 2.f, -1.f);
  cheb1_out_kernel<<<dim3(8, (BATCH*NPTS)/16), 128>>>(x, W1, b1);
  transpose_hilo_kernel<<<dim3(NPTS/32, 32, BATCH), dim3(32,8)>>>(pout1, pout1Th, pout1Tl);
  regnorm_kernel<<<dim3(8, BATCH), 128>>>(pout1, px11, 0);
  gathermax_kernel<<<BATCH*RR, 256>>>(sccs);

  // ---- fork side stream: Reeb branch (independent of out2 chain) ----
  cudaEventRecord(ev1, 0);
  cudaStreamWaitEvent(s_side, ev1, 0);
  wrt_kernel<<<dim3(188, 32), dim3(32,8), 0, s_side>>>(Wr);
  reeb_xs_kernel<<<dim3(8, BATCH), 128, 0, s_side>>>(Lr);
  {
    GemmArgs R{};
    R.Ah[0]=pxsRh; R.Al[0]=pxsRl; R.Bh[0]=pWrTh; R.Bl[0]=pWrTl;
    R.Ah[1]=pxsRh; R.Al[1]=pxsRl; R.Bh[1]=pWrTh; R.Bl[1]=pWrTl;
    R.Ah[2]=pxsRh; R.Al[2]=pxsRl; R.Bh[2]=pWrTh; R.Bl[2]=pWrTl;
    R.ldA = RK; R.ldB = RK; R.sA = 0; R.sB = 0;
    R.C = poutR; R.ldC = F1V; R.sC = 0;
    R.Ch = nullptr; R.Cl = nullptr; R.ldH = 0; R.sH = 0;
    R.Z = nullptr; R.ldZ = 0; R.sZ = 0;
    R.bias = br; R.sq = nullptr; R.sSq = 0;
    R.M = BATCH*RR; R.N = F1V; R.nseg = 1; R.kcs = RK/32; R.epi = 4;
    hgemm_kernel<<<dim3(8,3,1), 256, HSM_TOT, s_side>>>(R);
  }
  colmax_kernel<<<dim3(4, BATCH), 256, 0, s_side>>>(poutR, pgR, RR);
  cudaEventRecord(ev2, s_side);

  // ---- main chain continues ----
  sqnorm_kernel<<<BATCH*NPTS, 256>>>();
  zero_rs_kernel<<<128, 256>>>();

  GemmArgs A{};
  // adj2 = exp(2*out1@out1^T - sq_m - sq_n), upper triangle + fused rowsum atomics
  for (int s = 0; s < 3; s++){
    A.Ah[s]=pout1h; A.Al[s]=pout1l;
    A.Bh[s]=pout1h; A.Bl[s]=pout1l;
  }
  A.ldA = FPAD; A.ldB = FPAD; A.sA = (long)NPTS*FPAD; A.sB = (long)NPTS*FPAD;
  A.C = pL; A.ldC = NPTS; A.sC = (long)NPTS*NPTS;
  A.Ch = nullptr; A.Cl = nullptr; A.ldH = 0; A.sH = 0;
  A.Z = nullptr; A.ldZ = 0; A.sZ = 0; A.bias = nullptr;
  A.sq = psqn; A.sSq = NPTS;
  A.M = NPTS; A.N = NPTS; A.nseg = 1; A.kcs = FPAD/32; A.epi = 1;
  hgemm_kernel<<<dim3(16,16,BATCH), 256, HSM_TOT>>>(A);

  // fused mirror + laplacian -> bf16 L2 only
  mirror_lap_kernel<<<dim3(NPTS/32, NPTS/32, BATCH), dim3(32,8)>>>();

  // x12 = L2 @ out1
  for (int s = 0; s < 3; s++){
    A.Ah[s]=pLh; A.Al[s]=pLl;
    A.Bh[s]=pout1Th; A.Bl[s]=pout1Tl;
  }
  A.ldA = NPTS; A.ldB = NPTS; A.sA = (long)NPTS*NPTS; A.sB = (long)FPAD*NPTS;
  A.C = px12; A.ldC = F1V; A.sC = (long)NPTS*F1V;
  A.Ch = px12h; A.Cl = px12l; A.ldH = FPAD; A.sH = (long)NPTS*FPAD;
  A.Z = nullptr; A.sq = nullptr; A.bias = nullptr;
  A.M = NPTS; A.N = F1V; A.nseg = 1; A.kcs = NPTS/32; A.epi = 2;
  hgemm_kernel<<<dim3(8,16,BATCH), 256, HSM_TOT>>>(A);

  transpose_hilo_kernel<<<dim3(NPTS/32, 32, BATCH), dim3(32,8)>>>(px12, px12Th, px12Tl);

  // x22 = 2*L2@x12 - out1 (split2 only)
  for (int s = 0; s < 3; s++){
    A.Ah[s]=pLh; A.Al[s]=pLl;
    A.Bh[s]=px12Th; A.Bl[s]=px12Tl;
  }
  A.C = nullptr; A.ldC = 0; A.sC = 0;
  A.Ch = px22h; A.Cl = px22l; A.ldH = FPAD; A.sH = (long)NPTS*FPAD;
  A.Z = pout1; A.ldZ = F1V; A.sZ = (long)NPTS*F1V;
  A.M = NPTS; A.N = F1V; A.nseg = 1; A.kcs = NPTS/32; A.epi = 3;
  hgemm_kernel<<<dim3(8,16,BATCH), 256, HSM_TOT>>>(A);

  // W2 transposed split2 (interleaved rows 3c+seg)
  w2t_kernel<<<dim3(32, 32, 3), dim3(32,8)>>>(W2);

  // out2 = relu(out1@W2a + x12@W2b + x22@W2c + b2), M flattened
  A.Ah[0]=pout1h; A.Al[0]=pout1l;
  A.Ah[1]=px12h;  A.Al[1]=px12l;
  A.Ah[2]=px22h;  A.Al[2]=px22l;
  A.Bh[0]=pW2Th;                       A.Bl[0]=pW2Tl;
  A.Bh[1]=pW2Th + (size_t)FPAD*FPAD;   A.Bl[1]=pW2Tl + (size_t)FPAD*FPAD;
  A.Bh[2]=pW2Th + (size_t)2*FPAD*FPAD; A.Bl[2]=pW2Tl + (size_t)2*FPAD*FPAD;
  A.ldA = FPAD; A.ldB = FPAD; A.sA = 0; A.sB = 0;
  A.C = pout2; A.ldC = F1V; A.sC = 0;
  A.Ch = nullptr; A.Cl = nullptr; A.Z = nullptr;
  A.bias = b2;
  A.M = BATCH*NPTS; A.N = F1V; A.nseg = 3; A.kcs = FPAD/32; A.epi = 4;
  hgemm_kernel<<<dim3(8,256,1), 256, HSM_TOT>>>(A);

  // reg1 = ||out2^T (L2 x)|| with L2 from bf16 pair
  gemv6_bf16_kernel<<<dim3(NPTS/8, BATCH), 256>>>(x, pLx);
  regnorm_kernel<<<dim3(8, BATCH), 128>>>(pout2, pLx, 1);
  colmax_kernel<<<dim3(4, BATCH), 256>>>(pout2, pg, NPTS);

  // ---- join side stream before FC head ----
  cudaStreamWaitEvent(0, ev2, 0);

  // FC head
  fc1_kernel<<<BATCH, 512>>>(Wfc1, bfc1);
  fc2_kernel<<<BATCH, 128>>>(Wfc2, bfc2);
  fc3_kernel<<<BATCH, 64>>>(Wfc3, bfc3, out);

  // regs
  wreg_kernel<<<3, 256>>>(Wfc1, bfc1, Wfc2, bfc2, Wfc3, bfc3, out);
  finalize_kernel<<<1, 1>>>(out);
}

// round 15
// speedup vs baseline: 1.2061x; 1.0806x over previous
#include <cuda_runtime.h>
#include <cuda_bf16.h>
#include <math.h>
#include <stdint.h>

#define BATCH 16
#define NPTS 2048
#define CINF 6
#define RR 20
#define GG 128
#define F1V 1000
#define NCLS 40
#define FPAD 1024
#define RK 6016
#define RM 384

typedef __nv_bfloat16 bf16;

// ---------------- scratch (device globals; zero-initialized, no allocations) ----------------
__device__ float g_L[(size_t)BATCH*NPTS*NPTS];
__device__ float g_out1[(size_t)BATCH*NPTS*F1V];
__device__ float g_x12[(size_t)BATCH*NPTS*F1V];
__device__ float g_out2[(size_t)BATCH*NPTS*F1V];
__device__ bf16  g_Lh[(size_t)BATCH*NPTS*NPTS];
__device__ bf16  g_Ll[(size_t)BATCH*NPTS*NPTS];
__device__ bf16  g_out1h[(size_t)BATCH*NPTS*FPAD];
__device__ bf16  g_out1l[(size_t)BATCH*NPTS*FPAD];
__device__ bf16  g_out1Th[(size_t)BATCH*FPAD*NPTS];
__device__ bf16  g_out1Tl[(size_t)BATCH*FPAD*NPTS];
__device__ bf16  g_x12h[(size_t)BATCH*NPTS*FPAD];
__device__ bf16  g_x12l[(size_t)BATCH*NPTS*FPAD];
__device__ bf16  g_x12Th[(size_t)BATCH*FPAD*NPTS];
__device__ bf16  g_x12Tl[(size_t)BATCH*FPAD*NPTS];
__device__ bf16  g_x22h[(size_t)BATCH*NPTS*FPAD];
__device__ bf16  g_x22l[(size_t)BATCH*NPTS*FPAD];
__device__ bf16  g_W2Th[3*FPAD*FPAD];
__device__ bf16  g_W2Tl[3*FPAD*FPAD];
__device__ bf16  g_xsRh[(size_t)RM*RK];
__device__ bf16  g_xsRl[(size_t)RM*RK];
__device__ bf16  g_WrTh[(size_t)FPAD*RK];
__device__ bf16  g_WrTl[(size_t)FPAD*RK];
__device__ float g_x11[BATCH*NPTS*CINF];
__device__ float g_x21[BATCH*NPTS*CINF];
__device__ float g_Lx[BATCH*NPTS*CINF];
__device__ float g_rowsum[BATCH*NPTS];
__device__ float g_sqn[BATCH*NPTS];
__device__ float g_vR[BATCH*RR*F1V];
__device__ float g_outR[BATCH*RR*F1V];
__device__ float g_g[BATCH*F1V];
__device__ float g_gR[BATCH*F1V];
__device__ float g_h1[BATCH*512];
__device__ float g_h2[BATCH*128];
__device__ float g_acc[8];

// ---------------- helpers ----------------
__device__ __forceinline__ uint32_t smem_u32(const void* p){
  uint32_t a;
  asm("{ .reg .u64 t; cvta.to.shared.u64 t, %1; cvt.u32.u64 %0, t; }" : "=r"(a) : "l"(p));
  return a;
}
__device__ __forceinline__ void cp16(uint32_t s, const void* g){
  asm volatile("cp.async.cg.shared.global [%0], [%1], 16;" :: "r"(s), "l"(g));
}
__device__ __forceinline__ void ldsm4(uint32_t& r0, uint32_t& r1, uint32_t& r2, uint32_t& r3, uint32_t a){
  asm volatile("ldmatrix.sync.aligned.m8n8.x4.shared.b16 {%0,%1,%2,%3}, [%4];"
    : "=r"(r0), "=r"(r1), "=r"(r2), "=r"(r3) : "r"(a));
}
__device__ __forceinline__ void mma16816(float* d, const uint32_t* a, const uint32_t* b){
  asm volatile("mma.sync.aligned.m16n8k16.row.col.f32.bf16.bf16.f32 "
    "{%0,%1,%2,%3}, {%4,%5,%6,%7}, {%8,%9}, {%0,%1,%2,%3};"
    : "+f"(d[0]), "+f"(d[1]), "+f"(d[2]), "+f"(d[3])
    : "r"(a[0]), "r"(a[1]), "r"(a[2]), "r"(a[3]), "r"(b[0]), "r"(b[1]));
}
__device__ __forceinline__ void split2(float v, bf16* ph, bf16* pl){
  bf16 h = __float2bfloat16(v);
  *ph = h;
  *pl = __float2bfloat16(v - __bfloat162float(h));
}

// ---------------- HMMA GEMM: C[M,N], CTA tile 128x128, BK=32, 2-stage, 2 CTAs/SM ----------------
// epi: 0 plain C; 1 exp(2a - sq[m] - sq[n]) upper-only + rowsum atomics; 2 C + split2; 3 split2 of (2a - Z); 4 relu(a + bias[n])
struct GemmArgs {
  const bf16 *Ah[3], *Al[3], *Bh[3], *Bl[3];
  long ldA, ldB, sA, sB;
  float* C; long ldC, sC;
  bf16 *Ch, *Cl; long ldH, sH;
  const float* Z; long ldZ, sZ;
  const float* bias;
  const float* sq; long sSq;
  int M, N, nseg, kcs, epi;
};

#define STAGE_B 40960          // 4 parts * 128 rows * 80 bytes
#define PART_B  10240
#define HSM_TOT (2*STAGE_B)    // 81920 -> 2 CTAs per SM

__global__ __launch_bounds__(256, 2) void hgemm_kernel(GemmArgs P){
  // symmetric pairwise: skip lower-triangle blocks
  if (P.epi == 1 && blockIdx.x < blockIdx.y) return;

  extern __shared__ char sm[];
  uint32_t sb = smem_u32(sm);
  int tid = threadIdx.x;
  int w = tid >> 5, l = tid & 31;
  int wm = w & 3;
  int wn = w >> 2;
  int bz = blockIdx.z;
  int m0 = blockIdx.y * 128, n0 = blockIdx.x * 128;
  const int nk = P.nseg * P.kcs;

  float acc[2][8][4];
  #pragma unroll
  for (int t = 0; t < 2; t++)
    #pragma unroll
    for (int j = 0; j < 8; j++)
      #pragma unroll
      for (int r = 0; r < 4; r++) acc[t][j][r] = 0.f;

  auto stage_load = [&](int kt){
    int seg = kt / P.kcs, kc = kt % P.kcs;
    const bf16* pa[2] = {
      P.Ah[seg] + (size_t)bz*P.sA + (size_t)m0*P.ldA + (size_t)kc*32,
      P.Al[seg] + (size_t)bz*P.sA + (size_t)m0*P.ldA + (size_t)kc*32 };
    const bf16* pb[2] = {
      P.Bh[seg] + (size_t)bz*P.sB + (size_t)n0*P.ldB + (size_t)kc*32,
      P.Bl[seg] + (size_t)bz*P.sB + (size_t)n0*P.ldB + (size_t)kc*32 };
    uint32_t st = sb + (uint32_t)(kt & 1) * STAGE_B;
    #pragma unroll
    for (int i = 0; i < 8; i++){
      int part = i >> 1;
      int cid = tid + (i & 1)*256;
      int row = cid >> 2, col = cid & 3;
      const bf16* gp = (part < 2) ? pa[part] : pb[part - 2];
      long ld = (part < 2) ? P.ldA : P.ldB;
      cp16(st + part*PART_B + row*80 + col*16, gp + (size_t)row*ld + col*8);
    }
    asm volatile("cp.async.commit_group;" ::: "memory");
  };

  stage_load(0);

  for (int kt = 0; kt < nk; kt++){
    if (kt + 1 < nk){
      stage_load(kt + 1);
      asm volatile("cp.async.wait_group 1;" ::: "memory");
    } else {
      asm volatile("cp.async.wait_group 0;" ::: "memory");
    }
    __syncthreads();

    uint32_t st = sb + (uint32_t)(kt & 1) * STAGE_B;
    #pragma unroll
    for (int step = 0; step < 2; step++){
      uint32_t ah[2][4], al[2][4];
      #pragma unroll
      for (int t = 0; t < 2; t++){
        int row = wm*32 + t*16 + (l & 15);
        uint32_t koff = (uint32_t)(step*32 + ((l >> 4) & 1)*16);
        uint32_t addr = st + row*80 + koff;
        ldsm4(ah[t][0], ah[t][1], ah[t][2], ah[t][3], addr);
        ldsm4(al[t][0], al[t][1], al[t][2], al[t][3], addr + PART_B);
      }
      uint32_t bh[8][2], bl[8][2];
      #pragma unroll
      for (int j = 0; j < 4; j++){
        int n = wn*64 + j*16 + (((l >> 4) & 1) << 3) + (l & 7);
        uint32_t koff = (uint32_t)(step*32 + ((l >> 3) & 1)*16);
        uint32_t addr = st + 2*PART_B + n*80 + koff;
        ldsm4(bh[2*j][0], bh[2*j][1], bh[2*j+1][0], bh[2*j+1][1], addr);
        ldsm4(bl[2*j][0], bl[2*j][1], bl[2*j+1][0], bl[2*j+1][1], addr + PART_B);
      }
      #pragma unroll
      for (int t = 0; t < 2; t++)
        #pragma unroll
        for (int j = 0; j < 8; j++){
          mma16816(acc[t][j], ah[t], bh[j]);
          mma16816(acc[t][j], ah[t], bl[j]);
          mma16816(acc[t][j], al[t], bh[j]);
        }
    }
    __syncthreads();
  }

  // ---- epilogue ----
  int lm = l >> 2, ln = (l & 3)*2;

  if (P.epi == 1){
    const float* sqb = P.sq + (size_t)bz*P.sSq;
    float* C = P.C + (size_t)bz*P.sC;
    float* rs = g_rowsum + (size_t)bz*NPTS;
    bool dup = (blockIdx.x > blockIdx.y);
    float rowm[4] = {0.f, 0.f, 0.f, 0.f};
    float rown[16];
    #pragma unroll
    for (int q = 0; q < 16; q++) rown[q] = 0.f;
    #pragma unroll
    for (int t = 0; t < 2; t++){
      #pragma unroll
      for (int j = 0; j < 8; j++){
        #pragma unroll
        for (int r = 0; r < 4; r++){
          int m = m0 + wm*32 + t*16 + lm + (r >> 1)*8;
          int n = n0 + wn*64 + j*8 + ln + (r & 1);
          float e = expf(2.f*acc[t][j][r] - sqb[m] - sqb[n]);
          C[(size_t)m*P.ldC + n] = e;
          rowm[t*2 + (r >> 1)] += e;
          rown[j*2 + (r & 1)] += e;
        }
      }
    }
    #pragma unroll
    for (int q = 0; q < 4; q++){
      int m = m0 + wm*32 + (q >> 1)*16 + lm + (q & 1)*8;
      atomicAdd(&rs[m], rowm[q]);
    }
    if (dup){
      #pragma unroll
      for (int q = 0; q < 16; q++){
        int n = n0 + wn*64 + (q >> 1)*8 + ln + (q & 1);
        atomicAdd(&rs[n], rown[q]);
      }
    }
    return;
  }

  float* C = P.C ? (P.C + (size_t)bz*P.sC) : nullptr;
  bf16* Ch = P.Ch ? (P.Ch + (size_t)bz*P.sH) : nullptr;
  bf16* Cl = P.Cl ? (P.Cl + (size_t)bz*P.sH) : nullptr;
  const float* Z = P.Z ? (P.Z + (size_t)bz*P.sZ) : nullptr;

  #pragma unroll
  for (int t = 0; t < 2; t++){
    #pragma unroll
    for (int j = 0; j < 8; j++){
      #pragma unroll
      for (int r = 0; r < 4; r++){
        int m = m0 + wm*32 + t*16 + lm + (r >> 1)*8;
        int n = n0 + wn*64 + j*8 + ln + (r & 1);
        if (m < P.M && n < P.N){
          float a = acc[t][j][r];
          if (P.epi == 0){
            C[(size_t)m*P.ldC + n] = a;
          } else if (P.epi == 2){
            C[(size_t)m*P.ldC + n] = a;
            split2(a, Ch + (size_t)m*P.ldH + n, Cl + (size_t)m*P.ldH + n);
          } else if (P.epi == 3){
            float v = 2.f*a - Z[(size_t)m*P.ldZ + n];
            split2(v, Ch + (size_t)m*P.ldH + n, Cl + (size_t)m*P.ldH + n);
          } else {
            C[(size_t)m*P.ldC + n] = fmaxf(a + P.bias[n], 0.f);
          }
        }
      }
    }
  }
}

// fused mirror + laplacian + bf16 split for L2 (upper adj tiles -> bf16 L in both triangles)
__global__ void mirror_lap_kernel(){
  int b = blockIdx.z;
  int tx = blockIdx.x, ty = blockIdx.y;
  if (tx < ty) return;
  __shared__ float t[32][33];
  __shared__ float rim[32], rin[32];
  int x = threadIdx.x, y = threadIdx.y;
  size_t base = (size_t)b*NPTS*NPTS;
  for (int i = 0; i < 32; i += 8){
    int m = ty*32 + y + i, n = tx*32 + x;
    t[y+i][x] = g_L[base + (size_t)m*NPTS + n];
  }
  if (y == 0) rim[x] = rsqrtf(g_rowsum[b*NPTS + ty*32 + x]);
  if (y == 1) rin[x] = rsqrtf(g_rowsum[b*NPTS + tx*32 + x]);
  __syncthreads();
  for (int i = 0; i < 32; i += 8){
    int m = ty*32 + y + i, n = tx*32 + x;
    float Lv = ((m == n) ? 1.f : 0.f) - rim[y+i]*t[y+i][x]*rin[x];
    t[y+i][x] = Lv;
    size_t o = base + (size_t)m*NPTS + n;
    split2(Lv, &g_Lh[o], &g_Ll[o]);
  }
  if (tx > ty){
    __syncthreads();
    for (int i = 0; i < 32; i += 8){
      int m = tx*32 + y + i, n = ty*32 + x;
      float Lv = t[x][y+i];
      size_t o = base + (size_t)m*NPTS + n;
      split2(Lv, &g_Lh[o], &g_Ll[o]);
    }
  }
}

// ---------------- small kernels ----------------
__global__ void zeroacc_kernel(){ if (threadIdx.x < 8) g_acc[threadIdx.x] = 0.f; }

__global__ void zero_rs_kernel(){
  int i = blockIdx.x*256 + threadIdx.x;
  if (i < BATCH*NPTS) g_rowsum[i] = 0.f;
}

__global__ void pairwise6_kernel(const float* __restrict__ x){
  if (blockIdx.x < blockIdx.y) return;
  int b = blockIdx.z;
  int i0 = blockIdx.y*16, j0 = blockIdx.x*16;
  __shared__ float xi[16][6], xj[16][6];
  __shared__ float te[16][17];
  int tid = threadIdx.y*16 + threadIdx.x;
  if (tid < 96){
    int r = tid/6, c = tid%6;
    xi[r][c] = x[((size_t)b*NPTS + i0 + r)*CINF + c];
    xj[r][c] = x[((size_t)b*NPTS + j0 + r)*CINF + c];
  }
  __syncthreads();
  int i = threadIdx.y, j = threadIdx.x;
  float d = 0.f;
  #pragma unroll
  for (int c = 0; c < 6; c++){ float t = xi[i][c]-xj[j][c]; d += t*t; }
  float e = expf(-d);
  g_L[((size_t)b*NPTS + i0+i)*NPTS + j0+j] = e;
  te[i][j] = e;
  float* rs = g_rowsum + (size_t)b*NPTS;
  float s = e;
  #pragma unroll
  for (int o = 8; o > 0; o >>= 1) s += __shfl_down_sync(0xffffffffu, s, o, 16);
  if (j == 0) atomicAdd(&rs[i0 + i], s);
  if (blockIdx.x > blockIdx.y){
    __syncthreads();
    g_L[((size_t)b*NPTS + j0+i)*NPTS + i0+j] = te[j][i];
    if (tid < 16){
      float cs = 0.f;
      #pragma unroll
      for (int k = 0; k < 16; k++) cs += te[k][tid];
      atomicAdd(&rs[j0 + tid], cs);
    }
  }
}

__global__ void gemv6_adj_kernel(const float* __restrict__ X, const float* __restrict__ Z,
                                 float* __restrict__ Y, float s, float t){
  int b = blockIdx.y;
  __shared__ float xs[NPTS*CINF];
  const float* rs = g_rowsum + (size_t)b*NPTS;
  for (int idx = threadIdx.x; idx < NPTS*CINF; idx += 256){
    int row = idx / CINF;
    xs[idx] = X[(size_t)b*NPTS*CINF + idx] * rsqrtf(rs[row]);
  }
  __syncthreads();
  int warp = threadIdx.x >> 5, lane = threadIdx.x & 31;
  int i = blockIdx.x*8 + warp;
  const float* Arow = g_L + ((size_t)b*NPTS + i)*NPTS;
  float acc[6] = {0,0,0,0,0,0};
  for (int k = lane; k < NPTS; k += 32){
    float a = Arow[k];
    #pragma unroll
    for (int c = 0; c < 6; c++) acc[c] += a * xs[k*6 + c];
  }
  #pragma unroll
  for (int c = 0; c < 6; c++)
    for (int o = 16; o > 0; o >>= 1) acc[c] += __shfl_down_sync(0xffffffffu, acc[c], o);
  if (!lane){
    float rsi = rsqrtf(rs[i]);
    size_t base = ((size_t)b*NPTS + i)*CINF;
    #pragma unroll
    for (int c = 0; c < 6; c++){
      float v = s*(X[base + c] - rsi*acc[c]);
      if (Z) v += t*Z[base + c];
      Y[base + c] = v;
    }
  }
}

__global__ void gemv6_bf16_kernel(const float* __restrict__ X, float* __restrict__ Y){
  int b = blockIdx.y;
  __shared__ float xs[NPTS*CINF];
  for (int idx = threadIdx.x; idx < NPTS*CINF; idx += 256)
    xs[idx] = X[(size_t)b*NPTS*CINF + idx];
  __syncthreads();
  int warp = threadIdx.x >> 5, lane = threadIdx.x & 31;
  int i = blockIdx.x*8 + warp;
  const __nv_bfloat162* Lh2 = (const __nv_bfloat162*)(g_Lh + ((size_t)b*NPTS + i)*NPTS);
  const __nv_bfloat162* Ll2 = (const __nv_bfloat162*)(g_Ll + ((size_t)b*NPTS + i)*NPTS);
  float acc[6] = {0,0,0,0,0,0};
  for (int k = lane; k < NPTS/2; k += 32){
    float2 h = __bfloat1622float2(Lh2[k]);
    float2 lo = __bfloat1622float2(Ll2[k]);
    float a0 = h.x + lo.x, a1 = h.y + lo.y;
    #pragma unroll
    for (int c = 0; c < 6; c++)
      acc[c] += a0*xs[(2*k)*6 + c] + a1*xs[(2*k+1)*6 + c];
  }
  #pragma unroll
  for (int c = 0; c < 6; c++)
    for (int o = 16; o > 0; o >>= 1) acc[c] += __shfl_down_sync(0xffffffffu, acc[c], o);
  if (!lane){
    size_t base = ((size_t)b*NPTS + i)*CINF;
    #pragma unroll
    for (int c = 0; c < 6; c++) Y[base + c] = acc[c];
  }
}

__global__ void cheb1_out_kernel(const float* __restrict__ x, const float* __restrict__ W1,
                                 const float* __restrict__ b1){
  int f = blockIdx.x*128 + threadIdx.x;
  int row0 = blockIdx.y*16;
  __shared__ float xsr[16][18];
  for (int idx = threadIdx.x; idx < 16*18; idx += 128){
    int r = idx/18, q = idx%18, c = q/3, kk = q%3;
    size_t g = (size_t)(row0 + r)*CINF + c;
    xsr[r][q] = (kk == 0) ? x[g] : ((kk == 1) ? g_x11[g] : g_x21[g]);
  }
  __syncthreads();
  if (f >= F1V) return;
  float w[18];
  #pragma unroll
  for (int q = 0; q < 18; q++) w[q] = W1[q*F1V + f];
  float bb = b1[f];
  for (int r = 0; r < 16; r++){
    float a = bb;
    #pragma unroll
    for (int q = 0; q < 18; q++) a += xsr[r][q]*w[q];
    float v = fmaxf(a, 0.f);
    size_t rowi = (size_t)(row0 + r);
    g_out1[rowi*F1V + f] = v;
    split2(v, &g_out1h[rowi*FPAD + f], &g_out1l[rowi*FPAD + f]);
  }
}

__global__ void regnorm_kernel(const float* __restrict__ outp, const float* __restrict__ xc, int slot){
  int b = blockIdx.y;
  int f = blockIdx.x*128 + threadIdx.x;
  __shared__ float sh[128*6];
  float acc[6] = {0,0,0,0,0,0};
  for (int i0 = 0; i0 < NPTS; i0 += 128){
    __syncthreads();
    for (int idx = threadIdx.x; idx < 128*6; idx += 128)
      sh[idx] = xc[((size_t)b*NPTS + i0)*CINF + idx];
    __syncthreads();
    if (f < F1V){
      for (int ii = 0; ii < 128; ii++){
        float o = outp[((size_t)b*NPTS + i0 + ii)*F1V + f];
        #pragma unroll
        for (int c = 0; c < 6; c++) acc[c] += o*sh[ii*6 + c];
      }
    }
  }
  float s = 0.f;
  #pragma unroll
  for (int c = 0; c < 6; c++) s += acc[c]*acc[c];
  if (f >= F1V) s = 0.f;
  __shared__ float red[128];
  red[threadIdx.x] = s; __syncthreads();
  for (int o = 64; o > 0; o >>= 1){ if (threadIdx.x < o) red[threadIdx.x] += red[threadIdx.x+o]; __syncthreads(); }
  if (!threadIdx.x) atomicAdd(&g_acc[slot], red[0]);
}

__global__ void gathermax_kernel(const int* __restrict__ sccs){
  int br = blockIdx.x;
  int b = br / RR;
  __shared__ int idx[GG];
  for (int t = threadIdx.x; t < GG; t += 256) idx[t] = sccs[(size_t)br*GG + t];
  __syncthreads();
  for (int f = threadIdx.x; f < F1V; f += 256){
    float m = -1e30f;
    for (int g = 0; g < GG; g++)
      m = fmaxf(m, g_out1[((size_t)b*NPTS + idx[g])*F1V + f]);
    g_vR[(size_t)br*F1V + f] = m;
  }
}

__global__ void sqnorm_kernel(){
  size_t row = blockIdx.x;
  const float* p = g_out1 + row*F1V;
  float s = 0.f;
  for (int k = threadIdx.x; k < F1V; k += 256){ float v = p[k]; s += v*v; }
  __shared__ float sh[256];
  sh[threadIdx.x] = s; __syncthreads();
  for (int o = 128; o > 0; o >>= 1){ if (threadIdx.x < o) sh[threadIdx.x] += sh[threadIdx.x+o]; __syncthreads(); }
  if (!threadIdx.x) g_sqn[row] = sh[0];
}

__global__ void colmax_kernel(const float* __restrict__ src, float* __restrict__ dst, int rows){
  int b = blockIdx.y;
  int f = blockIdx.x*256 + threadIdx.x;
  if (f >= F1V) return;
  float m = -1e30f;
  for (int i = 0; i < rows; i++)
    m = fmaxf(m, src[((size_t)b*rows + i)*F1V + f]);
  dst[(size_t)b*F1V + f] = m;
}

__global__ void transpose_hilo_kernel(const float* __restrict__ src,
                                      bf16* __restrict__ dh, bf16* __restrict__ dl){
  int b = blockIdx.z;
  __shared__ float t[32][33];
  int m0 = blockIdx.x*32, n0 = blockIdx.y*32;
  int x = threadIdx.x, y = threadIdx.y;
  for (int i = 0; i < 32; i += 8){
    int n = n0 + x, m = m0 + y + i;
    t[y+i][x] = (n < F1V) ? src[((size_t)b*NPTS + m)*F1V + n] : 0.f;
  }
  __syncthreads();
  for (int i = 0; i < 32; i += 8){
    int n = n0 + y + i, m = m0 + x;
    if (n < F1V){
      float v = t[x][y+i];
      size_t o = ((size_t)b*FPAD + n)*NPTS + m;
      split2(v, &dh[o], &dl[o]);
    }
  }
}

__global__ void w2t_kernel(const float* __restrict__ W2){
  int seg = blockIdx.z;
  __shared__ float t[32][33];
  int k0 = blockIdx.x*32, n0 = blockIdx.y*32;
  int x = threadIdx.x, y = threadIdx.y;
  for (int i = 0; i < 32; i += 8){
    int n = n0 + x, k = k0 + y + i;
    t[y+i][x] = (n < F1V && k < F1V) ? W2[(size_t)(3*k + seg)*F1V + n] : 0.f;
  }
  __syncthreads();
  for (int i = 0; i < 32; i += 8){
    int n = n0 + y + i, k = k0 + x;
    if (n < F1V && k < F1V){
      size_t o = (size_t)seg*FPAD*FPAD + (size_t)n*FPAD + k;
      split2(t[x][y+i], &g_W2Th[o], &g_W2Tl[o]);
    }
  }
}

__global__ void wrt_kernel(const float* __restrict__ Wr){
  __shared__ float t[32][33];
  int q0 = blockIdx.x*32, n0 = blockIdx.y*32;
  int x = threadIdx.x, y = threadIdx.y;
  for (int i = 0; i < 32; i += 8){
    int n = n0 + x, q = q0 + y + i;
    t[y+i][x] = (n < F1V && q < 6000) ? Wr[(size_t)q*F1V + n] : 0.f;
  }
  __syncthreads();
  for (int i = 0; i < 32; i += 8){
    int n = n0 + y + i, q = q0 + x;
    if (n < F1V && q < 6000){
      size_t o = (size_t)n*RK + q;
      split2(t[x][y+i], &g_WrTh[o], &g_WrTl[o]);
    }
  }
}

__global__ void reeb_xs_kernel(const float* __restrict__ Lr){
  int b = blockIdx.y;
  int c = blockIdx.x*128 + threadIdx.x;
  __shared__ float Ls[RR*RR];
  for (int t = threadIdx.x; t < RR*RR; t += 128) Ls[t] = Lr[(size_t)b*RR*RR + t];
  __syncthreads();
  if (c >= F1V) return;
  float v0[RR], v1[RR], v2[RR];
  #pragma unroll
  for (int r = 0; r < RR; r++){
    v0[r] = g_vR[((size_t)b*RR + r)*F1V + c];
    size_t o = (size_t)(b*RR + r)*RK + c*6 + 0;
    split2(v0[r], &g_xsRh[o], &g_xsRl[o]);
  }
  #pragma unroll
  for (int r = 0; r < RR; r++){
    float s = 0.f;
    for (int r2 = 0; r2 < RR; r2++) s += Ls[r*RR + r2]*v0[r2];
    v1[r] = s;
    size_t o = (size_t)(b*RR + r)*RK + c*6 + 1;
    split2(s, &g_xsRh[o], &g_xsRl[o]);
  }
  for (int k = 2; k < 6; k++){
    #pragma unroll
    for (int r = 0; r < RR; r++){
      float s = 0.f;
      for (int r2 = 0; r2 < RR; r2++) s += Ls[r*RR + r2]*v1[r2];
      v2[r] = 2.f*s - v0[r];
      size_t o = (size_t)(b*RR + r)*RK + c*6 + k;
      split2(v2[r], &g_xsRh[o], &g_xsRl[o]);
    }
    #pragma unroll
    for (int r = 0; r < RR; r++){ v0[r] = v1[r]; v1[r] = v2[r]; }
  }
}

__global__ void fc1_kernel(const float* __restrict__ W, const float* __restrict__ bias){
  int b = blockIdx.x;
  __shared__ float ft[2*F1V];
  for (int c = threadIdx.x; c < 2*F1V; c += 512)
    ft[c] = (c < F1V) ? g_gR[(size_t)b*F1V + c] : g_g[(size_t)b*F1V + c - F1V];
  __syncthreads();
  int f = threadIdx.x;
  float a = bias[f];
  for (int c = 0; c < 2*F1V; c++) a += ft[c]*W[(size_t)c*512 + f];
  g_h1[b*512 + f] = fmaxf(a, 0.f);
}

__global__ void fc2_kernel(const float* __restrict__ W, const float* __restrict__ bias){
  int b = blockIdx.x;
  __shared__ float hs[512];
  for (int c = threadIdx.x; c < 512; c += 128) hs[c] = g_h1[b*512 + c];
  __syncthreads();
  int f = threadIdx.x;
  float a = bias[f];
  for (int c = 0; c < 512; c++) a += hs[c]*W[c*128 + f];
  g_h2[b*128 + f] = fmaxf(a, 0.f);
}

__global__ void fc3_kernel(const float* __restrict__ W, const float* __restrict__ bias, float* __restrict__ out){
  int b = blockIdx.x;
  __shared__ float hs[128];
  for (int c = threadIdx.x; c < 128; c += 64) hs[c] = g_h2[b*128 + c];
  __syncthreads();
  int f = threadIdx.x;
  if (f < NCLS){
    float a = bias[f];
    for (int c = 0; c < 128; c++) a += hs[c]*W[c*NCLS + f];
    out[b*NCLS + f] = a;
  }
}

__global__ void wreg_kernel(const float* W1, const float* B1, const float* W2, const float* B2,
                            const float* W3, const float* B3, float* out){
  int layer = blockIdx.x;
  const float* W; const float* Bp; int n, ld;
  if (layer == 0){ W = W1; Bp = B1; n = 2000; ld = 512; }
  else if (layer == 1){ W = W2; Bp = B2; n = 512; ld = 128; }
  else { W = W3; Bp = B3; n = 128; ld = 40; }
  float s = 0.f;
  for (int c = threadIdx.x; c < n; c += 256){ float v = W[(size_t)c*ld]; s += v*v; }
  __shared__ float sh[256];
  sh[threadIdx.x] = s; __syncthreads();
  for (int o = 128; o > 0; o >>= 1){ if (threadIdx.x < o) sh[threadIdx.x] += sh[threadIdx.x+o]; __syncthreads(); }
  if (!threadIdx.x){ out[642 + layer*2] = sh[0]; out[643 + layer*2] = Bp[0]*Bp[0]; }
}

__global__ void finalize_kernel(float* out){
  out[640] = sqrtf(g_acc[0]);
  out[641] = sqrtf(g_acc[1]);
}

// ---------------- host launch ----------------
extern "C" void kernel_launch(void* const* d_in, const int* in_sizes, int n_in,
                              void* d_out, int out_size){
  const float* x    = (const float*)d_in[0];
  const float* Lr   = (const float*)d_in[1];
  const int*   sccs = (const int*)  d_in[2];
  const float* W1   = (const float*)d_in[3];  const float* b1  = (const float*)d_in[4];
  const float* W2   = (const float*)d_in[5];  const float* b2  = (const float*)d_in[6];
  const float* Wr   = (const float*)d_in[7];  const float* br  = (const float*)d_in[8];
  const float* Wfc1 = (const float*)d_in[9];  const float* bfc1= (const float*)d_in[10];
  const float* Wfc2 = (const float*)d_in[11]; const float* bfc2= (const float*)d_in[12];
  const float* Wfc3 = (const float*)d_in[13]; const float* bfc3= (const float*)d_in[14];
  float* out = (float*)d_out;

  static bool init_done = false;
  static cudaStream_t s_side = nullptr;
  static cudaEvent_t ev1 = nullptr, ev2 = nullptr, evT = nullptr, evW = nullptr, evM = nullptr;
  if (!init_done){
    cudaFuncSetAttribute(hgemm_kernel, cudaFuncAttributeMaxDynamicSharedMemorySize, HSM_TOT);
    cudaStreamCreateWithFlags(&s_side, cudaStreamNonBlocking);
    cudaEventCreateWithFlags(&ev1, cudaEventDisableTiming);
    cudaEventCreateWithFlags(&ev2, cudaEventDisableTiming);
    cudaEventCreateWithFlags(&evT, cudaEventDisableTiming);
    cudaEventCreateWithFlags(&evW, cudaEventDisableTiming);
    cudaEventCreateWithFlags(&evM, cudaEventDisableTiming);
    init_done = true;
  }

  float *pL, *pout1, *px12, *pout2, *px11, *px21, *pLx, *psqn, *poutR, *pg, *pgR;
  bf16 *pLh, *pLl, *pout1h, *pout1l, *pout1Th, *pout1Tl;
  bf16 *px12h, *px12l, *px12Th, *px12Tl;
  bf16 *px22h, *px22l, *pW2Th, *pW2Tl;
  bf16 *pxsRh, *pxsRl, *pWrTh, *pWrTl;
  cudaGetSymbolAddress((void**)&pL,      g_L);
  cudaGetSymbolAddress((void**)&pout1,   g_out1);
  cudaGetSymbolAddress((void**)&px12,    g_x12);
  cudaGetSymbolAddress((void**)&pout2,   g_out2);
  cudaGetSymbolAddress((void**)&px11,    g_x11);
  cudaGetSymbolAddress((void**)&px21,    g_x21);
  cudaGetSymbolAddress((void**)&pLx,     g_Lx);
  cudaGetSymbolAddress((void**)&psqn,    g_sqn);
  cudaGetSymbolAddress((void**)&poutR,   g_outR);
  cudaGetSymbolAddress((void**)&pg,      g_g);
  cudaGetSymbolAddress((void**)&pgR,     g_gR);
  cudaGetSymbolAddress((void**)&pLh,     g_Lh);
  cudaGetSymbolAddress((void**)&pLl,     g_Ll);
  cudaGetSymbolAddress((void**)&pout1h,  g_out1h);
  cudaGetSymbolAddress((void**)&pout1l,  g_out1l);
  cudaGetSymbolAddress((void**)&pout1Th, g_out1Th);
  cudaGetSymbolAddress((void**)&pout1Tl, g_out1Tl);
  cudaGetSymbolAddress((void**)&px12h,   g_x12h);
  cudaGetSymbolAddress((void**)&px12l,   g_x12l);
  cudaGetSymbolAddress((void**)&px12Th,  g_x12Th);
  cudaGetSymbolAddress((void**)&px12Tl,  g_x12Tl);
  cudaGetSymbolAddress((void**)&px22h,   g_x22h);
  cudaGetSymbolAddress((void**)&px22l,   g_x22l);
  cudaGetSymbolAddress((void**)&pW2Th,   g_W2Th);
  cudaGetSymbolAddress((void**)&pW2Tl,   g_W2Tl);
  cudaGetSymbolAddress((void**)&pxsRh,   g_xsRh);
  cudaGetSymbolAddress((void**)&pxsRl,   g_xsRl);
  cudaGetSymbolAddress((void**)&pWrTh,   g_WrTh);
  cudaGetSymbolAddress((void**)&pWrTl,   g_WrTl);

  zeroacc_kernel<<<1, 32>>>();
  zero_rs_kernel<<<128, 256>>>();

  // adjacency A1 (symmetric, upper computed + mirrored) with fused rowsum; L1 never materialized
  pairwise6_kernel<<<dim3(NPTS/16, NPTS/16, BATCH), dim3(16,16)>>>(x);

  // cheb conv 1 via implicit laplacian
  gemv6_adj_kernel<<<dim3(NPTS/8, BATCH), 256>>>(x, nullptr, px11, 1.f, 0.f);
  gemv6_adj_kernel<<<dim3(NPTS/8, BATCH), 256>>>(px11, x, px21, 2.f, -1.f);
  cheb1_out_kernel<<<dim3(8, (BATCH*NPTS)/16), 128>>>(x, W1, b1);

  // ---- fork side stream segment A (independent of out2 GEMM chain) ----
  cudaEventRecord(ev1, 0);
  cudaStreamWaitEvent(s_side, ev1, 0);
  transpose_hilo_kernel<<<dim3(NPTS/32, 32, BATCH), dim3(32,8), 0, s_side>>>(pout1, pout1Th, pout1Tl);
  cudaEventRecord(evT, s_side);
  w2t_kernel<<<dim3(32, 32, 3), dim3(32,8), 0, s_side>>>(W2);
  cudaEventRecord(evW, s_side);
  regnorm_kernel<<<dim3(8, BATCH), 128, 0, s_side>>>(pout1, px11, 0);
  gathermax_kernel<<<BATCH*RR, 256, 0, s_side>>>(sccs);
  wrt_kernel<<<dim3(188, 32), dim3(32,8), 0, s_side>>>(Wr);
  reeb_xs_kernel<<<dim3(8, BATCH), 128, 0, s_side>>>(Lr);
  {
    GemmArgs R{};
    R.Ah[0]=pxsRh; R.Al[0]=pxsRl; R.Bh[0]=pWrTh; R.Bl[0]=pWrTl;
    R.Ah[1]=pxsRh; R.Al[1]=pxsRl; R.Bh[1]=pWrTh; R.Bl[1]=pWrTl;
    R.Ah[2]=pxsRh; R.Al[2]=pxsRl; R.Bh[2]=pWrTh; R.Bl[2]=pWrTl;
    R.ldA = RK; R.ldB = RK; R.sA = 0; R.sB = 0;
    R.C = poutR; R.ldC = F1V; R.sC = 0;
    R.Ch = nullptr; R.Cl = nullptr; R.ldH = 0; R.sH = 0;
    R.Z = nullptr; R.ldZ = 0; R.sZ = 0;
    R.bias = br; R.sq = nullptr; R.sSq = 0;
    R.M = BATCH*RR; R.N = F1V; R.nseg = 1; R.kcs = RK/32; R.epi = 4;
    hgemm_kernel<<<dim3(8,3,1), 256, HSM_TOT, s_side>>>(R);
  }
  colmax_kernel<<<dim3(4, BATCH), 256, 0, s_side>>>(poutR, pgR, RR);

  // ---- main chain continues ----
  sqnorm_kernel<<<BATCH*NPTS, 256>>>();
  zero_rs_kernel<<<128, 256>>>();

  GemmArgs A{};
  // adj2 = exp(2*out1@out1^T - sq_m - sq_n), upper triangle + fused rowsum atomics
  for (int s = 0; s < 3; s++){
    A.Ah[s]=pout1h; A.Al[s]=pout1l;
    A.Bh[s]=pout1h; A.Bl[s]=pout1l;
  }
  A.ldA = FPAD; A.ldB = FPAD; A.sA = (long)NPTS*FPAD; A.sB = (long)NPTS*FPAD;
  A.C = pL; A.ldC = NPTS; A.sC = (long)NPTS*NPTS;
  A.Ch = nullptr; A.Cl = nullptr; A.ldH = 0; A.sH = 0;
  A.Z = nullptr; A.ldZ = 0; A.sZ = 0; A.bias = nullptr;
  A.sq = psqn; A.sSq = NPTS;
  A.M = NPTS; A.N = NPTS; A.nseg = 1; A.kcs = FPAD/32; A.epi = 1;
  hgemm_kernel<<<dim3(16,16,BATCH), 256, HSM_TOT>>>(A);

  // fused mirror + laplacian -> bf16 L2 only
  mirror_lap_kernel<<<dim3(NPTS/32, NPTS/32, BATCH), dim3(32,8)>>>();
  cudaEventRecord(evM, 0);

  // ---- side stream segment B (enqueued AFTER evM is recorded -> capture-legal) ----
  cudaStreamWaitEvent(s_side, evM, 0);
  gemv6_bf16_kernel<<<dim3(NPTS/8, BATCH), 256, 0, s_side>>>(x, pLx);
  cudaEventRecord(ev2, s_side);

  // x12 = L2 @ out1 (needs out1T from side stream)
  cudaStreamWaitEvent(0, evT, 0);
  for (int s = 0; s < 3; s++){
    A.Ah[s]=pLh; A.Al[s]=pLl;
    A.Bh[s]=pout1Th; A.Bl[s]=pout1Tl;
  }
  A.ldA = NPTS; A.ldB = NPTS; A.sA = (long)NPTS*NPTS; A.sB = (long)FPAD*NPTS;
  A.C = px12; A.ldC = F1V; A.sC = (long)NPTS*F1V;
  A.Ch = px12h; A.Cl = px12l; A.ldH = FPAD; A.sH = (long)NPTS*FPAD;
  A.Z = nullptr; A.sq = nullptr; A.bias = nullptr;
  A.M = NPTS; A.N = F1V; A.nseg = 1; A.kcs = NPTS/32; A.epi = 2;
  hgemm_kernel<<<dim3(8,16,BATCH), 256, HSM_TOT>>>(A);

  transpose_hilo_kernel<<<dim3(NPTS/32, 32, BATCH), dim3(32,8)>>>(px12, px12Th, px12Tl);

  // x22 = 2*L2@x12 - out1 (split2 only)
  for (int s = 0; s < 3; s++){
    A.Ah[s]=pLh; A.Al[s]=pLl;
    A.Bh[s]=px12Th; A.Bl[s]=px12Tl;
  }
  A.C = nullptr; A.ldC = 0; A.sC = 0;
  A.Ch = px22h; A.Cl = px22l; A.ldH = FPAD; A.sH = (long)NPTS*FPAD;
  A.Z = pout1; A.ldZ = F1V; A.sZ = (long)NPTS*F1V;
  A.M = NPTS; A.N = F1V; A.nseg = 1; A.kcs = NPTS/32; A.epi = 3;
  hgemm_kernel<<<dim3(8,16,BATCH), 256, HSM_TOT>>>(A);

  // out2 = relu(out1@W2a + x12@W2b + x22@W2c + b2), M flattened (needs W2T from side)
  cudaStreamWaitEvent(0, evW, 0);
  A.Ah[0]=pout1h; A.Al[0]=pout1l;
  A.Ah[1]=px12h;  A.Al[1]=px12l;
  A.Ah[2]=px22h;  A.Al[2]=px22l;
  A.Bh[0]=pW2Th;                       A.Bl[0]=pW2Tl;
  A.Bh[1]=pW2Th + (size_t)FPAD*FPAD;   A.Bl[1]=pW2Tl + (size_t)FPAD*FPAD;
  A.Bh[2]=pW2Th + (size_t)2*FPAD*FPAD; A.Bl[2]=pW2Tl + (size_t)2*FPAD*FPAD;
  A.ldA = FPAD; A.ldB = FPAD; A.sA = 0; A.sB = 0;
  A.C = pout2; A.ldC = F1V; A.sC = 0;
  A.Ch = nullptr; A.Cl = nullptr; A.Z = nullptr;
  A.bias = b2;
  A.M = BATCH*NPTS; A.N = F1V; A.nseg = 3; A.kcs = FPAD/32; A.epi = 4;
  hgemm_kernel<<<dim3(8,256,1), 256, HSM_TOT>>>(A);

  colmax_kernel<<<dim3(4, BATCH), 256>>>(pout2, pg, NPTS);

  // ---- join side stream (pLx, gR ready) ----
  cudaStreamWaitEvent(0, ev2, 0);
  regnorm_kernel<<<dim3(8, BATCH), 128>>>(pout2, pLx, 1);

  // FC head
  fc1_kernel<<<BATCH, 512>>>(Wfc1, bfc1);
  fc2_kernel<<<BATCH, 128>>>(Wfc2, bfc2);
  fc3_kernel<<<BATCH, 64>>>(Wfc3, bfc3, out);

  // regs
  wreg_kernel<<<3, 256>>>(Wfc1, bfc1, Wfc2, bfc2, Wfc3, bfc3, out);
  finalize_kernel<<<1, 1>>>(out);
}

// round 16
// speedup vs baseline: 1.2186x; 1.0103x over previous
#include <cuda_runtime.h>
#include <cuda_bf16.h>
#include <math.h>
#include <stdint.h>

#define BATCH 16
#define NPTS 2048
#define CINF 6
#define RR 20
#define GG 128
#define F1V 1000
#define NCLS 40
#define FPAD 1024
#define RK 6016
#define RM 384

typedef __nv_bfloat16 bf16;

// ---------------- scratch (device globals; zero-initialized, no allocations) ----------------
__device__ float g_L[(size_t)BATCH*NPTS*NPTS];
__device__ float g_out1[(size_t)BATCH*NPTS*F1V];
__device__ float g_x12[(size_t)BATCH*NPTS*F1V];
__device__ float g_out2[(size_t)BATCH*NPTS*F1V];
__device__ bf16  g_Lh[(size_t)BATCH*NPTS*NPTS];
__device__ bf16  g_Ll[(size_t)BATCH*NPTS*NPTS];
__device__ bf16  g_out1h[(size_t)BATCH*NPTS*FPAD];
__device__ bf16  g_out1l[(size_t)BATCH*NPTS*FPAD];
__device__ bf16  g_out1Th[(size_t)BATCH*FPAD*NPTS];
__device__ bf16  g_out1Tl[(size_t)BATCH*FPAD*NPTS];
__device__ bf16  g_x12h[(size_t)BATCH*NPTS*FPAD];
__device__ bf16  g_x12l[(size_t)BATCH*NPTS*FPAD];
__device__ bf16  g_x12Th[(size_t)BATCH*FPAD*NPTS];
__device__ bf16  g_x12Tl[(size_t)BATCH*FPAD*NPTS];
__device__ bf16  g_x22h[(size_t)BATCH*NPTS*FPAD];
__device__ bf16  g_x22l[(size_t)BATCH*NPTS*FPAD];
__device__ bf16  g_W2Th[3*FPAD*FPAD];
__device__ bf16  g_W2Tl[3*FPAD*FPAD];
__device__ bf16  g_xsRh[(size_t)RM*RK];
__device__ bf16  g_xsRl[(size_t)RM*RK];
__device__ bf16  g_WrTh[(size_t)FPAD*RK];
__device__ bf16  g_WrTl[(size_t)FPAD*RK];
__device__ float g_x11[BATCH*NPTS*CINF];
__device__ float g_x21[BATCH*NPTS*CINF];
__device__ float g_Lx[BATCH*NPTS*CINF];
__device__ float g_rowsum[BATCH*NPTS];
__device__ float g_sqn[BATCH*NPTS];
__device__ float g_vR[BATCH*RR*F1V];
__device__ float g_outR[BATCH*RR*F1V];
__device__ float g_g[BATCH*F1V];
__device__ float g_gR[BATCH*F1V];
__device__ float g_h1[BATCH*512];
__device__ float g_h2[BATCH*128];
__device__ float g_acc[8];

// ---------------- helpers ----------------
__device__ __forceinline__ uint32_t smem_u32(const void* p){
  uint32_t a;
  asm("{ .reg .u64 t; cvta.to.shared.u64 t, %1; cvt.u32.u64 %0, t; }" : "=r"(a) : "l"(p));
  return a;
}
__device__ __forceinline__ void cp16(uint32_t s, const void* g){
  asm volatile("cp.async.cg.shared.global [%0], [%1], 16;" :: "r"(s), "l"(g));
}
__device__ __forceinline__ void ldsm4(uint32_t& r0, uint32_t& r1, uint32_t& r2, uint32_t& r3, uint32_t a){
  asm volatile("ldmatrix.sync.aligned.m8n8.x4.shared.b16 {%0,%1,%2,%3}, [%4];"
    : "=r"(r0), "=r"(r1), "=r"(r2), "=r"(r3) : "r"(a));
}
__device__ __forceinline__ void mma16816(float* d, const uint32_t* a, const uint32_t* b){
  asm volatile("mma.sync.aligned.m16n8k16.row.col.f32.bf16.bf16.f32 "
    "{%0,%1,%2,%3}, {%4,%5,%6,%7}, {%8,%9}, {%0,%1,%2,%3};"
    : "+f"(d[0]), "+f"(d[1]), "+f"(d[2]), "+f"(d[3])
    : "r"(a[0]), "r"(a[1]), "r"(a[2]), "r"(a[3]), "r"(b[0]), "r"(b[1]));
}
__device__ __forceinline__ void split2(float v, bf16* ph, bf16* pl){
  bf16 h = __float2bfloat16(v);
  *ph = h;
  *pl = __float2bfloat16(v - __bfloat162float(h));
}

// ---------------- HMMA GEMM: C[M,N], CTA tile 128x128, BK=32, 2-stage, 2 CTAs/SM ----------------
// epi: 0 plain C; 1 exp(2a - sq[m] - sq[n]) upper-only + rowsum atomics; 2 C + split2; 3 split2 of (2a - Z); 4 relu(a + bias[n]) [+ colmax atomics]
struct GemmArgs {
  const bf16 *Ah[3], *Al[3], *Bh[3], *Bl[3];
  long ldA, ldB, sA, sB;
  float* C; long ldC, sC;
  bf16 *Ch, *Cl; long ldH, sH;
  const float* Z; long ldZ, sZ;
  const float* bias;
  const float* sq; long sSq;
  unsigned* gmax;
  int M, N, nseg, kcs, epi;
};

#define STAGE_B 40960          // 4 parts * 128 rows * 80 bytes
#define PART_B  10240
#define HSM_TOT (2*STAGE_B)    // 81920 -> 2 CTAs per SM

__global__ __launch_bounds__(256, 2) void hgemm_kernel(GemmArgs P){
  // symmetric pairwise: skip lower-triangle blocks
  if (P.epi == 1 && blockIdx.x < blockIdx.y) return;

  extern __shared__ char sm[];
  uint32_t sb = smem_u32(sm);
  int tid = threadIdx.x;
  int w = tid >> 5, l = tid & 31;
  int wm = w & 3;
  int wn = w >> 2;
  int bz = blockIdx.z;
  int m0 = blockIdx.y * 128, n0 = blockIdx.x * 128;
  const int nk = P.nseg * P.kcs;

  float acc[2][8][4];
  #pragma unroll
  for (int t = 0; t < 2; t++)
    #pragma unroll
    for (int j = 0; j < 8; j++)
      #pragma unroll
      for (int r = 0; r < 4; r++) acc[t][j][r] = 0.f;

  auto stage_load = [&](int kt){
    int seg = kt / P.kcs, kc = kt % P.kcs;
    const bf16* pa[2] = {
      P.Ah[seg] + (size_t)bz*P.sA + (size_t)m0*P.ldA + (size_t)kc*32,
      P.Al[seg] + (size_t)bz*P.sA + (size_t)m0*P.ldA + (size_t)kc*32 };
    const bf16* pb[2] = {
      P.Bh[seg] + (size_t)bz*P.sB + (size_t)n0*P.ldB + (size_t)kc*32,
      P.Bl[seg] + (size_t)bz*P.sB + (size_t)n0*P.ldB + (size_t)kc*32 };
    uint32_t st = sb + (uint32_t)(kt & 1) * STAGE_B;
    #pragma unroll
    for (int i = 0; i < 8; i++){
      int part = i >> 1;
      int cid = tid + (i & 1)*256;
      int row = cid >> 2, col = cid & 3;
      const bf16* gp = (part < 2) ? pa[part] : pb[part - 2];
      long ld = (part < 2) ? P.ldA : P.ldB;
      cp16(st + part*PART_B + row*80 + col*16, gp + (size_t)row*ld + col*8);
    }
    asm volatile("cp.async.commit_group;" ::: "memory");
  };

  stage_load(0);

  for (int kt = 0; kt < nk; kt++){
    if (kt + 1 < nk){
      stage_load(kt + 1);
      asm volatile("cp.async.wait_group 1;" ::: "memory");
    } else {
      asm volatile("cp.async.wait_group 0;" ::: "memory");
    }
    __syncthreads();

    uint32_t st = sb + (uint32_t)(kt & 1) * STAGE_B;
    #pragma unroll
    for (int step = 0; step < 2; step++){
      uint32_t ah[2][4], al[2][4];
      #pragma unroll
      for (int t = 0; t < 2; t++){
        int row = wm*32 + t*16 + (l & 15);
        uint32_t koff = (uint32_t)(step*32 + ((l >> 4) & 1)*16);
        uint32_t addr = st + row*80 + koff;
        ldsm4(ah[t][0], ah[t][1], ah[t][2], ah[t][3], addr);
        ldsm4(al[t][0], al[t][1], al[t][2], al[t][3], addr + PART_B);
      }
      uint32_t bh[8][2], bl[8][2];
      #pragma unroll
      for (int j = 0; j < 4; j++){
        int n = wn*64 + j*16 + (((l >> 4) & 1) << 3) + (l & 7);
        uint32_t koff = (uint32_t)(step*32 + ((l >> 3) & 1)*16);
        uint32_t addr = st + 2*PART_B + n*80 + koff;
        ldsm4(bh[2*j][0], bh[2*j][1], bh[2*j+1][0], bh[2*j+1][1], addr);
        ldsm4(bl[2*j][0], bl[2*j][1], bl[2*j+1][0], bl[2*j+1][1], addr + PART_B);
      }
      #pragma unroll
      for (int t = 0; t < 2; t++)
        #pragma unroll
        for (int j = 0; j < 8; j++){
          mma16816(acc[t][j], ah[t], bh[j]);
          mma16816(acc[t][j], ah[t], bl[j]);
          mma16816(acc[t][j], al[t], bh[j]);
        }
    }
    __syncthreads();
  }

  // ---- epilogue ----
  int lm = l >> 2, ln = (l & 3)*2;

  if (P.epi == 1){
    const float* sqb = P.sq + (size_t)bz*P.sSq;
    float* C = P.C + (size_t)bz*P.sC;
    float* rs = g_rowsum + (size_t)bz*NPTS;
    bool dup = (blockIdx.x > blockIdx.y);
    float rowm[4] = {0.f, 0.f, 0.f, 0.f};
    float rown[16];
    #pragma unroll
    for (int q = 0; q < 16; q++) rown[q] = 0.f;
    #pragma unroll
    for (int t = 0; t < 2; t++){
      #pragma unroll
      for (int j = 0; j < 8; j++){
        #pragma unroll
        for (int r = 0; r < 4; r++){
          int m = m0 + wm*32 + t*16 + lm + (r >> 1)*8;
          int n = n0 + wn*64 + j*8 + ln + (r & 1);
          float e = expf(2.f*acc[t][j][r] - sqb[m] - sqb[n]);
          C[(size_t)m*P.ldC + n] = e;
          rowm[t*2 + (r >> 1)] += e;
          rown[j*2 + (r & 1)] += e;
        }
      }
    }
    #pragma unroll
    for (int q = 0; q < 4; q++){
      int m = m0 + wm*32 + (q >> 1)*16 + lm + (q & 1)*8;
      atomicAdd(&rs[m], rowm[q]);
    }
    if (dup){
      #pragma unroll
      for (int q = 0; q < 16; q++){
        int n = n0 + wn*64 + (q >> 1)*8 + ln + (q & 1);
        atomicAdd(&rs[n], rown[q]);
      }
    }
    return;
  }

  float* C = P.C ? (P.C + (size_t)bz*P.sC) : nullptr;
  bf16* Ch = P.Ch ? (P.Ch + (size_t)bz*P.sH) : nullptr;
  bf16* Cl = P.Cl ? (P.Cl + (size_t)bz*P.sH) : nullptr;
  const float* Z = P.Z ? (P.Z + (size_t)bz*P.sZ) : nullptr;

  float cmax[16];
  #pragma unroll
  for (int q = 0; q < 16; q++) cmax[q] = 0.f;

  #pragma unroll
  for (int t = 0; t < 2; t++){
    #pragma unroll
    for (int j = 0; j < 8; j++){
      #pragma unroll
      for (int r = 0; r < 4; r++){
        int m = m0 + wm*32 + t*16 + lm + (r >> 1)*8;
        int n = n0 + wn*64 + j*8 + ln + (r & 1);
        if (m < P.M && n < P.N){
          float a = acc[t][j][r];
          if (P.epi == 0){
            C[(size_t)m*P.ldC + n] = a;
          } else if (P.epi == 2){
            C[(size_t)m*P.ldC + n] = a;
            split2(a, Ch + (size_t)m*P.ldH + n, Cl + (size_t)m*P.ldH + n);
          } else if (P.epi == 3){
            float v = 2.f*a - Z[(size_t)m*P.ldZ + n];
            split2(v, Ch + (size_t)m*P.ldH + n, Cl + (size_t)m*P.ldH + n);
          } else {
            float v = fmaxf(a + P.bias[n], 0.f);
            C[(size_t)m*P.ldC + n] = v;
            cmax[j*2 + (r & 1)] = fmaxf(cmax[j*2 + (r & 1)], v);
          }
        }
      }
    }
  }

  // fused column max (out2 only): values are >=0 so uint atomicMax preserves float order
  if (P.epi == 4 && P.gmax){
    int b = m0 >> 11;                 // flattened M: 128-row blocks never straddle a batch
    #pragma unroll
    for (int q = 0; q < 16; q++){
      int n = n0 + wn*64 + (q >> 1)*8 + ln + (q & 1);
      if (n < P.N)
        atomicMax(&P.gmax[(size_t)b*F1V + n], __float_as_uint(cmax[q]));
    }
  }
}

// fused mirror + laplacian + bf16 split for L2 (upper adj tiles -> bf16 L in both triangles)
__global__ void mirror_lap_kernel(){
  int b = blockIdx.z;
  int tx = blockIdx.x, ty = blockIdx.y;
  if (tx < ty) return;
  __shared__ float t[32][33];
  __shared__ float rim[32], rin[32];
  int x = threadIdx.x, y = threadIdx.y;
  size_t base = (size_t)b*NPTS*NPTS;
  for (int i = 0; i < 32; i += 8){
    int m = ty*32 + y + i, n = tx*32 + x;
    t[y+i][x] = g_L[base + (size_t)m*NPTS + n];
  }
  if (y == 0) rim[x] = rsqrtf(g_rowsum[b*NPTS + ty*32 + x]);
  if (y == 1) rin[x] = rsqrtf(g_rowsum[b*NPTS + tx*32 + x]);
  __syncthreads();
  for (int i = 0; i < 32; i += 8){
    int m = ty*32 + y + i, n = tx*32 + x;
    float Lv = ((m == n) ? 1.f : 0.f) - rim[y+i]*t[y+i][x]*rin[x];
    t[y+i][x] = Lv;
    size_t o = base + (size_t)m*NPTS + n;
    split2(Lv, &g_Lh[o], &g_Ll[o]);
  }
  if (tx > ty){
    __syncthreads();
    for (int i = 0; i < 32; i += 8){
      int m = tx*32 + y + i, n = ty*32 + x;
      float Lv = t[x][y+i];
      size_t o = base + (size_t)m*NPTS + n;
      split2(Lv, &g_Lh[o], &g_Ll[o]);
    }
  }
}

// ---------------- small kernels ----------------
__global__ void zeroacc_kernel(){ if (threadIdx.x < 8) g_acc[threadIdx.x] = 0.f; }

__global__ void zero_rs_kernel(int withSq){
  int i = blockIdx.x*256 + threadIdx.x;
  if (i < BATCH*NPTS){
    g_rowsum[i] = 0.f;
    if (withSq) g_sqn[i] = 0.f;
  }
}

__global__ void zero_g_kernel(){
  int i = blockIdx.x*256 + threadIdx.x;
  if (i < BATCH*F1V) ((unsigned*)g_g)[i] = 0u;
}

__global__ void pairwise6_kernel(const float* __restrict__ x){
  if (blockIdx.x < blockIdx.y) return;
  int b = blockIdx.z;
  int i0 = blockIdx.y*16, j0 = blockIdx.x*16;
  __shared__ float xi[16][6], xj[16][6];
  __shared__ float te[16][17];
  int tid = threadIdx.y*16 + threadIdx.x;
  if (tid < 96){
    int r = tid/6, c = tid%6;
    xi[r][c] = x[((size_t)b*NPTS + i0 + r)*CINF + c];
    xj[r][c] = x[((size_t)b*NPTS + j0 + r)*CINF + c];
  }
  __syncthreads();
  int i = threadIdx.y, j = threadIdx.x;
  float d = 0.f;
  #pragma unroll
  for (int c = 0; c < 6; c++){ float t = xi[i][c]-xj[j][c]; d += t*t; }
  float e = expf(-d);
  g_L[((size_t)b*NPTS + i0+i)*NPTS + j0+j] = e;
  te[i][j] = e;
  float* rs = g_rowsum + (size_t)b*NPTS;
  float s = e;
  #pragma unroll
  for (int o = 8; o > 0; o >>= 1) s += __shfl_down_sync(0xffffffffu, s, o, 16);
  if (j == 0) atomicAdd(&rs[i0 + i], s);
  if (blockIdx.x > blockIdx.y){
    __syncthreads();
    g_L[((size_t)b*NPTS + j0+i)*NPTS + i0+j] = te[j][i];
    if (tid < 16){
      float cs = 0.f;
      #pragma unroll
      for (int k = 0; k < 16; k++) cs += te[k][tid];
      atomicAdd(&rs[j0 + tid], cs);
    }
  }
}

// Y = s * (L1 @ X) + t*Z implicitly from adjacency+rowsum; 512 threads, 16 rows/block
__global__ void gemv6_adj_kernel(const float* __restrict__ X, const float* __restrict__ Z,
                                 float* __restrict__ Y, float s, float t){
  int b = blockIdx.y;
  __shared__ float xs[NPTS*CINF];
  const float* rs = g_rowsum + (size_t)b*NPTS;
  for (int idx = threadIdx.x; idx < NPTS*CINF; idx += 512){
    int row = idx / CINF;
    xs[idx] = X[(size_t)b*NPTS*CINF + idx] * rsqrtf(rs[row]);
  }
  __syncthreads();
  int warp = threadIdx.x >> 5, lane = threadIdx.x & 31;
  int i = blockIdx.x*16 + warp;
  const float* Arow = g_L + ((size_t)b*NPTS + i)*NPTS;
  float acc[6] = {0,0,0,0,0,0};
  for (int k = lane; k < NPTS; k += 32){
    float a = Arow[k];
    #pragma unroll
    for (int c = 0; c < 6; c++) acc[c] += a * xs[k*6 + c];
  }
  #pragma unroll
  for (int c = 0; c < 6; c++)
    for (int o = 16; o > 0; o >>= 1) acc[c] += __shfl_down_sync(0xffffffffu, acc[c], o);
  if (!lane){
    float rsi = rsqrtf(rs[i]);
    size_t base = ((size_t)b*NPTS + i)*CINF;
    #pragma unroll
    for (int c = 0; c < 6; c++){
      float v = s*(X[base + c] - rsi*acc[c]);
      if (Z) v += t*Z[base + c];
      Y[base + c] = v;
    }
  }
}

__global__ void gemv6_bf16_kernel(const float* __restrict__ X, float* __restrict__ Y){
  int b = blockIdx.y;
  __shared__ float xs[NPTS*CINF];
  for (int idx = threadIdx.x; idx < NPTS*CINF; idx += 256)
    xs[idx] = X[(size_t)b*NPTS*CINF + idx];
  __syncthreads();
  int warp = threadIdx.x >> 5, lane = threadIdx.x & 31;
  int i = blockIdx.x*8 + warp;
  const __nv_bfloat162* Lh2 = (const __nv_bfloat162*)(g_Lh + ((size_t)b*NPTS + i)*NPTS);
  const __nv_bfloat162* Ll2 = (const __nv_bfloat162*)(g_Ll + ((size_t)b*NPTS + i)*NPTS);
  float acc[6] = {0,0,0,0,0,0};
  for (int k = lane; k < NPTS/2; k += 32){
    float2 h = __bfloat1622float2(Lh2[k]);
    float2 lo = __bfloat1622float2(Ll2[k]);
    float a0 = h.x + lo.x, a1 = h.y + lo.y;
    #pragma unroll
    for (int c = 0; c < 6; c++)
      acc[c] += a0*xs[(2*k)*6 + c] + a1*xs[(2*k+1)*6 + c];
  }
  #pragma unroll
  for (int c = 0; c < 6; c++)
    for (int o = 16; o > 0; o >>= 1) acc[c] += __shfl_down_sync(0xffffffffu, acc[c], o);
  if (!lane){
    size_t base = ((size_t)b*NPTS + i)*CINF;
    #pragma unroll
    for (int c = 0; c < 6; c++) Y[base + c] = acc[c];
  }
}

// cheb1 + fused sqnorm (g_sqn must be pre-zeroed)
__global__ void cheb1_out_kernel(const float* __restrict__ x, const float* __restrict__ W1,
                                 const float* __restrict__ b1){
  int f = blockIdx.x*128 + threadIdx.x;
  int row0 = blockIdx.y*16;
  __shared__ float xsr[16][18];
  for (int idx = threadIdx.x; idx < 16*18; idx += 128){
    int r = idx/18, q = idx%18, c = q/3, kk = q%3;
    size_t g = (size_t)(row0 + r)*CINF + c;
    xsr[r][q] = (kk == 0) ? x[g] : ((kk == 1) ? g_x11[g] : g_x21[g]);
  }
  __syncthreads();
  bool ok = (f < F1V);
  int lane = threadIdx.x & 31;
  float w[18];
  float bb = 0.f;
  #pragma unroll
  for (int q = 0; q < 18; q++) w[q] = ok ? W1[q*F1V + f] : 0.f;
  if (ok) bb = b1[f];
  for (int r = 0; r < 16; r++){
    float a = bb;
    #pragma unroll
    for (int q = 0; q < 18; q++) a += xsr[r][q]*w[q];
    float v = ok ? fmaxf(a, 0.f) : 0.f;
    size_t rowi = (size_t)(row0 + r);
    if (ok){
      g_out1[rowi*F1V + f] = v;
      split2(v, &g_out1h[rowi*FPAD + f], &g_out1l[rowi*FPAD + f]);
    }
    float sq = v*v;
    #pragma unroll
    for (int o = 16; o > 0; o >>= 1) sq += __shfl_down_sync(0xffffffffu, sq, o);
    if (!lane) atomicAdd(&g_sqn[rowi], sq);
  }
}

__global__ void regnorm_kernel(const float* __restrict__ outp, const float* __restrict__ xc, int slot){
  int b = blockIdx.y;
  int f = blockIdx.x*128 + threadIdx.x;
  __shared__ float sh[128*6];
  float acc[6] = {0,0,0,0,0,0};
  for (int i0 = 0; i0 < NPTS; i0 += 128){
    __syncthreads();
    for (int idx = threadIdx.x; idx < 128*6; idx += 128)
      sh[idx] = xc[((size_t)b*NPTS + i0)*CINF + idx];
    __syncthreads();
    if (f < F1V){
      for (int ii = 0; ii < 128; ii++){
        float o = outp[((size_t)b*NPTS + i0 + ii)*F1V + f];
        #pragma unroll
        for (int c = 0; c < 6; c++) acc[c] += o*sh[ii*6 + c];
      }
    }
  }
  float s = 0.f;
  #pragma unroll
  for (int c = 0; c < 6; c++) s += acc[c]*acc[c];
  if (f >= F1V) s = 0.f;
  __shared__ float red[128];
  red[threadIdx.x] = s; __syncthreads();
  for (int o = 64; o > 0; o >>= 1){ if (threadIdx.x < o) red[threadIdx.x] += red[threadIdx.x+o]; __syncthreads(); }
  if (!threadIdx.x) atomicAdd(&g_acc[slot], red[0]);
}

__global__ void gathermax_kernel(const int* __restrict__ sccs){
  int br = blockIdx.x;
  int b = br / RR;
  __shared__ int idx[GG];
  for (int t = threadIdx.x; t < GG; t += 256) idx[t] = sccs[(size_t)br*GG + t];
  __syncthreads();
  for (int f = threadIdx.x; f < F1V; f += 256){
    float m = -1e30f;
    for (int g = 0; g < GG; g++)
      m = fmaxf(m, g_out1[((size_t)b*NPTS + idx[g])*F1V + f]);
    g_vR[(size_t)br*F1V + f] = m;
  }
}

__global__ void colmax_kernel(const float* __restrict__ src, float* __restrict__ dst, int rows){
  int b = blockIdx.y;
  int f = blockIdx.x*256 + threadIdx.x;
  if (f >= F1V) return;
  float m = -1e30f;
  for (int i = 0; i < rows; i++)
    m = fmaxf(m, src[((size_t)b*rows + i)*F1V + f]);
  dst[(size_t)b*F1V + f] = m;
}

__global__ void transpose_hilo_kernel(const float* __restrict__ src,
                                      bf16* __restrict__ dh, bf16* __restrict__ dl){
  int b = blockIdx.z;
  __shared__ float t[32][33];
  int m0 = blockIdx.x*32, n0 = blockIdx.y*32;
  int x = threadIdx.x, y = threadIdx.y;
  for (int i = 0; i < 32; i += 8){
    int n = n0 + x, m = m0 + y + i;
    t[y+i][x] = (n < F1V) ? src[((size_t)b*NPTS + m)*F1V + n] : 0.f;
  }
  __syncthreads();
  for (int i = 0; i < 32; i += 8){
    int n = n0 + y + i, m = m0 + x;
    if (n < F1V){
      float v = t[x][y+i];
      size_t o = ((size_t)b*FPAD + n)*NPTS + m;
      split2(v, &dh[o], &dl[o]);
    }
  }
}

__global__ void w2t_kernel(const float* __restrict__ W2){
  int seg = blockIdx.z;
  __shared__ float t[32][33];
  int k0 = blockIdx.x*32, n0 = blockIdx.y*32;
  int x = threadIdx.x, y = threadIdx.y;
  for (int i = 0; i < 32; i += 8){
    int n = n0 + x, k = k0 + y + i;
    t[y+i][x] = (n < F1V && k < F1V) ? W2[(size_t)(3*k + seg)*F1V + n] : 0.f;
  }
  __syncthreads();
  for (int i = 0; i < 32; i += 8){
    int n = n0 + y + i, k = k0 + x;
    if (n < F1V && k < F1V){
      size_t o = (size_t)seg*FPAD*FPAD + (size_t)n*FPAD + k;
      split2(t[x][y+i], &g_W2Th[o], &g_W2Tl[o]);
    }
  }
}

__global__ void wrt_kernel(const float* __restrict__ Wr){
  __shared__ float t[32][33];
  int q0 = blockIdx.x*32, n0 = blockIdx.y*32;
  int x = threadIdx.x, y = threadIdx.y;
  for (int i = 0; i < 32; i += 8){
    int n = n0 + x, q = q0 + y + i;
    t[y+i][x] = (n < F1V && q < 6000) ? Wr[(size_t)q*F1V + n] : 0.f;
  }
  __syncthreads();
  for (int i = 0; i < 32; i += 8){
    int n = n0 + y + i, q = q0 + x;
    if (n < F1V && q < 6000){
      size_t o = (size_t)n*RK + q;
      split2(t[x][y+i], &g_WrTh[o], &g_WrTl[o]);
    }
  }
}

__global__ void reeb_xs_kernel(const float* __restrict__ Lr){
  int b = blockIdx.y;
  int c = blockIdx.x*128 + threadIdx.x;
  __shared__ float Ls[RR*RR];
  for (int t = threadIdx.x; t < RR*RR; t += 128) Ls[t] = Lr[(size_t)b*RR*RR + t];
  __syncthreads();
  if (c >= F1V) return;
  float v0[RR], v1[RR], v2[RR];
  #pragma unroll
  for (int r = 0; r < RR; r++){
    v0[r] = g_vR[((size_t)b*RR + r)*F1V + c];
    size_t o = (size_t)(b*RR + r)*RK + c*6 + 0;
    split2(v0[r], &g_xsRh[o], &g_xsRl[o]);
  }
  #pragma unroll
  for (int r = 0; r < RR; r++){
    float s = 0.f;
    for (int r2 = 0; r2 < RR; r2++) s += Ls[r*RR + r2]*v0[r2];
    v1[r] = s;
    size_t o = (size_t)(b*RR + r)*RK + c*6 + 1;
    split2(s, &g_xsRh[o], &g_xsRl[o]);
  }
  for (int k = 2; k < 6; k++){
    #pragma unroll
    for (int r = 0; r < RR; r++){
      float s = 0.f;
      for (int r2 = 0; r2 < RR; r2++) s += Ls[r*RR + r2]*v1[r2];
      v2[r] = 2.f*s - v0[r];
      size_t o = (size_t)(b*RR + r)*RK + c*6 + k;
      split2(v2[r], &g_xsRh[o], &g_xsRl[o]);
    }
    #pragma unroll
    for (int r = 0; r < RR; r++){ v0[r] = v1[r]; v1[r] = v2[r]; }
  }
}

__global__ void fc1_kernel(const float* __restrict__ W, const float* __restrict__ bias){
  int b = blockIdx.x;
  __shared__ float ft[2*F1V];
  for (int c = threadIdx.x; c < 2*F1V; c += 512)
    ft[c] = (c < F1V) ? g_gR[(size_t)b*F1V + c] : g_g[(size_t)b*F1V + c - F1V];
  __syncthreads();
  int f = threadIdx.x;
  float a = bias[f];
  for (int c = 0; c < 2*F1V; c++) a += ft[c]*W[(size_t)c*512 + f];
  g_h1[b*512 + f] = fmaxf(a, 0.f);
}

__global__ void fc2_kernel(const float* __restrict__ W, const float* __restrict__ bias){
  int b = blockIdx.x;
  __shared__ float hs[512];
  for (int c = threadIdx.x; c < 512; c += 128) hs[c] = g_h1[b*512 + c];
  __syncthreads();
  int f = threadIdx.x;
  float a = bias[f];
  for (int c = 0; c < 512; c++) a += hs[c]*W[c*128 + f];
  g_h2[b*128 + f] = fmaxf(a, 0.f);
}

__global__ void fc3_kernel(const float* __restrict__ W, const float* __restrict__ bias, float* __restrict__ out){
  int b = blockIdx.x;
  __shared__ float hs[128];
  for (int c = threadIdx.x; c < 128; c += 64) hs[c] = g_h2[b*128 + c];
  __syncthreads();
  int f = threadIdx.x;
  if (f < NCLS){
    float a = bias[f];
    for (int c = 0; c < 128; c++) a += hs[c]*W[c*NCLS + f];
    out[b*NCLS + f] = a;
  }
}

__global__ void wreg_kernel(const float* W1, const float* B1, const float* W2, const float* B2,
                            const float* W3, const float* B3, float* out){
  int layer = blockIdx.x;
  const float* W; const float* Bp; int n, ld;
  if (layer == 0){ W = W1; Bp = B1; n = 2000; ld = 512; }
  else if (layer == 1){ W = W2; Bp = B2; n = 512; ld = 128; }
  else { W = W3; Bp = B3; n = 128; ld = 40; }
  float s = 0.f;
  for (int c = threadIdx.x; c < n; c += 256){ float v = W[(size_t)c*ld]; s += v*v; }
  __shared__ float sh[256];
  sh[threadIdx.x] = s; __syncthreads();
  for (int o = 128; o > 0; o >>= 1){ if (threadIdx.x < o) sh[threadIdx.x] += sh[threadIdx.x+o]; __syncthreads(); }
  if (!threadIdx.x){ out[642 + layer*2] = sh[0]; out[643 + layer*2] = Bp[0]*Bp[0]; }
}

__global__ void finalize_kernel(float* out){
  out[640] = sqrtf(g_acc[0]);
  out[641] = sqrtf(g_acc[1]);
}

// ---------------- host launch ----------------
extern "C" void kernel_launch(void* const* d_in, const int* in_sizes, int n_in,
                              void* d_out, int out_size){
  const float* x    = (const float*)d_in[0];
  const float* Lr   = (const float*)d_in[1];
  const int*   sccs = (const int*)  d_in[2];
  const float* W1   = (const float*)d_in[3];  const float* b1  = (const float*)d_in[4];
  const float* W2   = (const float*)d_in[5];  const float* b2  = (const float*)d_in[6];
  const float* Wr   = (const float*)d_in[7];  const float* br  = (const float*)d_in[8];
  const float* Wfc1 = (const float*)d_in[9];  const float* bfc1= (const float*)d_in[10];
  const float* Wfc2 = (const float*)d_in[11]; const float* bfc2= (const float*)d_in[12];
  const float* Wfc3 = (const float*)d_in[13]; const float* bfc3= (const float*)d_in[14];
  float* out = (float*)d_out;

  static bool init_done = false;
  static cudaStream_t s_side = nullptr;
  static cudaEvent_t ev1 = nullptr, ev2 = nullptr, evT = nullptr, evW = nullptr, evM = nullptr;
  if (!init_done){
    cudaFuncSetAttribute(hgemm_kernel, cudaFuncAttributeMaxDynamicSharedMemorySize, HSM_TOT);
    cudaStreamCreateWithFlags(&s_side, cudaStreamNonBlocking);
    cudaEventCreateWithFlags(&ev1, cudaEventDisableTiming);
    cudaEventCreateWithFlags(&ev2, cudaEventDisableTiming);
    cudaEventCreateWithFlags(&evT, cudaEventDisableTiming);
    cudaEventCreateWithFlags(&evW, cudaEventDisableTiming);
    cudaEventCreateWithFlags(&evM, cudaEventDisableTiming);
    init_done = true;
  }

  float *pL, *pout1, *px12, *pout2, *px11, *px21, *pLx, *psqn, *poutR, *pg, *pgR;
  bf16 *pLh, *pLl, *pout1h, *pout1l, *pout1Th, *pout1Tl;
  bf16 *px12h, *px12l, *px12Th, *px12Tl;
  bf16 *px22h, *px22l, *pW2Th, *pW2Tl;
  bf16 *pxsRh, *pxsRl, *pWrTh, *pWrTl;
  cudaGetSymbolAddress((void**)&pL,      g_L);
  cudaGetSymbolAddress((void**)&pout1,   g_out1);
  cudaGetSymbolAddress((void**)&px12,    g_x12);
  cudaGetSymbolAddress((void**)&pout2,   g_out2);
  cudaGetSymbolAddress((void**)&px11,    g_x11);
  cudaGetSymbolAddress((void**)&px21,    g_x21);
  cudaGetSymbolAddress((void**)&pLx,     g_Lx);
  cudaGetSymbolAddress((void**)&psqn,    g_sqn);
  cudaGetSymbolAddress((void**)&poutR,   g_outR);
  cudaGetSymbolAddress((void**)&pg,      g_g);
  cudaGetSymbolAddress((void**)&pgR,     g_gR);
  cudaGetSymbolAddress((void**)&pLh,     g_Lh);
  cudaGetSymbolAddress((void**)&pLl,     g_Ll);
  cudaGetSymbolAddress((void**)&pout1h,  g_out1h);
  cudaGetSymbolAddress((void**)&pout1l,  g_out1l);
  cudaGetSymbolAddress((void**)&pout1Th, g_out1Th);
  cudaGetSymbolAddress((void**)&pout1Tl, g_out1Tl);
  cudaGetSymbolAddress((void**)&px12h,   g_x12h);
  cudaGetSymbolAddress((void**)&px12l,   g_x12l);
  cudaGetSymbolAddress((void**)&px12Th,  g_x12Th);
  cudaGetSymbolAddress((void**)&px12Tl,  g_x12Tl);
  cudaGetSymbolAddress((void**)&px22h,   g_x22h);
  cudaGetSymbolAddress((void**)&px22l,   g_x22l);
  cudaGetSymbolAddress((void**)&pW2Th,   g_W2Th);
  cudaGetSymbolAddress((void**)&pW2Tl,   g_W2Tl);
  cudaGetSymbolAddress((void**)&pxsRh,   g_xsRh);
  cudaGetSymbolAddress((void**)&pxsRl,   g_xsRl);
  cudaGetSymbolAddress((void**)&pWrTh,   g_WrTh);
  cudaGetSymbolAddress((void**)&pWrTl,   g_WrTl);

  zeroacc_kernel<<<1, 32>>>();
  zero_rs_kernel<<<128, 256>>>(1);

  // adjacency A1 (symmetric, upper computed + mirrored) with fused rowsum; L1 never materialized
  pairwise6_kernel<<<dim3(NPTS/16, NPTS/16, BATCH), dim3(16,16)>>>(x);

  // cheb conv 1 via implicit laplacian; cheb1 fuses sqnorm
  gemv6_adj_kernel<<<dim3(NPTS/16, BATCH), 512>>>(x, nullptr, px11, 1.f, 0.f);
  gemv6_adj_kernel<<<dim3(NPTS/16, BATCH), 512>>>(px11, x, px21, 2.f, -1.f);
  cheb1_out_kernel<<<dim3(8, (BATCH*NPTS)/16), 128>>>(x, W1, b1);

  // ---- fork side stream segment A (independent of out2 GEMM chain) ----
  cudaEventRecord(ev1, 0);
  cudaStreamWaitEvent(s_side, ev1, 0);
  transpose_hilo_kernel<<<dim3(NPTS/32, 32, BATCH), dim3(32,8), 0, s_side>>>(pout1, pout1Th, pout1Tl);
  cudaEventRecord(evT, s_side);
  w2t_kernel<<<dim3(32, 32, 3), dim3(32,8), 0, s_side>>>(W2);
  zero_g_kernel<<<63, 256, 0, s_side>>>();
  cudaEventRecord(evW, s_side);
  regnorm_kernel<<<dim3(8, BATCH), 128, 0, s_side>>>(pout1, px11, 0);
  gathermax_kernel<<<BATCH*RR, 256, 0, s_side>>>(sccs);
  wrt_kernel<<<dim3(188, 32), dim3(32,8), 0, s_side>>>(Wr);
  reeb_xs_kernel<<<dim3(8, BATCH), 128, 0, s_side>>>(Lr);
  {
    GemmArgs R{};
    R.Ah[0]=pxsRh; R.Al[0]=pxsRl; R.Bh[0]=pWrTh; R.Bl[0]=pWrTl;
    R.Ah[1]=pxsRh; R.Al[1]=pxsRl; R.Bh[1]=pWrTh; R.Bl[1]=pWrTl;
    R.Ah[2]=pxsRh; R.Al[2]=pxsRl; R.Bh[2]=pWrTh; R.Bl[2]=pWrTl;
    R.ldA = RK; R.ldB = RK; R.sA = 0; R.sB = 0;
    R.C = poutR; R.ldC = F1V; R.sC = 0;
    R.Ch = nullptr; R.Cl = nullptr; R.ldH = 0; R.sH = 0;
    R.Z = nullptr; R.ldZ = 0; R.sZ = 0;
    R.bias = br; R.sq = nullptr; R.sSq = 0; R.gmax = nullptr;
    R.M = BATCH*RR; R.N = F1V; R.nseg = 1; R.kcs = RK/32; R.epi = 4;
    hgemm_kernel<<<dim3(8,3,1), 256, HSM_TOT, s_side>>>(R);
  }
  colmax_kernel<<<dim3(4, BATCH), 256, 0, s_side>>>(poutR, pgR, RR);

  // ---- main chain continues ----
  zero_rs_kernel<<<128, 256>>>(0);

  GemmArgs A{};
  // adj2 = exp(2*out1@out1^T - sq_m - sq_n), upper triangle + fused rowsum atomics
  for (int s = 0; s < 3; s++){
    A.Ah[s]=pout1h; A.Al[s]=pout1l;
    A.Bh[s]=pout1h; A.Bl[s]=pout1l;
  }
  A.ldA = FPAD; A.ldB = FPAD; A.sA = (long)NPTS*FPAD; A.sB = (long)NPTS*FPAD;
  A.C = pL; A.ldC = NPTS; A.sC = (long)NPTS*NPTS;
  A.Ch = nullptr; A.Cl = nullptr; A.ldH = 0; A.sH = 0;
  A.Z = nullptr; A.ldZ = 0; A.sZ = 0; A.bias = nullptr;
  A.sq = psqn; A.sSq = NPTS; A.gmax = nullptr;
  A.M = NPTS; A.N = NPTS; A.nseg = 1; A.kcs = FPAD/32; A.epi = 1;
  hgemm_kernel<<<dim3(16,16,BATCH), 256, HSM_TOT>>>(A);

  // fused mirror + laplacian -> bf16 L2 only
  mirror_lap_kernel<<<dim3(NPTS/32, NPTS/32, BATCH), dim3(32,8)>>>();
  cudaEventRecord(evM, 0);

  // ---- side stream segment B (enqueued AFTER evM is recorded -> capture-legal) ----
  cudaStreamWaitEvent(s_side, evM, 0);
  gemv6_bf16_kernel<<<dim3(NPTS/8, BATCH), 256, 0, s_side>>>(x, pLx);
  cudaEventRecord(ev2, s_side);

  // x12 = L2 @ out1 (needs out1T from side stream)
  cudaStreamWaitEvent(0, evT, 0);
  for (int s = 0; s < 3; s++){
    A.Ah[s]=pLh; A.Al[s]=pLl;
    A.Bh[s]=pout1Th; A.Bl[s]=pout1Tl;
  }
  A.ldA = NPTS; A.ldB = NPTS; A.sA = (long)NPTS*NPTS; A.sB = (long)FPAD*NPTS;
  A.C = px12; A.ldC = F1V; A.sC = (long)NPTS*F1V;
  A.Ch = px12h; A.Cl = px12l; A.ldH = FPAD; A.sH = (long)NPTS*FPAD;
  A.Z = nullptr; A.sq = nullptr; A.bias = nullptr; A.gmax = nullptr;
  A.M = NPTS; A.N = F1V; A.nseg = 1; A.kcs = NPTS/32; A.epi = 2;
  hgemm_kernel<<<dim3(8,16,BATCH), 256, HSM_TOT>>>(A);

  transpose_hilo_kernel<<<dim3(NPTS/32, 32, BATCH), dim3(32,8)>>>(px12, px12Th, px12Tl);

  // x22 = 2*L2@x12 - out1 (split2 only)
  for (int s = 0; s < 3; s++){
    A.Ah[s]=pLh; A.Al[s]=pLl;
    A.Bh[s]=px12Th; A.Bl[s]=px12Tl;
  }
  A.C = nullptr; A.ldC = 0; A.sC = 0;
  A.Ch = px22h; A.Cl = px22l; A.ldH = FPAD; A.sH = (long)NPTS*FPAD;
  A.Z = pout1; A.ldZ = F1V; A.sZ = (long)NPTS*F1V;
  A.M = NPTS; A.N = F1V; A.nseg = 1; A.kcs = NPTS/32; A.epi = 3;
  hgemm_kernel<<<dim3(8,16,BATCH), 256, HSM_TOT>>>(A);

  // out2 = relu(out1@W2a + x12@W2b + x22@W2c + b2) + fused colmax (needs W2T + zeroed g from side)
  cudaStreamWaitEvent(0, evW, 0);
  A.Ah[0]=pout1h; A.Al[0]=pout1l;
  A.Ah[1]=px12h;  A.Al[1]=px12l;
  A.Ah[2]=px22h;  A.Al[2]=px22l;
  A.Bh[0]=pW2Th;                       A.Bl[0]=pW2Tl;
  A.Bh[1]=pW2Th + (size_t)FPAD*FPAD;   A.Bl[1]=pW2Tl + (size_t)FPAD*FPAD;
  A.Bh[2]=pW2Th + (size_t)2*FPAD*FPAD; A.Bl[2]=pW2Tl + (size_t)2*FPAD*FPAD;
  A.ldA = FPAD; A.ldB = FPAD; A.sA = 0; A.sB = 0;
  A.C = pout2; A.ldC = F1V; A.sC = 0;
  A.Ch = nullptr; A.Cl = nullptr; A.Z = nullptr;
  A.bias = b2; A.gmax = (unsigned*)pg;
  A.M = BATCH*NPTS; A.N = F1V; A.nseg = 3; A.kcs = FPAD/32; A.epi = 4;
  hgemm_kernel<<<dim3(8,256,1), 256, HSM_TOT>>>(A);

  // ---- join side stream (pLx, gR ready) ----
  cudaStreamWaitEvent(0, ev2, 0);
  regnorm_kernel<<<dim3(8, BATCH), 128>>>(pout2, pLx, 1);

  // FC head
  fc1_kernel<<<BATCH, 512>>>(Wfc1, bfc1);
  fc2_kernel<<<BATCH, 128>>>(Wfc2, bfc2);
  fc3_kernel<<<BATCH, 64>>>(Wfc3, bfc3, out);

  // regs
  wreg_kernel<<<3, 256>>>(Wfc1, bfc1, Wfc2, bfc2, Wfc3, bfc3, out);
  finalize_kernel<<<1, 1>>>(out);
}

// round 17
// speedup vs baseline: 1.2362x; 1.0145x over previous
#include <cuda_runtime.h>
#include <cuda_bf16.h>
#include <math.h>
#include <stdint.h>

#define BATCH 16
#define NPTS 2048
#define CINF 6
#define RR 20
#define GG 128
#define F1V 1000
#define NCLS 40
#define FPAD 1024
#define RK 6016
#define RM 384

typedef __nv_bfloat16 bf16;

// ---------------- scratch (device globals; zero-initialized, no allocations) ----------------
__device__ float g_L[(size_t)BATCH*NPTS*NPTS];
__device__ float g_out1[(size_t)BATCH*NPTS*F1V];
__device__ float g_x12[(size_t)BATCH*NPTS*F1V];
__device__ float g_out2[(size_t)BATCH*NPTS*F1V];
__device__ bf16  g_Lh[(size_t)BATCH*NPTS*NPTS];
__device__ bf16  g_Ll[(size_t)BATCH*NPTS*NPTS];
__device__ bf16  g_out1h[(size_t)BATCH*NPTS*FPAD];
__device__ bf16  g_out1l[(size_t)BATCH*NPTS*FPAD];
__device__ bf16  g_out1Th[(size_t)BATCH*FPAD*NPTS];
__device__ bf16  g_out1Tl[(size_t)BATCH*FPAD*NPTS];
__device__ bf16  g_x12h[(size_t)BATCH*NPTS*FPAD];
__device__ bf16  g_x12l[(size_t)BATCH*NPTS*FPAD];
__device__ bf16  g_x12Th[(size_t)BATCH*FPAD*NPTS];
__device__ bf16  g_x12Tl[(size_t)BATCH*FPAD*NPTS];
__device__ bf16  g_x22h[(size_t)BATCH*NPTS*FPAD];
__device__ bf16  g_x22l[(size_t)BATCH*NPTS*FPAD];
__device__ bf16  g_W2Th[3*FPAD*FPAD];
__device__ bf16  g_W2Tl[3*FPAD*FPAD];
__device__ bf16  g_xsRh[(size_t)RM*RK];
__device__ bf16  g_xsRl[(size_t)RM*RK];
__device__ bf16  g_WrTh[(size_t)FPAD*RK];
__device__ bf16  g_WrTl[(size_t)FPAD*RK];
__device__ float g_x11[BATCH*NPTS*CINF];
__device__ float g_x21[BATCH*NPTS*CINF];
__device__ float g_Lx[BATCH*NPTS*CINF];
__device__ float g_rowsum[BATCH*NPTS];
__device__ float g_sqn[BATCH*NPTS];
__device__ float g_vR[BATCH*RR*F1V];
__device__ float g_outR[BATCH*RR*F1V];
__device__ float g_g[BATCH*F1V];
__device__ float g_gR[BATCH*F1V];
__device__ float g_h1[BATCH*512];
__device__ float g_h2[BATCH*128];
__device__ float g_acc[8];

// ---------------- helpers ----------------
__device__ __forceinline__ uint32_t smem_u32(const void* p){
  uint32_t a;
  asm("{ .reg .u64 t; cvta.to.shared.u64 t, %1; cvt.u32.u64 %0, t; }" : "=r"(a) : "l"(p));
  return a;
}
__device__ __forceinline__ void cp16(uint32_t s, const void* g){
  asm volatile("cp.async.cg.shared.global [%0], [%1], 16;" :: "r"(s), "l"(g));
}
__device__ __forceinline__ void ldsm4(uint32_t& r0, uint32_t& r1, uint32_t& r2, uint32_t& r3, uint32_t a){
  asm volatile("ldmatrix.sync.aligned.m8n8.x4.shared.b16 {%0,%1,%2,%3}, [%4];"
    : "=r"(r0), "=r"(r1), "=r"(r2), "=r"(r3) : "r"(a));
}
__device__ __forceinline__ void mma16816(float* d, const uint32_t* a, const uint32_t* b){
  asm volatile("mma.sync.aligned.m16n8k16.row.col.f32.bf16.bf16.f32 "
    "{%0,%1,%2,%3}, {%4,%5,%6,%7}, {%8,%9}, {%0,%1,%2,%3};"
    : "+f"(d[0]), "+f"(d[1]), "+f"(d[2]), "+f"(d[3])
    : "r"(a[0]), "r"(a[1]), "r"(a[2]), "r"(a[3]), "r"(b[0]), "r"(b[1]));
}
__device__ __forceinline__ void split2(float v, bf16* ph, bf16* pl){
  bf16 h = __float2bfloat16(v);
  *ph = h;
  *pl = __float2bfloat16(v - __bfloat162float(h));
}
__device__ __forceinline__ void split2v(float v0, float v1, __nv_bfloat162* ph, __nv_bfloat162* pl){
  bf16 h0 = __float2bfloat16(v0);
  bf16 h1 = __float2bfloat16(v1);
  __nv_bfloat162 hh; hh.x = h0; hh.y = h1;
  __nv_bfloat162 ll;
  ll.x = __float2bfloat16(v0 - __bfloat162float(h0));
  ll.y = __float2bfloat16(v1 - __bfloat162float(h1));
  *ph = hh; *pl = ll;
}

// ---------------- HMMA GEMM: C[M,N], CTA tile 128x128, BK=32, 2-stage, 2 CTAs/SM ----------------
// epi: 0 plain C; 1 exp(2a - sq[m] - sq[n]) upper-only + rowsum atomics; 2 C + split2; 3 split2 of (2a - Z); 4 relu(a + bias[n]) [+ colmax atomics]
struct GemmArgs {
  const bf16 *Ah[3], *Al[3], *Bh[3], *Bl[3];
  long ldA, ldB, sA, sB;
  float* C; long ldC, sC;
  bf16 *Ch, *Cl; long ldH, sH;
  const float* Z; long ldZ, sZ;
  const float* bias;
  const float* sq; long sSq;
  unsigned* gmax;
  int M, N, nseg, kcs, epi;
};

#define STAGE_B 40960          // 4 parts * 128 rows * 80 bytes
#define PART_B  10240
#define HSM_TOT (2*STAGE_B)    // 81920 -> 2 CTAs per SM

__global__ __launch_bounds__(256, 2) void hgemm_kernel(GemmArgs P){
  // symmetric pairwise: skip lower-triangle blocks
  if (P.epi == 1 && blockIdx.x < blockIdx.y) return;

  extern __shared__ char sm[];
  uint32_t sb = smem_u32(sm);
  int tid = threadIdx.x;
  int w = tid >> 5, l = tid & 31;
  int wm = w & 3;
  int wn = w >> 2;
  int bz = blockIdx.z;
  int m0 = blockIdx.y * 128, n0 = blockIdx.x * 128;
  const int nk = P.nseg * P.kcs;

  float acc[2][8][4];
  #pragma unroll
  for (int t = 0; t < 2; t++)
    #pragma unroll
    for (int j = 0; j < 8; j++)
      #pragma unroll
      for (int r = 0; r < 4; r++) acc[t][j][r] = 0.f;

  auto stage_load = [&](int kt){
    int seg = kt / P.kcs, kc = kt % P.kcs;
    const bf16* pa[2] = {
      P.Ah[seg] + (size_t)bz*P.sA + (size_t)m0*P.ldA + (size_t)kc*32,
      P.Al[seg] + (size_t)bz*P.sA + (size_t)m0*P.ldA + (size_t)kc*32 };
    const bf16* pb[2] = {
      P.Bh[seg] + (size_t)bz*P.sB + (size_t)n0*P.ldB + (size_t)kc*32,
      P.Bl[seg] + (size_t)bz*P.sB + (size_t)n0*P.ldB + (size_t)kc*32 };
    uint32_t st = sb + (uint32_t)(kt & 1) * STAGE_B;
    #pragma unroll
    for (int i = 0; i < 8; i++){
      int part = i >> 1;
      int cid = tid + (i & 1)*256;
      int row = cid >> 2, col = cid & 3;
      const bf16* gp = (part < 2) ? pa[part] : pb[part - 2];
      long ld = (part < 2) ? P.ldA : P.ldB;
      cp16(st + part*PART_B + row*80 + col*16, gp + (size_t)row*ld + col*8);
    }
    asm volatile("cp.async.commit_group;" ::: "memory");
  };

  stage_load(0);

  for (int kt = 0; kt < nk; kt++){
    if (kt + 1 < nk){
      stage_load(kt + 1);
      asm volatile("cp.async.wait_group 1;" ::: "memory");
    } else {
      asm volatile("cp.async.wait_group 0;" ::: "memory");
    }
    __syncthreads();

    uint32_t st = sb + (uint32_t)(kt & 1) * STAGE_B;
    #pragma unroll
    for (int step = 0; step < 2; step++){
      uint32_t ah[2][4], al[2][4];
      #pragma unroll
      for (int t = 0; t < 2; t++){
        int row = wm*32 + t*16 + (l & 15);
        uint32_t koff = (uint32_t)(step*32 + ((l >> 4) & 1)*16);
        uint32_t addr = st + row*80 + koff;
        ldsm4(ah[t][0], ah[t][1], ah[t][2], ah[t][3], addr);
        ldsm4(al[t][0], al[t][1], al[t][2], al[t][3], addr + PART_B);
      }
      uint32_t bh[8][2], bl[8][2];
      #pragma unroll
      for (int j = 0; j < 4; j++){
        int n = wn*64 + j*16 + (((l >> 4) & 1) << 3) + (l & 7);
        uint32_t koff = (uint32_t)(step*32 + ((l >> 3) & 1)*16);
        uint32_t addr = st + 2*PART_B + n*80 + koff;
        ldsm4(bh[2*j][0], bh[2*j][1], bh[2*j+1][0], bh[2*j+1][1], addr);
        ldsm4(bl[2*j][0], bl[2*j][1], bl[2*j+1][0], bl[2*j+1][1], addr + PART_B);
      }
      #pragma unroll
      for (int t = 0; t < 2; t++)
        #pragma unroll
        for (int j = 0; j < 8; j++){
          mma16816(acc[t][j], ah[t], bh[j]);
          mma16816(acc[t][j], ah[t], bl[j]);
          mma16816(acc[t][j], al[t], bh[j]);
        }
    }
    __syncthreads();
  }

  // ---- epilogue ----
  int lm = l >> 2, ln = (l & 3)*2;

  if (P.epi == 1){
    const float* sqb = P.sq + (size_t)bz*P.sSq;
    float* C = P.C + (size_t)bz*P.sC;
    float* rs = g_rowsum + (size_t)bz*NPTS;
    bool dup = (blockIdx.x > blockIdx.y);
    float rowm[4] = {0.f, 0.f, 0.f, 0.f};
    float rown[16];
    #pragma unroll
    for (int q = 0; q < 16; q++) rown[q] = 0.f;
    #pragma unroll
    for (int t = 0; t < 2; t++){
      #pragma unroll
      for (int j = 0; j < 8; j++){
        #pragma unroll
        for (int r = 0; r < 4; r++){
          int m = m0 + wm*32 + t*16 + lm + (r >> 1)*8;
          int n = n0 + wn*64 + j*8 + ln + (r & 1);
          float e = expf(2.f*acc[t][j][r] - sqb[m] - sqb[n]);
          C[(size_t)m*P.ldC + n] = e;
          rowm[t*2 + (r >> 1)] += e;
          rown[j*2 + (r & 1)] += e;
        }
      }
    }
    #pragma unroll
    for (int q = 0; q < 4; q++){
      int m = m0 + wm*32 + (q >> 1)*16 + lm + (q & 1)*8;
      atomicAdd(&rs[m], rowm[q]);
    }
    if (dup){
      #pragma unroll
      for (int q = 0; q < 16; q++){
        int n = n0 + wn*64 + (q >> 1)*8 + ln + (q & 1);
        atomicAdd(&rs[n], rown[q]);
      }
    }
    return;
  }

  float* C = P.C ? (P.C + (size_t)bz*P.sC) : nullptr;
  bf16* Ch = P.Ch ? (P.Ch + (size_t)bz*P.sH) : nullptr;
  bf16* Cl = P.Cl ? (P.Cl + (size_t)bz*P.sH) : nullptr;
  const float* Z = P.Z ? (P.Z + (size_t)bz*P.sZ) : nullptr;

  float cmax[16];
  #pragma unroll
  for (int q = 0; q < 16; q++) cmax[q] = 0.f;

  #pragma unroll
  for (int t = 0; t < 2; t++){
    #pragma unroll
    for (int j = 0; j < 8; j++){
      #pragma unroll
      for (int r = 0; r < 4; r++){
        int m = m0 + wm*32 + t*16 + lm + (r >> 1)*8;
        int n = n0 + wn*64 + j*8 + ln + (r & 1);
        if (m < P.M && n < P.N){
          float a = acc[t][j][r];
          if (P.epi == 0){
            C[(size_t)m*P.ldC + n] = a;
          } else if (P.epi == 2){
            C[(size_t)m*P.ldC + n] = a;
            split2(a, Ch + (size_t)m*P.ldH + n, Cl + (size_t)m*P.ldH + n);
          } else if (P.epi == 3){
            float v = 2.f*a - Z[(size_t)m*P.ldZ + n];
            split2(v, Ch + (size_t)m*P.ldH + n, Cl + (size_t)m*P.ldH + n);
          } else {
            float v = fmaxf(a + P.bias[n], 0.f);
            C[(size_t)m*P.ldC + n] = v;
            cmax[j*2 + (r & 1)] = fmaxf(cmax[j*2 + (r & 1)], v);
          }
        }
      }
    }
  }

  if (P.epi == 4 && P.gmax){
    int b = m0 >> 11;
    #pragma unroll
    for (int q = 0; q < 16; q++){
      int n = n0 + wn*64 + (q >> 1)*8 + ln + (q & 1);
      if (n < P.N)
        atomicMax(&P.gmax[(size_t)b*F1V + n], __float_as_uint(cmax[q]));
    }
  }
}

// fused mirror + laplacian + bf16 split for L2, vectorized bf162 stores (block 16x16)
__global__ void mirror_lap_kernel(){
  int b = blockIdx.z;
  int tx = blockIdx.x, ty = blockIdx.y;
  if (tx < ty) return;
  __shared__ float t[32][33];
  __shared__ float rim[32], rin[32];
  int x = threadIdx.x;              // 0..15  (col pair)
  int y = threadIdx.y;              // 0..15  (rows y, y+16)
  int tid = y*16 + x;
  size_t base = (size_t)b*NPTS*NPTS;
  if (tid < 32) rim[tid] = rsqrtf(g_rowsum[b*NPTS + ty*32 + tid]);
  else if (tid < 64) rin[tid-32] = rsqrtf(g_rowsum[b*NPTS + tx*32 + (tid-32)]);
  __syncthreads();
  #pragma unroll
  for (int rr = 0; rr < 2; rr++){
    int r = y + rr*16;
    int m = ty*32 + r;
    int n = tx*32 + 2*x;
    float2 a = *(const float2*)&g_L[base + (size_t)m*NPTS + n];
    float Lv0 = ((m == n)   ? 1.f : 0.f) - rim[r]*a.x*rin[2*x];
    float Lv1 = ((m == n+1) ? 1.f : 0.f) - rim[r]*a.y*rin[2*x+1];
    t[r][2*x] = Lv0; t[r][2*x+1] = Lv1;
    size_t o = base + (size_t)m*NPTS + n;
    split2v(Lv0, Lv1, (__nv_bfloat162*)&g_Lh[o], (__nv_bfloat162*)&g_Ll[o]);
  }
  if (tx > ty){
    __syncthreads();
    #pragma unroll
    for (int rr = 0; rr < 2; rr++){
      int r = y + rr*16;                   // row within mirrored tile
      int m = tx*32 + r;
      int n = ty*32 + 2*x;
      float Lv0 = t[2*x][r];
      float Lv1 = t[2*x+1][r];
      size_t o = base + (size_t)m*NPTS + n;
      split2v(Lv0, Lv1, (__nv_bfloat162*)&g_Lh[o], (__nv_bfloat162*)&g_Ll[o]);
    }
  }
}

// ---------------- small kernels ----------------
__global__ void zeroacc_kernel(){ if (threadIdx.x < 8) g_acc[threadIdx.x] = 0.f; }

__global__ void zero_rs_kernel(int withSq){
  int i = blockIdx.x*256 + threadIdx.x;
  if (i < BATCH*NPTS){
    g_rowsum[i] = 0.f;
    if (withSq) g_sqn[i] = 0.f;
  }
}

__global__ void zero_g_kernel(){
  int i = blockIdx.x*256 + threadIdx.x;
  if (i < BATCH*F1V) ((unsigned*)g_g)[i] = 0u;
}

__global__ void pairwise6_kernel(const float* __restrict__ x){
  if (blockIdx.x < blockIdx.y) return;
  int b = blockIdx.z;
  int i0 = blockIdx.y*16, j0 = blockIdx.x*16;
  __shared__ float xi[16][6], xj[16][6];
  __shared__ float te[16][17];
  int tid = threadIdx.y*16 + threadIdx.x;
  if (tid < 96){
    int r = tid/6, c = tid%6;
    xi[r][c] = x[((size_t)b*NPTS + i0 + r)*CINF + c];
    xj[r][c] = x[((size_t)b*NPTS + j0 + r)*CINF + c];
  }
  __syncthreads();
  int i = threadIdx.y, j = threadIdx.x;
  float d = 0.f;
  #pragma unroll
  for (int c = 0; c < 6; c++){ float t = xi[i][c]-xj[j][c]; d += t*t; }
  float e = expf(-d);
  g_L[((size_t)b*NPTS + i0+i)*NPTS + j0+j] = e;
  te[i][j] = e;
  float* rs = g_rowsum + (size_t)b*NPTS;
  float s = e;
  #pragma unroll
  for (int o = 8; o > 0; o >>= 1) s += __shfl_down_sync(0xffffffffu, s, o, 16);
  if (j == 0) atomicAdd(&rs[i0 + i], s);
  if (blockIdx.x > blockIdx.y){
    __syncthreads();
    g_L[((size_t)b*NPTS + j0+i)*NPTS + i0+j] = te[j][i];
    if (tid < 16){
      float cs = 0.f;
      #pragma unroll
      for (int k = 0; k < 16; k++) cs += te[k][tid];
      atomicAdd(&rs[j0 + tid], cs);
    }
  }
}

__global__ void gemv6_adj_kernel(const float* __restrict__ X, const float* __restrict__ Z,
                                 float* __restrict__ Y, float s, float t){
  int b = blockIdx.y;
  __shared__ float xs[NPTS*CINF];
  const float* rs = g_rowsum + (size_t)b*NPTS;
  for (int idx = threadIdx.x; idx < NPTS*CINF; idx += 512){
    int row = idx / CINF;
    xs[idx] = X[(size_t)b*NPTS*CINF + idx] * rsqrtf(rs[row]);
  }
  __syncthreads();
  int warp = threadIdx.x >> 5, lane = threadIdx.x & 31;
  int i = blockIdx.x*16 + warp;
  const float* Arow = g_L + ((size_t)b*NPTS + i)*NPTS;
  float acc[6] = {0,0,0,0,0,0};
  for (int k = lane; k < NPTS; k += 32){
    float a = Arow[k];
    #pragma unroll
    for (int c = 0; c < 6; c++) acc[c] += a * xs[k*6 + c];
  }
  #pragma unroll
  for (int c = 0; c < 6; c++)
    for (int o = 16; o > 0; o >>= 1) acc[c] += __shfl_down_sync(0xffffffffu, acc[c], o);
  if (!lane){
    float rsi = rsqrtf(rs[i]);
    size_t base = ((size_t)b*NPTS + i)*CINF;
    #pragma unroll
    for (int c = 0; c < 6; c++){
      float v = s*(X[base + c] - rsi*acc[c]);
      if (Z) v += t*Z[base + c];
      Y[base + c] = v;
    }
  }
}

__global__ void gemv6_bf16_kernel(const float* __restrict__ X, float* __restrict__ Y){
  int b = blockIdx.y;
  __shared__ float xs[NPTS*CINF];
  for (int idx = threadIdx.x; idx < NPTS*CINF; idx += 256)
    xs[idx] = X[(size_t)b*NPTS*CINF + idx];
  __syncthreads();
  int warp = threadIdx.x >> 5, lane = threadIdx.x & 31;
  int i = blockIdx.x*8 + warp;
  const __nv_bfloat162* Lh2 = (const __nv_bfloat162*)(g_Lh + ((size_t)b*NPTS + i)*NPTS);
  const __nv_bfloat162* Ll2 = (const __nv_bfloat162*)(g_Ll + ((size_t)b*NPTS + i)*NPTS);
  float acc[6] = {0,0,0,0,0,0};
  for (int k = lane; k < NPTS/2; k += 32){
    float2 h = __bfloat1622float2(Lh2[k]);
    float2 lo = __bfloat1622float2(Ll2[k]);
    float a0 = h.x + lo.x, a1 = h.y + lo.y;
    #pragma unroll
    for (int c = 0; c < 6; c++)
      acc[c] += a0*xs[(2*k)*6 + c] + a1*xs[(2*k+1)*6 + c];
  }
  #pragma unroll
  for (int c = 0; c < 6; c++)
    for (int o = 16; o > 0; o >>= 1) acc[c] += __shfl_down_sync(0xffffffffu, acc[c], o);
  if (!lane){
    size_t base = ((size_t)b*NPTS + i)*CINF;
    #pragma unroll
    for (int c = 0; c < 6; c++) Y[base + c] = acc[c];
  }
}

// cheb1 + fused sqnorm (g_sqn must be pre-zeroed)
__global__ void cheb1_out_kernel(const float* __restrict__ x, const float* __restrict__ W1,
                                 const float* __restrict__ b1){
  int f = blockIdx.x*128 + threadIdx.x;
  int row0 = blockIdx.y*16;
  __shared__ float xsr[16][18];
  for (int idx = threadIdx.x; idx < 16*18; idx += 128){
    int r = idx/18, q = idx%18, c = q/3, kk = q%3;
    size_t g = (size_t)(row0 + r)*CINF + c;
    xsr[r][q] = (kk == 0) ? x[g] : ((kk == 1) ? g_x11[g] : g_x21[g]);
  }
  __syncthreads();
  bool ok = (f < F1V);
  int lane = threadIdx.x & 31;
  float w[18];
  float bb = 0.f;
  #pragma unroll
  for (int q = 0; q < 18; q++) w[q] = ok ? W1[q*F1V + f] : 0.f;
  if (ok) bb = b1[f];
  for (int r = 0; r < 16; r++){
    float a = bb;
    #pragma unroll
    for (int q = 0; q < 18; q++) a += xsr[r][q]*w[q];
    float v = ok ? fmaxf(a, 0.f) : 0.f;
    size_t rowi = (size_t)(row0 + r);
    if (ok){
      g_out1[rowi*F1V + f] = v;
      split2(v, &g_out1h[rowi*FPAD + f], &g_out1l[rowi*FPAD + f]);
    }
    float sq = v*v;
    #pragma unroll
    for (int o = 16; o > 0; o >>= 1) sq += __shfl_down_sync(0xffffffffu, sq, o);
    if (!lane) atomicAdd(&g_sqn[rowi], sq);
  }
}

__global__ void regnorm_kernel(const float* __restrict__ outp, const float* __restrict__ xc, int slot){
  int b = blockIdx.y;
  int f = blockIdx.x*128 + threadIdx.x;
  __shared__ float sh[128*6];
  float acc[6] = {0,0,0,0,0,0};
  for (int i0 = 0; i0 < NPTS; i0 += 128){
    __syncthreads();
    for (int idx = threadIdx.x; idx < 128*6; idx += 128)
      sh[idx] = xc[((size_t)b*NPTS + i0)*CINF + idx];
    __syncthreads();
    if (f < F1V){
      for (int ii = 0; ii < 128; ii++){
        float o = outp[((size_t)b*NPTS + i0 + ii)*F1V + f];
        #pragma unroll
        for (int c = 0; c < 6; c++) acc[c] += o*sh[ii*6 + c];
      }
    }
  }
  float s = 0.f;
  #pragma unroll
  for (int c = 0; c < 6; c++) s += acc[c]*acc[c];
  if (f >= F1V) s = 0.f;
  __shared__ float red[128];
  red[threadIdx.x] = s; __syncthreads();
  for (int o = 64; o > 0; o >>= 1){ if (threadIdx.x < o) red[threadIdx.x] += red[threadIdx.x+o]; __syncthreads(); }
  if (!threadIdx.x) atomicAdd(&g_acc[slot], red[0]);
}

__global__ void gathermax_kernel(const int* __restrict__ sccs){
  int br = blockIdx.x;
  int b = br / RR;
  __shared__ int idx[GG];
  for (int t = threadIdx.x; t < GG; t += 256) idx[t] = sccs[(size_t)br*GG + t];
  __syncthreads();
  for (int f = threadIdx.x; f < F1V; f += 256){
    float m = -1e30f;
    for (int g = 0; g < GG; g++)
      m = fmaxf(m, g_out1[((size_t)b*NPTS + idx[g])*F1V + f]);
    g_vR[(size_t)br*F1V + f] = m;
  }
}

__global__ void colmax_kernel(const float* __restrict__ src, float* __restrict__ dst, int rows){
  int b = blockIdx.y;
  int f = blockIdx.x*256 + threadIdx.x;
  if (f >= F1V) return;
  float m = -1e30f;
  for (int i = 0; i < rows; i++)
    m = fmaxf(m, src[((size_t)b*rows + i)*F1V + f]);
  dst[(size_t)b*F1V + f] = m;
}

// transpose fp32 [b][2048][1000] -> bf16 split2 [b][1024 rows(n)][2048], bf162 stores
__global__ void transpose_hilo_kernel(const float* __restrict__ src,
                                      bf16* __restrict__ dh, bf16* __restrict__ dl){
  int b = blockIdx.z;
  __shared__ float t[32][33];
  int m0 = blockIdx.x*32, n0 = blockIdx.y*32;
  int x = threadIdx.x, y = threadIdx.y;
  int tid = y*32 + x;
  for (int i = 0; i < 32; i += 8){
    int n = n0 + x, m = m0 + y + i;
    t[y+i][x] = (n < F1V) ? src[((size_t)b*NPTS + m)*F1V + n] : 0.f;
  }
  __syncthreads();
  for (int q = tid; q < 512; q += 256){
    int ni = q >> 4;
    int mi = (q & 15) << 1;
    int n = n0 + ni;
    if (n < F1V){
      float v0 = t[mi][ni], v1 = t[mi+1][ni];
      size_t o = ((size_t)b*FPAD + n)*NPTS + m0 + mi;
      split2v(v0, v1, (__nv_bfloat162*)&dh[o], (__nv_bfloat162*)&dl[o]);
    }
  }
}

__global__ void w2t_kernel(const float* __restrict__ W2){
  int seg = blockIdx.z;
  __shared__ float t[32][33];
  int k0 = blockIdx.x*32, n0 = blockIdx.y*32;
  int x = threadIdx.x, y = threadIdx.y;
  for (int i = 0; i < 32; i += 8){
    int n = n0 + x, k = k0 + y + i;
    t[y+i][x] = (n < F1V && k < F1V) ? W2[(size_t)(3*k + seg)*F1V + n] : 0.f;
  }
  __syncthreads();
  for (int i = 0; i < 32; i += 8){
    int n = n0 + y + i, k = k0 + x;
    if (n < F1V && k < F1V){
      size_t o = (size_t)seg*FPAD*FPAD + (size_t)n*FPAD + k;
      split2(t[x][y+i], &g_W2Th[o], &g_W2Tl[o]);
    }
  }
}

__global__ void wrt_kernel(const float* __restrict__ Wr){
  __shared__ float t[32][33];
  int q0 = blockIdx.x*32, n0 = blockIdx.y*32;
  int x = threadIdx.x, y = threadIdx.y;
  for (int i = 0; i < 32; i += 8){
    int n = n0 + x, q = q0 + y + i;
    t[y+i][x] = (n < F1V && q < 6000) ? Wr[(size_t)q*F1V + n] : 0.f;
  }
  __syncthreads();
  for (int i = 0; i < 32; i += 8){
    int n = n0 + y + i, q = q0 + x;
    if (n < F1V && q < 6000){
      size_t o = (size_t)n*RK + q;
      split2(t[x][y+i], &g_WrTh[o], &g_WrTl[o]);
    }
  }
}

__global__ void reeb_xs_kernel(const float* __restrict__ Lr){
  int b = blockIdx.y;
  int c = blockIdx.x*128 + threadIdx.x;
  __shared__ float Ls[RR*RR];
  for (int t = threadIdx.x; t < RR*RR; t += 128) Ls[t] = Lr[(size_t)b*RR*RR + t];
  __syncthreads();
  if (c >= F1V) return;
  float v0[RR], v1[RR], v2[RR];
  #pragma unroll
  for (int r = 0; r < RR; r++){
    v0[r] = g_vR[((size_t)b*RR + r)*F1V + c];
    size_t o = (size_t)(b*RR + r)*RK + c*6 + 0;
    split2(v0[r], &g_xsRh[o], &g_xsRl[o]);
  }
  #pragma unroll
  for (int r = 0; r < RR; r++){
    float s = 0.f;
    for (int r2 = 0; r2 < RR; r2++) s += Ls[r*RR + r2]*v0[r2];
    v1[r] = s;
    size_t o = (size_t)(b*RR + r)*RK + c*6 + 1;
    split2(s, &g_xsRh[o], &g_xsRl[o]);
  }
  for (int k = 2; k < 6; k++){
    #pragma unroll
    for (int r = 0; r < RR; r++){
      float s = 0.f;
      for (int r2 = 0; r2 < RR; r2++) s += Ls[r*RR + r2]*v1[r2];
      v2[r] = 2.f*s - v0[r];
      size_t o = (size_t)(b*RR + r)*RK + c*6 + k;
      split2(v2[r], &g_xsRh[o], &g_xsRl[o]);
    }
    #pragma unroll
    for (int r = 0; r < RR; r++){ v0[r] = v1[r]; v1[r] = v2[r]; }
  }
}

__global__ void fc1_kernel(const float* __restrict__ W, const float* __restrict__ bias){
  int b = blockIdx.x;
  __shared__ float ft[2*F1V];
  for (int c = threadIdx.x; c < 2*F1V; c += 512)
    ft[c] = (c < F1V) ? g_gR[(size_t)b*F1V + c] : g_g[(size_t)b*F1V + c - F1V];
  __syncthreads();
  int f = threadIdx.x;
  float a = bias[f];
  for (int c = 0; c < 2*F1V; c++) a += ft[c]*W[(size_t)c*512 + f];
  g_h1[b*512 + f] = fmaxf(a, 0.f);
}

__global__ void fc2_kernel(const float* __restrict__ W, const float* __restrict__ bias){
  int b = blockIdx.x;
  __shared__ float hs[512];
  for (int c = threadIdx.x; c < 512; c += 128) hs[c] = g_h1[b*512 + c];
  __syncthreads();
  int f = threadIdx.x;
  float a = bias[f];
  for (int c = 0; c < 512; c++) a += hs[c]*W[c*128 + f];
  g_h2[b*128 + f] = fmaxf(a, 0.f);
}

__global__ void fc3_kernel(const float* __restrict__ W, const float* __restrict__ bias, float* __restrict__ out){
  int b = blockIdx.x;
  __shared__ float hs[128];
  for (int c = threadIdx.x; c < 128; c += 64) hs[c] = g_h2[b*128 + c];
  __syncthreads();
  int f = threadIdx.x;
  if (f < NCLS){
    float a = bias[f];
    for (int c = 0; c < 128; c++) a += hs[c]*W[c*NCLS + f];
    out[b*NCLS + f] = a;
  }
}

__global__ void wreg_kernel(const float* W1, const float* B1, const float* W2, const float* B2,
                            const float* W3, const float* B3, float* out){
  int layer = blockIdx.x;
  const float* W; const float* Bp; int n, ld;
  if (layer == 0){ W = W1; Bp = B1; n = 2000; ld = 512; }
  else if (layer == 1){ W = W2; Bp = B2; n = 512; ld = 128; }
  else { W = W3; Bp = B3; n = 128; ld = 40; }
  float s = 0.f;
  for (int c = threadIdx.x; c < n; c += 256){ float v = W[(size_t)c*ld]; s += v*v; }
  __shared__ float sh[256];
  sh[threadIdx.x] = s; __syncthreads();
  for (int o = 128; o > 0; o >>= 1){ if (threadIdx.x < o) sh[threadIdx.x] += sh[threadIdx.x+o]; __syncthreads(); }
  if (!threadIdx.x){ out[642 + layer*2] = sh[0]; out[643 + layer*2] = Bp[0]*Bp[0]; }
}

__global__ void finalize_kernel(float* out){
  out[640] = sqrtf(g_acc[0]);
  out[641] = sqrtf(g_acc[1]);
}

// ---------------- host launch ----------------
extern "C" void kernel_launch(void* const* d_in, const int* in_sizes, int n_in,
                              void* d_out, int out_size){
  const float* x    = (const float*)d_in[0];
  const float* Lr   = (const float*)d_in[1];
  const int*   sccs = (const int*)  d_in[2];
  const float* W1   = (const float*)d_in[3];  const float* b1  = (const float*)d_in[4];
  const float* W2   = (const float*)d_in[5];  const float* b2  = (const float*)d_in[6];
  const float* Wr   = (const float*)d_in[7];  const float* br  = (const float*)d_in[8];
  const float* Wfc1 = (const float*)d_in[9];  const float* bfc1= (const float*)d_in[10];
  const float* Wfc2 = (const float*)d_in[11]; const float* bfc2= (const float*)d_in[12];
  const float* Wfc3 = (const float*)d_in[13]; const float* bfc3= (const float*)d_in[14];
  float* out = (float*)d_out;

  static bool init_done = false;
  static cudaStream_t s_side = nullptr;
  static cudaEvent_t ev1 = nullptr, ev2 = nullptr, evT = nullptr, evW = nullptr, evM = nullptr;
  static cudaEvent_t evR = nullptr, evO = nullptr, ev3 = nullptr;
  if (!init_done){
    cudaFuncSetAttribute(hgemm_kernel, cudaFuncAttributeMaxDynamicSharedMemorySize, HSM_TOT);
    cudaStreamCreateWithFlags(&s_side, cudaStreamNonBlocking);
    cudaEventCreateWithFlags(&ev1, cudaEventDisableTiming);
    cudaEventCreateWithFlags(&ev2, cudaEventDisableTiming);
    cudaEventCreateWithFlags(&evT, cudaEventDisableTiming);
    cudaEventCreateWithFlags(&evW, cudaEventDisableTiming);
    cudaEventCreateWithFlags(&evM, cudaEventDisableTiming);
    cudaEventCreateWithFlags(&evR, cudaEventDisableTiming);
    cudaEventCreateWithFlags(&evO, cudaEventDisableTiming);
    cudaEventCreateWithFlags(&ev3, cudaEventDisableTiming);
    init_done = true;
  }

  float *pL, *pout1, *px12, *pout2, *px11, *px21, *pLx, *psqn, *poutR, *pg, *pgR;
  bf16 *pLh, *pLl, *pout1h, *pout1l, *pout1Th, *pout1Tl;
  bf16 *px12h, *px12l, *px12Th, *px12Tl;
  bf16 *px22h, *px22l, *pW2Th, *pW2Tl;
  bf16 *pxsRh, *pxsRl, *pWrTh, *pWrTl;
  cudaGetSymbolAddress((void**)&pL,      g_L);
  cudaGetSymbolAddress((void**)&pout1,   g_out1);
  cudaGetSymbolAddress((void**)&px12,    g_x12);
  cudaGetSymbolAddress((void**)&pout2,   g_out2);
  cudaGetSymbolAddress((void**)&px11,    g_x11);
  cudaGetSymbolAddress((void**)&px21,    g_x21);
  cudaGetSymbolAddress((void**)&pLx,     g_Lx);
  cudaGetSymbolAddress((void**)&psqn,    g_sqn);
  cudaGetSymbolAddress((void**)&poutR,   g_outR);
  cudaGetSymbolAddress((void**)&pg,      g_g);
  cudaGetSymbolAddress((void**)&pgR,     g_gR);
  cudaGetSymbolAddress((void**)&pLh,     g_Lh);
  cudaGetSymbolAddress((void**)&pLl,     g_Ll);
  cudaGetSymbolAddress((void**)&pout1h,  g_out1h);
  cudaGetSymbolAddress((void**)&pout1l,  g_out1l);
  cudaGetSymbolAddress((void**)&pout1Th, g_out1Th);
  cudaGetSymbolAddress((void**)&pout1Tl, g_out1Tl);
  cudaGetSymbolAddress((void**)&px12h,   g_x12h);
  cudaGetSymbolAddress((void**)&px12l,   g_x12l);
  cudaGetSymbolAddress((void**)&px12Th,  g_x12Th);
  cudaGetSymbolAddress((void**)&px12Tl,  g_x12Tl);
  cudaGetSymbolAddress((void**)&px22h,   g_x22h);
  cudaGetSymbolAddress((void**)&px22l,   g_x22l);
  cudaGetSymbolAddress((void**)&pW2Th,   g_W2Th);
  cudaGetSymbolAddress((void**)&pW2Tl,   g_W2Tl);
  cudaGetSymbolAddress((void**)&pxsRh,   g_xsRh);
  cudaGetSymbolAddress((void**)&pxsRl,   g_xsRl);
  cudaGetSymbolAddress((void**)&pWrTh,   g_WrTh);
  cudaGetSymbolAddress((void**)&pWrTl,   g_WrTl);

  zeroacc_kernel<<<1, 32>>>();
  zero_rs_kernel<<<128, 256>>>(1);

  // adjacency A1 (symmetric) with fused rowsum; L1 never materialized
  pairwise6_kernel<<<dim3(NPTS/16, NPTS/16, BATCH), dim3(16,16)>>>(x);

  // cheb conv 1 via implicit laplacian; cheb1 fuses sqnorm
  gemv6_adj_kernel<<<dim3(NPTS/16, BATCH), 512>>>(x, nullptr, px11, 1.f, 0.f);
  gemv6_adj_kernel<<<dim3(NPTS/16, BATCH), 512>>>(px11, x, px21, 2.f, -1.f);
  cheb1_out_kernel<<<dim3(8, (BATCH*NPTS)/16), 128>>>(x, W1, b1);

  // ---- fork side stream segment A ----
  cudaEventRecord(ev1, 0);
  cudaStreamWaitEvent(s_side, ev1, 0);
  transpose_hilo_kernel<<<dim3(NPTS/32, 32, BATCH), dim3(32,8), 0, s_side>>>(pout1, pout1Th, pout1Tl);
  cudaEventRecord(evT, s_side);
  w2t_kernel<<<dim3(32, 32, 3), dim3(32,8), 0, s_side>>>(W2);
  zero_g_kernel<<<63, 256, 0, s_side>>>();
  cudaEventRecord(evW, s_side);
  regnorm_kernel<<<dim3(8, BATCH), 128, 0, s_side>>>(pout1, px11, 0);
  gathermax_kernel<<<BATCH*RR, 256, 0, s_side>>>(sccs);
  wrt_kernel<<<dim3(188, 32), dim3(32,8), 0, s_side>>>(Wr);
  reeb_xs_kernel<<<dim3(8, BATCH), 128, 0, s_side>>>(Lr);
  {
    GemmArgs R{};
    R.Ah[0]=pxsRh; R.Al[0]=pxsRl; R.Bh[0]=pWrTh; R.Bl[0]=pWrTl;
    R.Ah[1]=pxsRh; R.Al[1]=pxsRl; R.Bh[1]=pWrTh; R.Bl[1]=pWrTl;
    R.Ah[2]=pxsRh; R.Al[2]=pxsRl; R.Bh[2]=pWrTh; R.Bl[2]=pWrTl;
    R.ldA = RK; R.ldB = RK; R.sA = 0; R.sB = 0;
    R.C = poutR; R.ldC = F1V; R.sC = 0;
    R.Ch = nullptr; R.Cl = nullptr; R.ldH = 0; R.sH = 0;
    R.Z = nullptr; R.ldZ = 0; R.sZ = 0;
    R.bias = br; R.sq = nullptr; R.sSq = 0; R.gmax = nullptr;
    R.M = BATCH*RR; R.N = F1V; R.nseg = 1; R.kcs = RK/32; R.epi = 4;
    hgemm_kernel<<<dim3(8,3,1), 256, HSM_TOT, s_side>>>(R);
  }
  colmax_kernel<<<dim3(4, BATCH), 256, 0, s_side>>>(poutR, pgR, RR);
  wreg_kernel<<<3, 256, 0, s_side>>>(Wfc1, bfc1, Wfc2, bfc2, Wfc3, bfc3, out);
  cudaEventRecord(evR, s_side);

  // ---- main chain continues ----
  zero_rs_kernel<<<128, 256>>>(0);

  GemmArgs A{};
  // adj2 = exp(2*out1@out1^T - sq_m - sq_n), upper triangle + fused rowsum atomics
  for (int s = 0; s < 3; s++){
    A.Ah[s]=pout1h; A.Al[s]=pout1l;
    A.Bh[s]=pout1h; A.Bl[s]=pout1l;
  }
  A.ldA = FPAD; A.ldB = FPAD; A.sA = (long)NPTS*FPAD; A.sB = (long)NPTS*FPAD;
  A.C = pL; A.ldC = NPTS; A.sC = (long)NPTS*NPTS;
  A.Ch = nullptr; A.Cl = nullptr; A.ldH = 0; A.sH = 0;
  A.Z = nullptr; A.ldZ = 0; A.sZ = 0; A.bias = nullptr;
  A.sq = psqn; A.sSq = NPTS; A.gmax = nullptr;
  A.M = NPTS; A.N = NPTS; A.nseg = 1; A.kcs = FPAD/32; A.epi = 1;
  hgemm_kernel<<<dim3(16,16,BATCH), 256, HSM_TOT>>>(A);

  // fused mirror + laplacian -> bf16 L2 (vectorized)
  mirror_lap_kernel<<<dim3(NPTS/32, NPTS/32, BATCH), dim3(16,16)>>>();
  cudaEventRecord(evM, 0);

  // ---- side stream segment B ----
  cudaStreamWaitEvent(s_side, evM, 0);
  gemv6_bf16_kernel<<<dim3(NPTS/8, BATCH), 256, 0, s_side>>>(x, pLx);
  cudaEventRecord(ev2, s_side);

  // x12 = L2 @ out1 (needs out1T from side stream)
  cudaStreamWaitEvent(0, evT, 0);
  for (int s = 0; s < 3; s++){
    A.Ah[s]=pLh; A.Al[s]=pLl;
    A.Bh[s]=pout1Th; A.Bl[s]=pout1Tl;
  }
  A.ldA = NPTS; A.ldB = NPTS; A.sA = (long)NPTS*NPTS; A.sB = (long)FPAD*NPTS;
  A.C = px12; A.ldC = F1V; A.sC = (long)NPTS*F1V;
  A.Ch = px12h; A.Cl = px12l; A.ldH = FPAD; A.sH = (long)NPTS*FPAD;
  A.Z = nullptr; A.sq = nullptr; A.bias = nullptr; A.gmax = nullptr;
  A.M = NPTS; A.N = F1V; A.nseg = 1; A.kcs = NPTS/32; A.epi = 2;
  hgemm_kernel<<<dim3(8,16,BATCH), 256, HSM_TOT>>>(A);

  transpose_hilo_kernel<<<dim3(NPTS/32, 32, BATCH), dim3(32,8)>>>(px12, px12Th, px12Tl);

  // x22 = 2*L2@x12 - out1 (split2 only)
  for (int s = 0; s < 3; s++){
    A.Ah[s]=pLh; A.Al[s]=pLl;
    A.Bh[s]=px12Th; A.Bl[s]=px12Tl;
  }
  A.C = nullptr; A.ldC = 0; A.sC = 0;
  A.Ch = px22h; A.Cl = px22l; A.ldH = FPAD; A.sH = (long)NPTS*FPAD;
  A.Z = pout1; A.ldZ = F1V; A.sZ = (long)NPTS*F1V;
  A.M = NPTS; A.N = F1V; A.nseg = 1; A.kcs = NPTS/32; A.epi = 3;
  hgemm_kernel<<<dim3(8,16,BATCH), 256, HSM_TOT>>>(A);

  // out2 = relu(...) + fused colmax (needs W2T + zeroed g from side)
  cudaStreamWaitEvent(0, evW, 0);
  A.Ah[0]=pout1h; A.Al[0]=pout1l;
  A.Ah[1]=px12h;  A.Al[1]=px12l;
  A.Ah[2]=px22h;  A.Al[2]=px22l;
  A.Bh[0]=pW2Th;                       A.Bl[0]=pW2Tl;
  A.Bh[1]=pW2Th + (size_t)FPAD*FPAD;   A.Bl[1]=pW2Tl + (size_t)FPAD*FPAD;
  A.Bh[2]=pW2Th + (size_t)2*FPAD*FPAD; A.Bl[2]=pW2Tl + (size_t)2*FPAD*FPAD;
  A.ldA = FPAD; A.ldB = FPAD; A.sA = 0; A.sB = 0;
  A.C = pout2; A.ldC = F1V; A.sC = 0;
  A.Ch = nullptr; A.Cl = nullptr; A.Z = nullptr;
  A.bias = b2; A.gmax = (unsigned*)pg;
  A.M = BATCH*NPTS; A.N = F1V; A.nseg = 3; A.kcs = FPAD/32; A.epi = 4;
  hgemm_kernel<<<dim3(8,256,1), 256, HSM_TOT>>>(A);
  cudaEventRecord(evO, 0);

  // ---- side stream segment C: regnorm(out2, Lx) in parallel with FC head ----
  cudaStreamWaitEvent(s_side, evO, 0);
  regnorm_kernel<<<dim3(8, BATCH), 128, 0, s_side>>>(pout2, pLx, 1);
  cudaEventRecord(ev3, s_side);

  // FC head on main (needs gR from segment A)
  cudaStreamWaitEvent(0, evR, 0);
  fc1_kernel<<<BATCH, 512>>>(Wfc1, bfc1);
  fc2_kernel<<<BATCH, 128>>>(Wfc2, bfc2);
  fc3_kernel<<<BATCH, 64>>>(Wfc3, bfc3, out);

  // finalize needs g_acc[0] (segA) and g_acc[1] (segC), both ordered before ev3
  cudaStreamWaitEvent(0, ev3, 0);
  finalize_kernel<<<1, 1>>>(out);
}